// round 2
// baseline (speedup 1.0000x reference)
#include <cuda_runtime.h>
#include <math.h>

#define NN 20000
#define NE 320000
#define DD 128
#define KK 2000

// ---------------- scratch (static device globals; no allocation) ----------------
__device__ float g_score[(size_t)KK * NN];   // 160 MB: score, then exp(score - m)
__device__ float g_t[NN * DD];
__device__ float g_h1[NN * DD];
__device__ float g_h2[NN * DD];
__device__ float g_Kd[NN * DD];
__device__ float g_Vd[NN * DD];
__device__ float g_Q[KK * DD];
__device__ float g_out[KK * DD];
__device__ float g_t2[KK * DD];
__device__ float g_xl[KK * DD];
__device__ float g_dinv[NN];
__device__ float g_rcpl[NN];
__device__ int   g_cnt[NN];
__device__ int   g_rptr[NN + 1];
__device__ int   g_col[NE];
__device__ int   g_bsums[64];

// ---------------- CSR construction ----------------
__global__ void k_zero_int(int* p, int n) {
    int i = blockIdx.x * blockDim.x + threadIdx.x;
    if (i < n) p[i] = 0;
}

__global__ void k_count_dst(const int* __restrict__ dst, int* __restrict__ cnt) {
    int e = blockIdx.x * blockDim.x + threadIdx.x;
    if (e < NE) atomicAdd(&cnt[dst[e]], 1);
}

__global__ void k_scan1(const int* __restrict__ cnt, int* __restrict__ rptr,
                        int* __restrict__ bsums) {
    __shared__ int sh[1024];
    int i = blockIdx.x * 1024 + threadIdx.x;
    int v = (i < NN) ? cnt[i] : 0;
    sh[threadIdx.x] = v;
    __syncthreads();
    for (int off = 1; off < 1024; off <<= 1) {
        int t = 0;
        if ((int)threadIdx.x >= off) t = sh[threadIdx.x - off];
        __syncthreads();
        sh[threadIdx.x] += t;
        __syncthreads();
    }
    if (i < NN) rptr[i] = sh[threadIdx.x] - v;   // exclusive
    if (threadIdx.x == 1023) bsums[blockIdx.x] = sh[1023];
}

__global__ void k_scan2(int* bsums, int nb) {
    if (threadIdx.x == 0 && blockIdx.x == 0) {
        int acc = 0;
        for (int b = 0; b < nb; b++) { int t = bsums[b]; bsums[b] = acc; acc += t; }
    }
}

__global__ void k_scan3(int* __restrict__ rptr, const int* __restrict__ bsums) {
    int i = blockIdx.x * 1024 + threadIdx.x;
    if (i < NN) rptr[i] += bsums[blockIdx.x];
    if (i == 0) rptr[NN] = NE;
}

__global__ void k_dinv_reset(int* __restrict__ cnt, float* __restrict__ dinv) {
    int n = blockIdx.x * blockDim.x + threadIdx.x;
    if (n < NN) {
        dinv[n] = rsqrtf((float)(cnt[n] + 1));  // +1 self loop
        cnt[n] = 0;                             // becomes cursor
    }
}

__global__ void k_fill_csr(const int* __restrict__ src, const int* __restrict__ dst,
                           const int* __restrict__ rptr, int* __restrict__ cnt,
                           int* __restrict__ colv) {
    int e = blockIdx.x * blockDim.x + threadIdx.x;
    if (e < NE) {
        int d = dst[e];
        int p = rptr[d] + atomicAdd(&cnt[d], 1);
        colv[p] = src[e];
    }
}

// ---------------- SGEMM: C[M,128] = A[M,128] @ W[128,128] (+bias) (relu) ------------
__global__ void k_sgemm(const float* __restrict__ A, const float* __restrict__ W,
                        const float* __restrict__ bias, float* __restrict__ C,
                        int M, int relu) {
    __shared__ float As[64][17];
    __shared__ float Ws[16][65];
    int tx = threadIdx.x, ty = threadIdx.y;
    int tid = ty * 16 + tx;
    int m0 = blockIdx.x * 64;
    int n0 = blockIdx.y * 64;
    float c[4][4] = {};
    for (int k0 = 0; k0 < 128; k0 += 16) {
#pragma unroll
        for (int i = 0; i < 4; i++) {
            int idx = tid + i * 256;
            int r = idx >> 4, kk = idx & 15;
            int m = m0 + r;
            As[r][kk] = (m < M) ? A[m * 128 + k0 + kk] : 0.f;
        }
#pragma unroll
        for (int i = 0; i < 4; i++) {
            int idx = tid + i * 256;
            int kk = idx >> 6, cc = idx & 63;
            Ws[kk][cc] = W[(k0 + kk) * 128 + n0 + cc];
        }
        __syncthreads();
#pragma unroll
        for (int kk = 0; kk < 16; kk++) {
            float a[4], b[4];
#pragma unroll
            for (int i = 0; i < 4; i++) a[i] = As[ty * 4 + i][kk];
#pragma unroll
            for (int j = 0; j < 4; j++) b[j] = Ws[kk][tx * 4 + j];
#pragma unroll
            for (int i = 0; i < 4; i++)
#pragma unroll
                for (int j = 0; j < 4; j++) c[i][j] += a[i] * b[j];
        }
        __syncthreads();
    }
#pragma unroll
    for (int i = 0; i < 4; i++) {
        int m = m0 + ty * 4 + i;
        if (m >= M) continue;
#pragma unroll
        for (int j = 0; j < 4; j++) {
            int n = n0 + tx * 4 + j;
            float v = c[i][j] + (bias ? bias[n] : 0.f);
            if (relu) v = fmaxf(v, 0.f);
            C[m * 128 + n] = v;
        }
    }
}

// ---------------- GCN aggregation: Out[n] = dinv[n]*(sum dinv[s]*H[s] + dinv[n]*H[n]) + b
__global__ void k_aggregate(const float* __restrict__ H, const int* __restrict__ rptr,
                            const int* __restrict__ colv, const float* __restrict__ dinv,
                            const float* __restrict__ bias, float* __restrict__ Out,
                            int relu) {
    int w = (blockIdx.x * blockDim.x + threadIdx.x) >> 5;
    int lane = threadIdx.x & 31;
    if (w >= NN) return;
    const float4* H4 = (const float4*)H;
    float4 acc = make_float4(0.f, 0.f, 0.f, 0.f);
    int s = rptr[w], e = rptr[w + 1];
    for (int j = s; j < e; j++) {
        int src = colv[j];
        float wt = dinv[src];
        float4 h = H4[src * 32 + lane];
        acc.x += wt * h.x; acc.y += wt * h.y; acc.z += wt * h.z; acc.w += wt * h.w;
    }
    float dn = dinv[w];
    float4 hs = H4[w * 32 + lane];
    float4 bb = ((const float4*)bias)[lane];
    acc.x = dn * (acc.x + dn * hs.x) + bb.x;
    acc.y = dn * (acc.y + dn * hs.y) + bb.y;
    acc.z = dn * (acc.z + dn * hs.z) + bb.z;
    acc.w = dn * (acc.w + dn * hs.w) + bb.w;
    if (relu) {
        acc.x = fmaxf(acc.x, 0.f); acc.y = fmaxf(acc.y, 0.f);
        acc.z = fmaxf(acc.z, 0.f); acc.w = fmaxf(acc.w, 0.f);
    }
    ((float4*)Out)[w * 32 + lane] = acc;
}

// ---------------- score[k,n] = (Q[k,:] . Kd[n,:]) / sqrt(128) ----------------
__global__ void k_score_gemm(const float* __restrict__ Q, const float* __restrict__ Kd,
                             float* __restrict__ Sc) {
    __shared__ float As[64][17];
    __shared__ float Bs[64][17];
    int tx = threadIdx.x, ty = threadIdx.y;
    int tid = ty * 16 + tx;
    int n0 = blockIdx.x * 64;
    int k0 = blockIdx.y * 64;
    float c[4][4] = {};
    for (int d0 = 0; d0 < 128; d0 += 16) {
#pragma unroll
        for (int i = 0; i < 4; i++) {
            int idx = tid + i * 256;
            int r = idx >> 4, dd = idx & 15;
            int k = k0 + r;
            As[r][dd] = (k < KK) ? Q[k * 128 + d0 + dd] : 0.f;
            int n = n0 + r;
            Bs[r][dd] = (n < NN) ? Kd[n * 128 + d0 + dd] : 0.f;
        }
        __syncthreads();
#pragma unroll
        for (int dd = 0; dd < 16; dd++) {
            float a[4], b[4];
#pragma unroll
            for (int i = 0; i < 4; i++) a[i] = As[ty * 4 + i][dd];
#pragma unroll
            for (int j = 0; j < 4; j++) b[j] = Bs[tx * 4 + j][dd];
#pragma unroll
            for (int i = 0; i < 4; i++)
#pragma unroll
                for (int j = 0; j < 4; j++) c[i][j] += a[i] * b[j];
        }
        __syncthreads();
    }
    const float scale = 0.0883883476483184f;  // 1/sqrt(128)
#pragma unroll
    for (int i = 0; i < 4; i++) {
        int k = k0 + ty * 4 + i;
        if (k >= KK) continue;
#pragma unroll
        for (int j = 0; j < 4; j++) {
            int n = n0 + tx * 4 + j;
            if (n < NN) Sc[(size_t)k * NN + n] = c[i][j] * scale;
        }
    }
}

// ---------------- per-node-column softmax over K; stores exp(score-m) in place ------
__global__ void k_softmax_cols(float* __restrict__ Sc, float* __restrict__ rcpl) {
    int n = blockIdx.x * blockDim.x + threadIdx.x;
    if (n >= NN) return;
    float m = -1e30f;
#pragma unroll 4
    for (int k = 0; k < KK; k++) m = fmaxf(m, Sc[(size_t)k * NN + n]);
    float l = 0.f;
#pragma unroll 4
    for (int k = 0; k < KK; k++) {
        float e = __expf(Sc[(size_t)k * NN + n] - m);
        l += e;
        Sc[(size_t)k * NN + n] = e;
    }
    rcpl[n] = 1.f / l;
}

// ---------------- elementwise helpers ----------------
__global__ void k_scale_rows(float* __restrict__ X, const float* __restrict__ r, int n) {
    int i = blockIdx.x * blockDim.x + threadIdx.x;
    if (i < n) X[i] *= r[i >> 7];
}
__global__ void k_copy(const float* __restrict__ a, float* __restrict__ b, int n) {
    int i = blockIdx.x * blockDim.x + threadIdx.x;
    if (i < n) b[i] = a[i];
}
__global__ void k_add(float* __restrict__ a, const float* __restrict__ b, int n) {
    int i = blockIdx.x * blockDim.x + threadIdx.x;
    if (i < n) a[i] += b[i];
}

// ---------------- Out[k,d] += sum_n Aexp[k,n]*Vds[n,d]   (split-K over n) ----------
__global__ void k_av_gemm(const float* __restrict__ Aexp, const float* __restrict__ Vds,
                          float* __restrict__ Out) {
    __shared__ float As[64][17];
    __shared__ float Bs[16][65];
    int tx = threadIdx.x, ty = threadIdx.y;
    int tid = ty * 16 + tx;
    int k0 = blockIdx.x * 64;
    int d0 = blockIdx.y * 64;
    int nstart = blockIdx.z * 2512;
    float c[4][4] = {};
    for (int n0 = nstart; n0 < nstart + 2512; n0 += 16) {
#pragma unroll
        for (int i = 0; i < 4; i++) {
            int idx = tid + i * 256;
            int r = idx >> 4, nn = idx & 15;
            int k = k0 + r;
            int n = n0 + nn;
            As[r][nn] = (k < KK && n < NN) ? Aexp[(size_t)k * NN + n] : 0.f;
        }
#pragma unroll
        for (int i = 0; i < 4; i++) {
            int idx = tid + i * 256;
            int nn = idx >> 6, cc = idx & 63;
            int n = n0 + nn;
            Bs[nn][cc] = (n < NN) ? Vds[n * 128 + d0 + cc] : 0.f;
        }
        __syncthreads();
#pragma unroll
        for (int nn = 0; nn < 16; nn++) {
            float a[4], b[4];
#pragma unroll
            for (int i = 0; i < 4; i++) a[i] = As[ty * 4 + i][nn];
#pragma unroll
            for (int j = 0; j < 4; j++) b[j] = Bs[nn][tx * 4 + j];
#pragma unroll
            for (int i = 0; i < 4; i++)
#pragma unroll
                for (int j = 0; j < 4; j++) c[i][j] += a[i] * b[j];
        }
        __syncthreads();
    }
#pragma unroll
    for (int i = 0; i < 4; i++) {
        int k = k0 + ty * 4 + i;
        if (k >= KK) continue;
#pragma unroll
        for (int j = 0; j < 4; j++)
            atomicAdd(&Out[k * 128 + d0 + tx * 4 + j], c[i][j]);
    }
}

// ---------------- Xout[n,d] = rcpl[n] * sum_k Aexp[k,n]*Xl[k,d] ----------------
__global__ void k_atx_gemm(const float* __restrict__ Aexp, const float* __restrict__ Xl,
                           const float* __restrict__ rcpl, float* __restrict__ Xout) {
    __shared__ float As[16][65];
    __shared__ float Bs[16][65];
    int tx = threadIdx.x, ty = threadIdx.y;
    int tid = ty * 16 + tx;
    int n0 = blockIdx.x * 64;
    int d0 = blockIdx.y * 64;
    float c[4][4] = {};
    for (int k0 = 0; k0 < KK; k0 += 16) {
#pragma unroll
        for (int i = 0; i < 4; i++) {
            int idx = tid + i * 256;
            int kk = idx >> 6, cc = idx & 63;
            int n = n0 + cc;
            As[kk][cc] = (n < NN) ? Aexp[(size_t)(k0 + kk) * NN + n] : 0.f;
            Bs[kk][cc] = Xl[(k0 + kk) * 128 + d0 + cc];
        }
        __syncthreads();
#pragma unroll
        for (int kk = 0; kk < 16; kk++) {
            float a[4], b[4];
#pragma unroll
            for (int i = 0; i < 4; i++) a[i] = As[kk][ty * 4 + i];
#pragma unroll
            for (int j = 0; j < 4; j++) b[j] = Bs[kk][tx * 4 + j];
#pragma unroll
            for (int i = 0; i < 4; i++)
#pragma unroll
                for (int j = 0; j < 4; j++) c[i][j] += a[i] * b[j];
        }
        __syncthreads();
    }
#pragma unroll
    for (int i = 0; i < 4; i++) {
        int n = n0 + ty * 4 + i;
        if (n >= NN) continue;
        float r = rcpl[n];
#pragma unroll
        for (int j = 0; j < 4; j++)
            Xout[n * 128 + d0 + tx * 4 + j] = r * c[i][j];
    }
}

// ---------------- LayerNorm rows of X[M,128] ----------------
__global__ void k_layernorm(float* __restrict__ X, const float* __restrict__ g,
                            const float* __restrict__ b, int M) {
    int w = (blockIdx.x * blockDim.x + threadIdx.x) >> 5;
    int lane = threadIdx.x & 31;
    if (w >= M) return;
    float4 v = ((const float4*)X)[w * 32 + lane];
    float s = v.x + v.y + v.z + v.w;
    float sq = v.x * v.x + v.y * v.y + v.z * v.z + v.w * v.w;
#pragma unroll
    for (int o = 16; o; o >>= 1) {
        s += __shfl_xor_sync(0xffffffffu, s, o);
        sq += __shfl_xor_sync(0xffffffffu, sq, o);
    }
    float mean = s * (1.f / 128.f);
    float var = sq * (1.f / 128.f) - mean * mean;
    float rstd = rsqrtf(var + 1e-5f);
    float4 gg = ((const float4*)g)[lane];
    float4 bb = ((const float4*)b)[lane];
    v.x = (v.x - mean) * rstd * gg.x + bb.x;
    v.y = (v.y - mean) * rstd * gg.y + bb.y;
    v.z = (v.z - mean) * rstd * gg.z + bb.z;
    v.w = (v.w - mean) * rstd * gg.w + bb.w;
    ((float4*)X)[w * 32 + lane] = v;
}

// ---------------- host orchestration ----------------
static float* faddr(const void* sym) {
    void* p = nullptr;
    cudaGetSymbolAddress(&p, sym);
    return (float*)p;
}
static int* iaddr(const void* sym) {
    void* p = nullptr;
    cudaGetSymbolAddress(&p, sym);
    return (int*)p;
}

extern "C" void kernel_launch(void* const* d_in, const int* in_sizes, int n_in,
                              void* d_out, int out_size) {
    const float* x  = (const float*)d_in[0];
    const int*   ei = (const int*)d_in[1];
    const float* W1 = (const float*)d_in[3];  const float* b1 = (const float*)d_in[4];
    const float* W2 = (const float*)d_in[5];  const float* b2 = (const float*)d_in[6];
    const float* S  = (const float*)d_in[7];
    const float* Wq = (const float*)d_in[8];  const float* bq = (const float*)d_in[9];
    const float* Wk = (const float*)d_in[10]; const float* bk = (const float*)d_in[11];
    const float* Wv = (const float*)d_in[12]; const float* bv = (const float*)d_in[13];
    const float* Wo = (const float*)d_in[14]; const float* bo = (const float*)d_in[15];
    const float* g0 = (const float*)d_in[16]; const float* be0 = (const float*)d_in[17];
    const float* g1 = (const float*)d_in[18]; const float* be1 = (const float*)d_in[19];
    const float* Wl = (const float*)d_in[20]; const float* bl = (const float*)d_in[21];
    const float* W3 = (const float*)d_in[22]; const float* b3 = (const float*)d_in[23];
    const float* W4 = (const float*)d_in[24]; const float* b4 = (const float*)d_in[25];
    const float* W5 = (const float*)d_in[26]; const float* b5 = (const float*)d_in[27];

    const int* src = ei;
    const int* dst = ei + NE;

    float* score = faddr(g_score);
    float* t     = faddr(g_t);
    float* h1    = faddr(g_h1);
    float* h2    = faddr(g_h2);
    float* Kd    = faddr(g_Kd);
    float* Vd    = faddr(g_Vd);
    float* Q     = faddr(g_Q);
    float* outb  = faddr(g_out);
    float* t2    = faddr(g_t2);
    float* xl    = faddr(g_xl);
    float* dinv  = faddr(g_dinv);
    float* rcpl  = faddr(g_rcpl);
    int* cnt   = iaddr(g_cnt);
    int* rptr  = iaddr(g_rptr);
    int* colv  = iaddr(g_col);
    int* bsums = iaddr(g_bsums);

    dim3 tb16(16, 16);
    dim3 gN((NN + 63) / 64, 2);     // M=20000 sgemm
    dim3 gK((KK + 63) / 64, 2);     // M=2000 sgemm
    dim3 gScore((NN + 63) / 64, (KK + 63) / 64);
    dim3 gAV((KK + 63) / 64, 2, 8);
    dim3 gATX((NN + 63) / 64, 2);
    float* dOut = (float*)d_out;

    // --- CSR + degree ---
    k_zero_int<<<(NN + 255) / 256, 256>>>(cnt, NN);
    k_count_dst<<<(NE + 255) / 256, 256>>>(dst, cnt);
    k_scan1<<<20, 1024>>>(cnt, rptr, bsums);
    k_scan2<<<1, 32>>>(bsums, 20);
    k_scan3<<<20, 1024>>>(rptr, bsums);
    k_dinv_reset<<<(NN + 255) / 256, 256>>>(cnt, dinv);
    k_fill_csr<<<(NE + 255) / 256, 256>>>(src, dst, rptr, cnt, colv);

    // --- GCN1, GCN2 ---
    k_sgemm<<<gN, tb16>>>(x, W1, nullptr, t, NN, 0);
    k_aggregate<<<(NN * 32 + 255) / 256, 256>>>(t, rptr, colv, dinv, b1, h1, 1);
    k_sgemm<<<gN, tb16>>>(h1, W2, nullptr, t, NN, 0);
    k_aggregate<<<(NN * 32 + 255) / 256, 256>>>(t, rptr, colv, dinv, b2, h2, 1);

    // --- Q, Kd, Vd ---
    k_sgemm<<<gK, tb16>>>(S, Wq, bq, Q, KK, 0);
    k_sgemm<<<gN, tb16>>>(h2, Wk, nullptr, t, NN, 0);
    k_aggregate<<<(NN * 32 + 255) / 256, 256>>>(t, rptr, colv, dinv, bk, Kd, 0);
    k_sgemm<<<gN, tb16>>>(h2, Wv, nullptr, t, NN, 0);
    k_aggregate<<<(NN * 32 + 255) / 256, 256>>>(t, rptr, colv, dinv, bv, Vd, 0);

    // --- attention ---
    k_score_gemm<<<gScore, tb16>>>(Q, Kd, score);
    k_softmax_cols<<<(NN + 255) / 256, 256>>>(score, rcpl);
    k_scale_rows<<<(NN * DD + 255) / 256, 256>>>(Vd, rcpl, NN * DD);   // fold 1/l into V
    k_copy<<<(KK * DD + 255) / 256, 256>>>(Q, outb, KK * DD);          // Out = Q
    k_av_gemm<<<gAV, tb16>>>(score, Vd, outb);                         // Out += A @ Vd

    // --- epilogue on [K,128] ---
    k_layernorm<<<(KK * 32 + 255) / 256, 256>>>(outb, g0, be0, KK);
    k_sgemm<<<gK, tb16>>>(outb, Wo, bo, t2, KK, 1);
    k_add<<<(KK * DD + 255) / 256, 256>>>(outb, t2, KK * DD);
    k_layernorm<<<(KK * 32 + 255) / 256, 256>>>(outb, g1, be1, KK);
    k_sgemm<<<gK, tb16>>>(outb, Wl, bl, xl, KK, 0);

    // --- x_out = A^T @ xl (rcpl folded into epilogue) ---
    k_atx_gemm<<<gATX, tb16>>>(score, xl, rcpl, h1);

    // --- GCN3, GCN4, GCN5 ---
    k_sgemm<<<gN, tb16>>>(h1, W3, nullptr, t, NN, 0);
    k_aggregate<<<(NN * 32 + 255) / 256, 256>>>(t, rptr, colv, dinv, b3, h2, 1);
    k_sgemm<<<gN, tb16>>>(h2, W4, nullptr, t, NN, 0);
    k_aggregate<<<(NN * 32 + 255) / 256, 256>>>(t, rptr, colv, dinv, b4, h1, 1);
    k_sgemm<<<gN, tb16>>>(h1, W5, nullptr, t, NN, 0);
    k_aggregate<<<(NN * 32 + 255) / 256, 256>>>(t, rptr, colv, dinv, b5, dOut, 0);
}

// round 6
// speedup vs baseline: 1.8350x; 1.8350x over previous
#include <cuda_runtime.h>
#include <math.h>

#define NN 20000
#define NE 320000
#define DD 128
#define KK 2000
#define KK32 2016   // KK padded to multiple of 32 for the ATX gemm

// ---------------- scratch (static device globals; no allocation) ----------------
__device__ float g_score[(size_t)KK32 * NN]; // 162 MB: score, then exp(score - m); rows >= KK are zero
__device__ float g_t[NN * DD];
__device__ float g_h1[NN * DD];
__device__ float g_h2[NN * DD];
__device__ float g_Kd[NN * DD];
__device__ float g_Vd[NN * DD];
__device__ float g_Q[KK * DD];
__device__ float g_out[KK * DD];
__device__ float g_t2[KK * DD];
__device__ float g_xl[KK32 * DD];            // rows >= KK are zero
__device__ float g_dinv[NN];
__device__ float g_rcpl[NN];
__device__ int   g_cnt[NN];
__device__ int   g_rptr[NN + 1];
__device__ int   g_col[NE];
__device__ int   g_bsums[64];

// ---------------- CSR construction ----------------
__global__ void k_zero_int(int* p, int n) {
    int i = blockIdx.x * blockDim.x + threadIdx.x;
    if (i < n) p[i] = 0;
}
__global__ void k_zero_float(float* p, int n) {
    int i = blockIdx.x * blockDim.x + threadIdx.x;
    if (i < n) p[i] = 0.f;
}

__global__ void k_count_dst(const int* __restrict__ dst, int* __restrict__ cnt) {
    int e = blockIdx.x * blockDim.x + threadIdx.x;
    if (e < NE) atomicAdd(&cnt[dst[e]], 1);
}

__global__ void k_scan1(const int* __restrict__ cnt, int* __restrict__ rptr,
                        int* __restrict__ bsums) {
    __shared__ int sh[1024];
    int i = blockIdx.x * 1024 + threadIdx.x;
    int v = (i < NN) ? cnt[i] : 0;
    sh[threadIdx.x] = v;
    __syncthreads();
    for (int off = 1; off < 1024; off <<= 1) {
        int t = 0;
        if ((int)threadIdx.x >= off) t = sh[threadIdx.x - off];
        __syncthreads();
        sh[threadIdx.x] += t;
        __syncthreads();
    }
    if (i < NN) rptr[i] = sh[threadIdx.x] - v;   // exclusive
    if (threadIdx.x == 1023) bsums[blockIdx.x] = sh[1023];
}

__global__ void k_scan2(int* bsums, int nb) {
    if (threadIdx.x == 0 && blockIdx.x == 0) {
        int acc = 0;
        for (int b = 0; b < nb; b++) { int t = bsums[b]; bsums[b] = acc; acc += t; }
    }
}

__global__ void k_scan3(int* __restrict__ rptr, const int* __restrict__ bsums) {
    int i = blockIdx.x * 1024 + threadIdx.x;
    if (i < NN) rptr[i] += bsums[blockIdx.x];
    if (i == 0) rptr[NN] = NE;
}

__global__ void k_dinv_reset(int* __restrict__ cnt, float* __restrict__ dinv) {
    int n = blockIdx.x * blockDim.x + threadIdx.x;
    if (n < NN) {
        dinv[n] = rsqrtf((float)(cnt[n] + 1));  // +1 self loop
        cnt[n] = 0;                             // becomes cursor
    }
}

__global__ void k_fill_csr(const int* __restrict__ src, const int* __restrict__ dst,
                           const int* __restrict__ rptr, int* __restrict__ cnt,
                           int* __restrict__ colv) {
    int e = blockIdx.x * blockDim.x + threadIdx.x;
    if (e < NE) {
        int d = dst[e];
        int p = rptr[d] + atomicAdd(&cnt[d], 1);
        colv[p] = src[e];
    }
}

// ================= 3xTF32 tensor-core GEMM (fp32-accurate) =================
// C[M,N] = op(A) @ op(B), BM=BN=128, BK=32, 256 threads (8 warps, warp tile 64x32)
// x = xhi + xlo (xhi = x & 0xFFFFE000); acc += hi*hi + hi*lo + lo*hi (error ~2^-22)
// NOTE: (kE - kB) must be a multiple of 32 for every launch.
#define GBM 128
#define GBN 128
#define GBK 32
#define LDMK 36    // [row][k] storage (16B-aligned rows for ldmatrix)
#define LDKM 132   // [k][row] storage
#define ASZ 4608   // max(128*36, 32*132)
#define STG 9216   // ASZ * 2 (A + B region)
#define GSMEM (2 * STG * 4)

__device__ __forceinline__ void cp16(unsigned dst, const float* src, bool v) {
    int sz = v ? 16 : 0;
    asm volatile("cp.async.cg.shared.global [%0], [%1], 16, %2;\n"
                 :: "r"(dst), "l"(src), "r"(sz));
}
#define CP_COMMIT asm volatile("cp.async.commit_group;\n")
#define CP_WAIT0  asm volatile("cp.async.wait_group 0;\n" ::: "memory")

__device__ __forceinline__ void mma8(float* d, unsigned a0, unsigned a1, unsigned a2,
                                     unsigned a3, unsigned b0, unsigned b1) {
    asm volatile("mma.sync.aligned.m16n8k8.row.col.f32.tf32.tf32.f32 "
        "{%0,%1,%2,%3}, {%4,%5,%6,%7}, {%8,%9}, {%0,%1,%2,%3};\n"
        : "+f"(d[0]), "+f"(d[1]), "+f"(d[2]), "+f"(d[3])
        : "r"(a0), "r"(a1), "r"(a2), "r"(a3), "r"(b0), "r"(b1));
}
__device__ __forceinline__ unsigned lo_part(unsigned x) {
    return __float_as_uint(__uint_as_float(x) - __uint_as_float(x & 0xFFFFE000u));
}

template<int TRANSA, int TRANSB, int EPI>
__global__ __launch_bounds__(256, 1)
void k_gemm(const float* __restrict__ A, const float* __restrict__ B,
            float* __restrict__ C, int M, int N, int Ktot, int kChunk,
            int ldA, int ldB, int ldC, float alpha,
            const float* __restrict__ bias, const float* __restrict__ rowscale,
            int relu)
{
    extern __shared__ float smf[];
    const int tid = threadIdx.x;
    const int lane = tid & 31;
    const int warp = tid >> 5;
    const int wm = (warp >> 2) * 64;
    const int wn = (warp & 3) * 32;
    const int g = lane >> 2, tig = lane & 3;
    const int m0 = blockIdx.x * GBM;
    const int n0 = blockIdx.y * GBN;
    const int kB = blockIdx.z * kChunk;
    const int kE = (Ktot < kB + kChunk) ? Ktot : (kB + kChunk);
    const int T = (kE - kB) >> 5;

    const unsigned sbase = (unsigned)__cvta_generic_to_shared(smf);

    int arow, acol, brow, bcol;
    if (!TRANSA) { arow = tid >> 3; acol = (tid & 7) * 4; }
    else         { arow = tid >> 5; acol = (tid & 31) * 4; }
    if (!TRANSB) { brow = tid >> 5; bcol = (tid & 31) * 4; }
    else         { brow = tid >> 3; bcol = (tid & 7) * 4; }

    const int a_lr = ((lane >> 3) & 1) * 8 + (lane & 7);
    const int a_lk = (lane >> 4) * 4;
    const int b_lr = (lane >> 4) * 8 + (lane & 7);
    const int b_lk = ((lane >> 3) & 1) * 4;

    float acc[4][4][4];
#pragma unroll
    for (int i = 0; i < 4; i++)
#pragma unroll
        for (int j = 0; j < 4; j++)
#pragma unroll
            for (int q = 0; q < 4; q++) acc[i][j][q] = 0.f;

    auto prefetch = [&](int kt, int s) {
        unsigned abase = sbase + (unsigned)(s * STG) * 4u;
        unsigned bbase = abase + ASZ * 4u;
        int kof = kB + kt * 32;
#pragma unroll
        for (int p = 0; p < 4; p++) {
            if (!TRANSA) {
                int m = m0 + arow + 32 * p;
                bool v = m < M;
                const float* src = A + (size_t)(v ? m : 0) * ldA + kof + acol;
                cp16(abase + (unsigned)((arow + 32 * p) * LDMK + acol) * 4u, src, v);
            } else {
                int m = m0 + acol;
                bool v = m < M;
                const float* src = A + (size_t)(kof + arow + 8 * p) * ldA + (v ? m : 0);
                cp16(abase + (unsigned)((arow + 8 * p) * LDKM + acol) * 4u, src, v);
            }
        }
#pragma unroll
        for (int p = 0; p < 4; p++) {
            if (!TRANSB) {
                int n = n0 + bcol;
                bool v = n < N;
                const float* src = B + (size_t)(kof + brow + 8 * p) * ldB + (v ? n : 0);
                cp16(bbase + (unsigned)((brow + 8 * p) * LDKM + bcol) * 4u, src, v);
            } else {
                int n = n0 + brow + 32 * p;
                bool v = n < N;
                const float* src = B + (size_t)(v ? n : 0) * ldB + kof + bcol;
                cp16(bbase + (unsigned)((brow + 32 * p) * LDMK + bcol) * 4u, src, v);
            }
        }
    };

    prefetch(0, 0);
    CP_COMMIT;
    int s = 0;
    for (int kt = 0; kt < T; kt++) {
        CP_WAIT0;
        __syncthreads();
        if (kt + 1 < T) { prefetch(kt + 1, s ^ 1); CP_COMMIT; }
        const float* AsF = smf + s * STG;
        const float* BsF = AsF + ASZ;
        unsigned abase = sbase + (unsigned)(s * STG) * 4u;
        unsigned bbase = abase + ASZ * 4u;
#pragma unroll
        for (int ks = 0; ks < 4; ks++) {
            const int k0 = ks * 8;
            unsigned ah[4][4], al[4][4];
            if (!TRANSA) {
#pragma unroll
                for (int mf = 0; mf < 4; mf++) {
                    unsigned addr = abase + (unsigned)((wm + mf * 16 + a_lr) * LDMK + k0 + a_lk) * 4u;
                    asm volatile("ldmatrix.sync.aligned.m8n8.x4.shared.b16 {%0,%1,%2,%3}, [%4];\n"
                        : "=r"(ah[mf][0]), "=r"(ah[mf][1]), "=r"(ah[mf][2]), "=r"(ah[mf][3]) : "r"(addr));
                }
            } else {
#pragma unroll
                for (int mf = 0; mf < 4; mf++) {
                    int mb = wm + mf * 16 + g;
                    ah[mf][0] = __float_as_uint(AsF[(k0 + tig) * LDKM + mb]);
                    ah[mf][1] = __float_as_uint(AsF[(k0 + tig) * LDKM + mb + 8]);
                    ah[mf][2] = __float_as_uint(AsF[(k0 + tig + 4) * LDKM + mb]);
                    ah[mf][3] = __float_as_uint(AsF[(k0 + tig + 4) * LDKM + mb + 8]);
                }
            }
#pragma unroll
            for (int mf = 0; mf < 4; mf++)
#pragma unroll
                for (int q = 0; q < 4; q++) {
                    al[mf][q] = lo_part(ah[mf][q]);
                    ah[mf][q] &= 0xFFFFE000u;
                }
            unsigned braw[4][2];
            if (TRANSB) {
#pragma unroll
                for (int h = 0; h < 2; h++) {
                    unsigned addr = bbase + (unsigned)((wn + h * 16 + b_lr) * LDMK + k0 + b_lk) * 4u;
                    asm volatile("ldmatrix.sync.aligned.m8n8.x4.shared.b16 {%0,%1,%2,%3}, [%4];\n"
                        : "=r"(braw[2 * h][0]), "=r"(braw[2 * h][1]),
                          "=r"(braw[2 * h + 1][0]), "=r"(braw[2 * h + 1][1])
                        : "r"(addr));
                }
            } else {
#pragma unroll
                for (int nf = 0; nf < 4; nf++) {
                    int nb = wn + nf * 8 + g;
                    braw[nf][0] = __float_as_uint(BsF[(k0 + tig) * LDKM + nb]);
                    braw[nf][1] = __float_as_uint(BsF[(k0 + tig + 4) * LDKM + nb]);
                }
            }
#pragma unroll
            for (int nf = 0; nf < 4; nf++) {
                unsigned bh0 = braw[nf][0] & 0xFFFFE000u;
                unsigned bh1 = braw[nf][1] & 0xFFFFE000u;
                unsigned bl0 = lo_part(braw[nf][0]);
                unsigned bl1 = lo_part(braw[nf][1]);
#pragma unroll
                for (int mf = 0; mf < 4; mf++) {
                    mma8(acc[mf][nf], ah[mf][0], ah[mf][1], ah[mf][2], ah[mf][3], bh0, bh1);
                    mma8(acc[mf][nf], ah[mf][0], ah[mf][1], ah[mf][2], ah[mf][3], bl0, bl1);
                    mma8(acc[mf][nf], al[mf][0], al[mf][1], al[mf][2], al[mf][3], bh0, bh1);
                }
            }
        }
        s ^= 1;
    }

    // epilogue
#pragma unroll
    for (int mf = 0; mf < 4; mf++) {
        int r0 = m0 + wm + mf * 16 + g;
        int r1 = r0 + 8;
#pragma unroll
        for (int nf = 0; nf < 4; nf++) {
            int c = n0 + wn + nf * 8 + tig * 2;
            float v0 = acc[mf][nf][0] * alpha;
            float v1 = acc[mf][nf][1] * alpha;
            float v2 = acc[mf][nf][2] * alpha;
            float v3 = acc[mf][nf][3] * alpha;
            if (EPI == 0) {
                float bb0 = bias ? bias[c] : 0.f;
                float bb1 = bias ? bias[c + 1] : 0.f;
                v0 += bb0; v1 += bb1; v2 += bb0; v3 += bb1;
                if (relu) {
                    v0 = fmaxf(v0, 0.f); v1 = fmaxf(v1, 0.f);
                    v2 = fmaxf(v2, 0.f); v3 = fmaxf(v3, 0.f);
                }
                if (c < N) {
                    if (r0 < M) { C[(size_t)r0 * ldC + c] = v0; C[(size_t)r0 * ldC + c + 1] = v1; }
                    if (r1 < M) { C[(size_t)r1 * ldC + c] = v2; C[(size_t)r1 * ldC + c + 1] = v3; }
                }
            } else if (EPI == 1) {
                if (c < N) {
                    if (r0 < M) { atomicAdd(&C[(size_t)r0 * ldC + c], v0); atomicAdd(&C[(size_t)r0 * ldC + c + 1], v1); }
                    if (r1 < M) { atomicAdd(&C[(size_t)r1 * ldC + c], v2); atomicAdd(&C[(size_t)r1 * ldC + c + 1], v3); }
                }
            } else {
                if (c < N) {
                    if (r0 < M) { float sc = rowscale[r0]; C[(size_t)r0 * ldC + c] = sc * v0; C[(size_t)r0 * ldC + c + 1] = sc * v1; }
                    if (r1 < M) { float sc = rowscale[r1]; C[(size_t)r1 * ldC + c] = sc * v2; C[(size_t)r1 * ldC + c + 1] = sc * v3; }
                }
            }
        }
    }
}

// ---------------- GCN aggregation ----------------
__global__ void k_aggregate(const float* __restrict__ H, const int* __restrict__ rptr,
                            const int* __restrict__ colv, const float* __restrict__ dinv,
                            const float* __restrict__ bias, float* __restrict__ Out,
                            int relu) {
    int w = (blockIdx.x * blockDim.x + threadIdx.x) >> 5;
    int lane = threadIdx.x & 31;
    if (w >= NN) return;
    const float4* H4 = (const float4*)H;
    float4 acc = make_float4(0.f, 0.f, 0.f, 0.f);
    int s = rptr[w], e = rptr[w + 1];
    for (int j = s; j < e; j++) {
        int src = colv[j];
        float wt = dinv[src];
        float4 h = H4[src * 32 + lane];
        acc.x += wt * h.x; acc.y += wt * h.y; acc.z += wt * h.z; acc.w += wt * h.w;
    }
    float dn = dinv[w];
    float4 hs = H4[w * 32 + lane];
    float4 bb = ((const float4*)bias)[lane];
    acc.x = dn * (acc.x + dn * hs.x) + bb.x;
    acc.y = dn * (acc.y + dn * hs.y) + bb.y;
    acc.z = dn * (acc.z + dn * hs.z) + bb.z;
    acc.w = dn * (acc.w + dn * hs.w) + bb.w;
    if (relu) {
        acc.x = fmaxf(acc.x, 0.f); acc.y = fmaxf(acc.y, 0.f);
        acc.z = fmaxf(acc.z, 0.f); acc.w = fmaxf(acc.w, 0.f);
    }
    ((float4*)Out)[w * 32 + lane] = acc;
}

// ---------------- per-node-column softmax over K (4 k-slices per column) -----------
__global__ void k_softmax_cols(float* __restrict__ Sc, float* __restrict__ rcpl) {
    __shared__ float red[4][64];
    int nl = threadIdx.x & 63;
    int sl = threadIdx.x >> 6;
    int n = blockIdx.x * 64 + nl;
    bool ok = n < NN;
    float m = -1e30f;
    if (ok) {
#pragma unroll 4
        for (int k = sl; k < KK; k += 4) m = fmaxf(m, Sc[(size_t)k * NN + n]);
    }
    red[sl][nl] = m;
    __syncthreads();
    m = fmaxf(fmaxf(red[0][nl], red[1][nl]), fmaxf(red[2][nl], red[3][nl]));
    __syncthreads();
    float l = 0.f;
    if (ok) {
#pragma unroll 4
        for (int k = sl; k < KK; k += 4) {
            size_t idx = (size_t)k * NN + n;
            float e = __expf(Sc[idx] - m);
            l += e;
            Sc[idx] = e;
        }
    }
    red[sl][nl] = l;
    __syncthreads();
    if (sl == 0 && ok)
        rcpl[n] = 1.f / (red[0][nl] + red[1][nl] + red[2][nl] + red[3][nl]);
}

// ---------------- elementwise helpers ----------------
__global__ void k_scale_rows(float* __restrict__ X, const float* __restrict__ r, int n) {
    int i = blockIdx.x * blockDim.x + threadIdx.x;
    if (i < n) X[i] *= r[i >> 7];
}
__global__ void k_copy(const float* __restrict__ a, float* __restrict__ b, int n) {
    int i = blockIdx.x * blockDim.x + threadIdx.x;
    if (i < n) b[i] = a[i];
}
__global__ void k_add(float* __restrict__ a, const float* __restrict__ b, int n) {
    int i = blockIdx.x * blockDim.x + threadIdx.x;
    if (i < n) a[i] += b[i];
}

// ---------------- LayerNorm rows of X[M,128] ----------------
__global__ void k_layernorm(float* __restrict__ X, const float* __restrict__ g,
                            const float* __restrict__ b, int M) {
    int w = (blockIdx.x * blockDim.x + threadIdx.x) >> 5;
    int lane = threadIdx.x & 31;
    if (w >= M) return;
    float4 v = ((const float4*)X)[w * 32 + lane];
    float s = v.x + v.y + v.z + v.w;
    float sq = v.x * v.x + v.y * v.y + v.z * v.z + v.w * v.w;
#pragma unroll
    for (int o = 16; o; o >>= 1) {
        s += __shfl_xor_sync(0xffffffffu, s, o);
        sq += __shfl_xor_sync(0xffffffffu, sq, o);
    }
    float mean = s * (1.f / 128.f);
    float var = sq * (1.f / 128.f) - mean * mean;
    float rstd = rsqrtf(var + 1e-5f);
    float4 gg = ((const float4*)g)[lane];
    float4 bb = ((const float4*)b)[lane];
    v.x = (v.x - mean) * rstd * gg.x + bb.x;
    v.y = (v.y - mean) * rstd * gg.y + bb.y;
    v.z = (v.z - mean) * rstd * gg.z + bb.z;
    v.w = (v.w - mean) * rstd * gg.w + bb.w;
    ((float4*)X)[w * 32 + lane] = v;
}

// ---------------- host orchestration ----------------
static float* faddr(const void* sym) {
    void* p = nullptr;
    cudaGetSymbolAddress(&p, sym);
    return (float*)p;
}
static int* iaddr(const void* sym) {
    void* p = nullptr;
    cudaGetSymbolAddress(&p, sym);
    return (int*)p;
}

extern "C" void kernel_launch(void* const* d_in, const int* in_sizes, int n_in,
                              void* d_out, int out_size) {
    const float* x  = (const float*)d_in[0];
    const int*   ei = (const int*)d_in[1];
    const float* W1 = (const float*)d_in[3];  const float* b1 = (const float*)d_in[4];
    const float* W2 = (const float*)d_in[5];  const float* b2 = (const float*)d_in[6];
    const float* S  = (const float*)d_in[7];
    const float* Wq = (const float*)d_in[8];  const float* bq = (const float*)d_in[9];
    const float* Wk = (const float*)d_in[10]; const float* bk = (const float*)d_in[11];
    const float* Wv = (const float*)d_in[12]; const float* bv = (const float*)d_in[13];
    const float* Wo = (const float*)d_in[14]; const float* bo = (const float*)d_in[15];
    const float* g0 = (const float*)d_in[16]; const float* be0 = (const float*)d_in[17];
    const float* g1 = (const float*)d_in[18]; const float* be1 = (const float*)d_in[19];
    const float* Wl = (const float*)d_in[20]; const float* bl = (const float*)d_in[21];
    const float* W3 = (const float*)d_in[22]; const float* b3 = (const float*)d_in[23];
    const float* W4 = (const float*)d_in[24]; const float* b4 = (const float*)d_in[25];
    const float* W5 = (const float*)d_in[26]; const float* b5 = (const float*)d_in[27];

    const int* src = ei;
    const int* dst = ei + NE;

    float* score = faddr(g_score);
    float* t     = faddr(g_t);
    float* h1    = faddr(g_h1);
    float* h2    = faddr(g_h2);
    float* Kd    = faddr(g_Kd);
    float* Vd    = faddr(g_Vd);
    float* Q     = faddr(g_Q);
    float* outb  = faddr(g_out);
    float* t2    = faddr(g_t2);
    float* xl    = faddr(g_xl);
    float* dinv  = faddr(g_dinv);
    float* rcpl  = faddr(g_rcpl);
    int* cnt   = iaddr(g_cnt);
    int* rptr  = iaddr(g_rptr);
    int* colv  = iaddr(g_col);
    int* bsums = iaddr(g_bsums);

    // opt-in dynamic smem for the tf32 gemm instantiations (idempotent, capture-safe)
    cudaFuncSetAttribute((const void*)k_gemm<0,0,0>, cudaFuncAttributeMaxDynamicSharedMemorySize, GSMEM);
    cudaFuncSetAttribute((const void*)k_gemm<0,1,0>, cudaFuncAttributeMaxDynamicSharedMemorySize, GSMEM);
    cudaFuncSetAttribute((const void*)k_gemm<0,0,1>, cudaFuncAttributeMaxDynamicSharedMemorySize, GSMEM);
    cudaFuncSetAttribute((const void*)k_gemm<1,0,2>, cudaFuncAttributeMaxDynamicSharedMemorySize, GSMEM);

    const int mbN = (NN + 127) / 128;   // 157
    const int mbK = (KK + 127) / 128;   // 16
    float* dOut = (float*)d_out;
    const float rs128 = 0.0883883476483184f;  // 1/sqrt(128)

    // --- zero the k-padding rows (score rows KK..KK32, xl rows KK..KK32) ---
    k_zero_float<<<((KK32 - KK) * NN + 255) / 256, 256>>>(score + (size_t)KK * NN, (KK32 - KK) * NN);
    k_zero_float<<<((KK32 - KK) * DD + 255) / 256, 256>>>(xl + (size_t)KK * DD, (KK32 - KK) * DD);

    // --- CSR + degree ---
    k_zero_int<<<(NN + 255) / 256, 256>>>(cnt, NN);
    k_count_dst<<<(NE + 255) / 256, 256>>>(dst, cnt);
    k_scan1<<<20, 1024>>>(cnt, rptr, bsums);
    k_scan2<<<1, 32>>>(bsums, 20);
    k_scan3<<<20, 1024>>>(rptr, bsums);
    k_dinv_reset<<<(NN + 255) / 256, 256>>>(cnt, dinv);
    k_fill_csr<<<(NE + 255) / 256, 256>>>(src, dst, rptr, cnt, colv);

    // --- GCN1, GCN2 ---
    k_gemm<0,0,0><<<dim3(mbN,1,1), 256, GSMEM>>>(x,  W1, t, NN, 128, 128, 128, 128, 128, 128, 1.f, nullptr, nullptr, 0);
    k_aggregate<<<(NN * 32 + 255) / 256, 256>>>(t, rptr, colv, dinv, b1, h1, 1);
    k_gemm<0,0,0><<<dim3(mbN,1,1), 256, GSMEM>>>(h1, W2, t, NN, 128, 128, 128, 128, 128, 128, 1.f, nullptr, nullptr, 0);
    k_aggregate<<<(NN * 32 + 255) / 256, 256>>>(t, rptr, colv, dinv, b2, h2, 1);

    // --- Q, Kd, Vd ---
    k_gemm<0,0,0><<<dim3(mbK,1,1), 256, GSMEM>>>(S,  Wq, Q, KK, 128, 128, 128, 128, 128, 128, 1.f, bq, nullptr, 0);
    k_gemm<0,0,0><<<dim3(mbN,1,1), 256, GSMEM>>>(h2, Wk, t, NN, 128, 128, 128, 128, 128, 128, 1.f, nullptr, nullptr, 0);
    k_aggregate<<<(NN * 32 + 255) / 256, 256>>>(t, rptr, colv, dinv, bk, Kd, 0);
    k_gemm<0,0,0><<<dim3(mbN,1,1), 256, GSMEM>>>(h2, Wv, t, NN, 128, 128, 128, 128, 128, 128, 1.f, nullptr, nullptr, 0);
    k_aggregate<<<(NN * 32 + 255) / 256, 256>>>(t, rptr, colv, dinv, bv, Vd, 0);

    // --- attention: score = Q @ Kd^T / sqrt(D) ---
    k_gemm<0,1,0><<<dim3(mbK, mbN, 1), 256, GSMEM>>>(Q, Kd, score, KK, NN, 128, 128, 128, 128, NN, rs128, nullptr, nullptr, 0);
    k_softmax_cols<<<(NN + 63) / 64, 256>>>(score, rcpl);
    k_scale_rows<<<(NN * DD + 255) / 256, 256>>>(Vd, rcpl, NN * DD);   // fold 1/l into V
    k_copy<<<(KK * DD + 255) / 256, 256>>>(Q, outb, KK * DD);          // Out = Q
    // Out += Aexp @ Vd_scaled   (split-K over n: 16 chunks of 1280)
    k_gemm<0,0,1><<<dim3(mbK, 1, 16), 256, GSMEM>>>(score, Vd, outb, KK, 128, NN, 1280, NN, 128, 128, 1.f, nullptr, nullptr, 0);

    // --- epilogue on [K,128] ---
    k_layernorm<<<(KK * 32 + 255) / 256, 256>>>(outb, g0, be0, KK);
    k_gemm<0,0,0><<<dim3(mbK,1,1), 256, GSMEM>>>(outb, Wo, t2, KK, 128, 128, 128, 128, 128, 128, 1.f, bo, nullptr, 1);
    k_add<<<(KK * DD + 255) / 256, 256>>>(outb, t2, KK * DD);
    k_layernorm<<<(KK * 32 + 255) / 256, 256>>>(outb, g1, be1, KK);
    k_gemm<0,0,0><<<dim3(mbK,1,1), 256, GSMEM>>>(outb, Wl, xl, KK, 128, 128, 128, 128, 128, 128, 1.f, bl, nullptr, 0);

    // --- x_out = rcpl[n] * (Aexp^T @ xl), k padded to KK32 (pad rows are zero) ---
    k_gemm<1,0,2><<<dim3(mbN,1,1), 256, GSMEM>>>(score, xl, h1, NN, 128, KK32, KK32, NN, 128, 128, 1.f, nullptr, rcpl, 0);

    // --- GCN3, GCN4, GCN5 ---
    k_gemm<0,0,0><<<dim3(mbN,1,1), 256, GSMEM>>>(h1, W3, t, NN, 128, 128, 128, 128, 128, 128, 1.f, nullptr, nullptr, 0);
    k_aggregate<<<(NN * 32 + 255) / 256, 256>>>(t, rptr, colv, dinv, b3, h2, 1);
    k_gemm<0,0,0><<<dim3(mbN,1,1), 256, GSMEM>>>(h2, W4, t, NN, 128, 128, 128, 128, 128, 128, 1.f, nullptr, nullptr, 0);
    k_aggregate<<<(NN * 32 + 255) / 256, 256>>>(t, rptr, colv, dinv, b4, h1, 1);
    k_gemm<0,0,0><<<dim3(mbN,1,1), 256, GSMEM>>>(h1, W5, t, NN, 128, 128, 128, 128, 128, 128, 1.f, nullptr, nullptr, 0);
    k_aggregate<<<(NN * 32 + 255) / 256, 256>>>(t, rptr, colv, dinv, b5, dOut, 0);
}

// round 10
// speedup vs baseline: 2.1361x; 1.1641x over previous
#include <cuda_runtime.h>
#include <math.h>

#define NN 20000
#define NE 320000
#define DD 128
#define KK 2000
#define KK32 2016   // KK padded to multiple of 32 for the ATX gemm

// ---------------- scratch (static device globals; no allocation) ----------------
__device__ float g_score[(size_t)KK32 * NN]; // 162 MB: score, then exp(score - m); rows >= KK are zero
__device__ float g_t[NN * DD];
__device__ float g_h1[NN * DD];
__device__ float g_h2[NN * DD];
__device__ float g_Kd[NN * DD];
__device__ float g_Vd[NN * DD];
__device__ float g_Q[KK * DD];
__device__ float g_out[KK * DD];
__device__ float g_t2[KK * DD];
__device__ float g_xl[KK32 * DD];            // rows >= KK are zero
__device__ float g_dinv[NN];
__device__ float g_rcpl[NN];
__device__ int   g_cnt[NN];
__device__ int   g_rptr[NN + 1];
__device__ int   g_col[NE];
__device__ int   g_bsums[64];

// ---------------- CSR construction ----------------
__global__ void k_zero_int(int* p, int n) {
    int i = blockIdx.x * blockDim.x + threadIdx.x;
    if (i < n) p[i] = 0;
}
__global__ void k_zero_float(float* p, int n) {
    int i = blockIdx.x * blockDim.x + threadIdx.x;
    if (i < n) p[i] = 0.f;
}

__global__ void k_count_dst(const int* __restrict__ dst, int* __restrict__ cnt) {
    int e = blockIdx.x * blockDim.x + threadIdx.x;
    if (e < NE) atomicAdd(&cnt[dst[e]], 1);
}

__global__ void k_scan1(const int* __restrict__ cnt, int* __restrict__ rptr,
                        int* __restrict__ bsums) {
    __shared__ int sh[1024];
    int i = blockIdx.x * 1024 + threadIdx.x;
    int v = (i < NN) ? cnt[i] : 0;
    sh[threadIdx.x] = v;
    __syncthreads();
    for (int off = 1; off < 1024; off <<= 1) {
        int t = 0;
        if ((int)threadIdx.x >= off) t = sh[threadIdx.x - off];
        __syncthreads();
        sh[threadIdx.x] += t;
        __syncthreads();
    }
    if (i < NN) rptr[i] = sh[threadIdx.x] - v;   // exclusive
    if (threadIdx.x == 1023) bsums[blockIdx.x] = sh[1023];
}

__global__ void k_scan2(int* bsums, int nb) {
    if (threadIdx.x == 0 && blockIdx.x == 0) {
        int acc = 0;
        for (int b = 0; b < nb; b++) { int t = bsums[b]; bsums[b] = acc; acc += t; }
    }
}

__global__ void k_scan3(int* __restrict__ rptr, const int* __restrict__ bsums) {
    int i = blockIdx.x * 1024 + threadIdx.x;
    if (i < NN) rptr[i] += bsums[blockIdx.x];
    if (i == 0) rptr[NN] = NE;
}

__global__ void k_dinv_reset(int* __restrict__ cnt, float* __restrict__ dinv) {
    int n = blockIdx.x * blockDim.x + threadIdx.x;
    if (n < NN) {
        dinv[n] = rsqrtf((float)(cnt[n] + 1));  // +1 self loop
        cnt[n] = 0;                             // becomes cursor
    }
}

__global__ void k_fill_csr(const int* __restrict__ src, const int* __restrict__ dst,
                           const int* __restrict__ rptr, int* __restrict__ cnt,
                           int* __restrict__ colv) {
    int e = blockIdx.x * blockDim.x + threadIdx.x;
    if (e < NE) {
        int d = dst[e];
        int p = rptr[d] + atomicAdd(&cnt[d], 1);
        colv[p] = src[e];
    }
}

// ================= tf32 tensor-core GEMM (PREC=3: fp32-accurate 3xTF32; PREC=1: raw tf32)
// C[M,N] = op(A) @ op(B), BM=BN=128, BK=32, 256 threads (8 warps, warp tile 64x32)
// PREC=3: x = xhi + xlo (xhi = x & 0xFFFFE000); acc += hi*hi + hi*lo + lo*hi (~2^-22)
// PREC=1: single MMA on truncated operands (~5e-4 biased shrink) — use only where
//         downstream softmax/LayerNorm cancels scale errors.
// NOTE: (kE - kB) must be a multiple of 32 for every launch.
#define GBM 128
#define GBN 128
#define GBK 32
#define LDMK 36    // [row][k] storage (16B-aligned rows for ldmatrix)
#define LDKM 132   // [k][row] storage
#define ASZ 4608   // max(128*36, 32*132)
#define STG 9216   // ASZ * 2 (A + B region)
#define GSMEM (2 * STG * 4)

__device__ __forceinline__ void cp16(unsigned dst, const float* src, bool v) {
    int sz = v ? 16 : 0;
    asm volatile("cp.async.cg.shared.global [%0], [%1], 16, %2;\n"
                 :: "r"(dst), "l"(src), "r"(sz));
}
#define CP_COMMIT asm volatile("cp.async.commit_group;\n")
#define CP_WAIT0  asm volatile("cp.async.wait_group 0;\n" ::: "memory")

__device__ __forceinline__ void mma8(float* d, unsigned a0, unsigned a1, unsigned a2,
                                     unsigned a3, unsigned b0, unsigned b1) {
    asm volatile("mma.sync.aligned.m16n8k8.row.col.f32.tf32.tf32.f32 "
        "{%0,%1,%2,%3}, {%4,%5,%6,%7}, {%8,%9}, {%0,%1,%2,%3};\n"
        : "+f"(d[0]), "+f"(d[1]), "+f"(d[2]), "+f"(d[3])
        : "r"(a0), "r"(a1), "r"(a2), "r"(a3), "r"(b0), "r"(b1));
}
__device__ __forceinline__ unsigned lo_part(unsigned x) {
    return __float_as_uint(__uint_as_float(x) - __uint_as_float(x & 0xFFFFE000u));
}

template<int TRANSA, int TRANSB, int EPI, int PREC>
__global__ __launch_bounds__(256, 1)
void k_gemm(const float* __restrict__ A, const float* __restrict__ B,
            float* __restrict__ C, int M, int N, int Ktot, int kChunk,
            int ldA, int ldB, int ldC, float alpha,
            const float* __restrict__ bias, const float* __restrict__ rowscale,
            int relu)
{
    extern __shared__ float smf[];
    const int tid = threadIdx.x;
    const int lane = tid & 31;
    const int warp = tid >> 5;
    const int wm = (warp >> 2) * 64;
    const int wn = (warp & 3) * 32;
    const int g = lane >> 2, tig = lane & 3;
    const int m0 = blockIdx.x * GBM;
    const int n0 = blockIdx.y * GBN;
    const int kB = blockIdx.z * kChunk;
    const int kE = (Ktot < kB + kChunk) ? Ktot : (kB + kChunk);
    const int T = (kE - kB) >> 5;

    const unsigned sbase = (unsigned)__cvta_generic_to_shared(smf);

    int arow, acol, brow, bcol;
    if (!TRANSA) { arow = tid >> 3; acol = (tid & 7) * 4; }
    else         { arow = tid >> 5; acol = (tid & 31) * 4; }
    if (!TRANSB) { brow = tid >> 5; bcol = (tid & 31) * 4; }
    else         { brow = tid >> 3; bcol = (tid & 7) * 4; }

    const int a_lr = ((lane >> 3) & 1) * 8 + (lane & 7);
    const int a_lk = (lane >> 4) * 4;
    const int b_lr = (lane >> 4) * 8 + (lane & 7);
    const int b_lk = ((lane >> 3) & 1) * 4;

    float acc[4][4][4];
#pragma unroll
    for (int i = 0; i < 4; i++)
#pragma unroll
        for (int j = 0; j < 4; j++)
#pragma unroll
            for (int q = 0; q < 4; q++) acc[i][j][q] = 0.f;

    auto prefetch = [&](int kt, int s) {
        unsigned abase = sbase + (unsigned)(s * STG) * 4u;
        unsigned bbase = abase + ASZ * 4u;
        int kof = kB + kt * 32;
#pragma unroll
        for (int p = 0; p < 4; p++) {
            if (!TRANSA) {
                int m = m0 + arow + 32 * p;
                bool v = m < M;
                const float* src = A + (size_t)(v ? m : 0) * ldA + kof + acol;
                cp16(abase + (unsigned)((arow + 32 * p) * LDMK + acol) * 4u, src, v);
            } else {
                int m = m0 + acol;
                bool v = m < M;
                const float* src = A + (size_t)(kof + arow + 8 * p) * ldA + (v ? m : 0);
                cp16(abase + (unsigned)((arow + 8 * p) * LDKM + acol) * 4u, src, v);
            }
        }
#pragma unroll
        for (int p = 0; p < 4; p++) {
            if (!TRANSB) {
                int n = n0 + bcol;
                bool v = n < N;
                const float* src = B + (size_t)(kof + brow + 8 * p) * ldB + (v ? n : 0);
                cp16(bbase + (unsigned)((brow + 8 * p) * LDKM + bcol) * 4u, src, v);
            } else {
                int n = n0 + brow + 32 * p;
                bool v = n < N;
                const float* src = B + (size_t)(v ? n : 0) * ldB + kof + bcol;
                cp16(bbase + (unsigned)((brow + 32 * p) * LDMK + bcol) * 4u, src, v);
            }
        }
    };

    prefetch(0, 0);
    CP_COMMIT;
    int s = 0;
    for (int kt = 0; kt < T; kt++) {
        CP_WAIT0;
        __syncthreads();
        if (kt + 1 < T) { prefetch(kt + 1, s ^ 1); CP_COMMIT; }
        const float* AsF = smf + s * STG;
        const float* BsF = AsF + ASZ;
        unsigned abase = sbase + (unsigned)(s * STG) * 4u;
        unsigned bbase = abase + ASZ * 4u;
#pragma unroll
        for (int ks = 0; ks < 4; ks++) {
            const int k0 = ks * 8;
            unsigned ah[4][4], al[4][4];
            if (!TRANSA) {
#pragma unroll
                for (int mf = 0; mf < 4; mf++) {
                    unsigned addr = abase + (unsigned)((wm + mf * 16 + a_lr) * LDMK + k0 + a_lk) * 4u;
                    asm volatile("ldmatrix.sync.aligned.m8n8.x4.shared.b16 {%0,%1,%2,%3}, [%4];\n"
                        : "=r"(ah[mf][0]), "=r"(ah[mf][1]), "=r"(ah[mf][2]), "=r"(ah[mf][3]) : "r"(addr));
                }
            } else {
#pragma unroll
                for (int mf = 0; mf < 4; mf++) {
                    int mb = wm + mf * 16 + g;
                    ah[mf][0] = __float_as_uint(AsF[(k0 + tig) * LDKM + mb]);
                    ah[mf][1] = __float_as_uint(AsF[(k0 + tig) * LDKM + mb + 8]);
                    ah[mf][2] = __float_as_uint(AsF[(k0 + tig + 4) * LDKM + mb]);
                    ah[mf][3] = __float_as_uint(AsF[(k0 + tig + 4) * LDKM + mb + 8]);
                }
            }
            if (PREC == 3) {
#pragma unroll
                for (int mf = 0; mf < 4; mf++)
#pragma unroll
                    for (int q = 0; q < 4; q++) {
                        al[mf][q] = lo_part(ah[mf][q]);
                        ah[mf][q] &= 0xFFFFE000u;
                    }
            }
            unsigned braw[4][2];
            if (TRANSB) {
#pragma unroll
                for (int h = 0; h < 2; h++) {
                    unsigned addr = bbase + (unsigned)((wn + h * 16 + b_lr) * LDMK + k0 + b_lk) * 4u;
                    asm volatile("ldmatrix.sync.aligned.m8n8.x4.shared.b16 {%0,%1,%2,%3}, [%4];\n"
                        : "=r"(braw[2 * h][0]), "=r"(braw[2 * h][1]),
                          "=r"(braw[2 * h + 1][0]), "=r"(braw[2 * h + 1][1])
                        : "r"(addr));
                }
            } else {
#pragma unroll
                for (int nf = 0; nf < 4; nf++) {
                    int nb = wn + nf * 8 + g;
                    braw[nf][0] = __float_as_uint(BsF[(k0 + tig) * LDKM + nb]);
                    braw[nf][1] = __float_as_uint(BsF[(k0 + tig + 4) * LDKM + nb]);
                }
            }
#pragma unroll
            for (int nf = 0; nf < 4; nf++) {
                if (PREC == 3) {
                    unsigned bh0 = braw[nf][0] & 0xFFFFE000u;
                    unsigned bh1 = braw[nf][1] & 0xFFFFE000u;
                    unsigned bl0 = lo_part(braw[nf][0]);
                    unsigned bl1 = lo_part(braw[nf][1]);
#pragma unroll
                    for (int mf = 0; mf < 4; mf++) {
                        mma8(acc[mf][nf], ah[mf][0], ah[mf][1], ah[mf][2], ah[mf][3], bh0, bh1);
                        mma8(acc[mf][nf], ah[mf][0], ah[mf][1], ah[mf][2], ah[mf][3], bl0, bl1);
                        mma8(acc[mf][nf], al[mf][0], al[mf][1], al[mf][2], al[mf][3], bh0, bh1);
                    }
                } else {
#pragma unroll
                    for (int mf = 0; mf < 4; mf++)
                        mma8(acc[mf][nf], ah[mf][0], ah[mf][1], ah[mf][2], ah[mf][3],
                             braw[nf][0], braw[nf][1]);
                }
            }
        }
        s ^= 1;
    }

    // epilogue
#pragma unroll
    for (int mf = 0; mf < 4; mf++) {
        int r0 = m0 + wm + mf * 16 + g;
        int r1 = r0 + 8;
#pragma unroll
        for (int nf = 0; nf < 4; nf++) {
            int c = n0 + wn + nf * 8 + tig * 2;
            float v0 = acc[mf][nf][0] * alpha;
            float v1 = acc[mf][nf][1] * alpha;
            float v2 = acc[mf][nf][2] * alpha;
            float v3 = acc[mf][nf][3] * alpha;
            if (EPI == 0) {
                float bb0 = bias ? bias[c] : 0.f;
                float bb1 = bias ? bias[c + 1] : 0.f;
                v0 += bb0; v1 += bb1; v2 += bb0; v3 += bb1;
                if (relu) {
                    v0 = fmaxf(v0, 0.f); v1 = fmaxf(v1, 0.f);
                    v2 = fmaxf(v2, 0.f); v3 = fmaxf(v3, 0.f);
                }
                if (c < N) {
                    if (r0 < M) { C[(size_t)r0 * ldC + c] = v0; C[(size_t)r0 * ldC + c + 1] = v1; }
                    if (r1 < M) { C[(size_t)r1 * ldC + c] = v2; C[(size_t)r1 * ldC + c + 1] = v3; }
                }
            } else if (EPI == 1) {
                if (c < N) {
                    if (r0 < M) { atomicAdd(&C[(size_t)r0 * ldC + c], v0); atomicAdd(&C[(size_t)r0 * ldC + c + 1], v1); }
                    if (r1 < M) { atomicAdd(&C[(size_t)r1 * ldC + c], v2); atomicAdd(&C[(size_t)r1 * ldC + c + 1], v3); }
                }
            } else {
                if (c < N) {
                    if (r0 < M) { float sc = rowscale[r0]; C[(size_t)r0 * ldC + c] = sc * v0; C[(size_t)r0 * ldC + c + 1] = sc * v1; }
                    if (r1 < M) { float sc = rowscale[r1]; C[(size_t)r1 * ldC + c] = sc * v2; C[(size_t)r1 * ldC + c + 1] = sc * v3; }
                }
            }
        }
    }
}

// ---------------- GCN aggregation ----------------
__global__ void k_aggregate(const float* __restrict__ H, const int* __restrict__ rptr,
                            const int* __restrict__ colv, const float* __restrict__ dinv,
                            const float* __restrict__ bias, float* __restrict__ Out,
                            int relu) {
    int w = (blockIdx.x * blockDim.x + threadIdx.x) >> 5;
    int lane = threadIdx.x & 31;
    if (w >= NN) return;
    const float4* H4 = (const float4*)H;
    float4 acc = make_float4(0.f, 0.f, 0.f, 0.f);
    int s = rptr[w], e = rptr[w + 1];
    for (int j = s; j < e; j++) {
        int src = colv[j];
        float wt = dinv[src];
        float4 h = H4[src * 32 + lane];
        acc.x += wt * h.x; acc.y += wt * h.y; acc.z += wt * h.z; acc.w += wt * h.w;
    }
    float dn = dinv[w];
    float4 hs = H4[w * 32 + lane];
    float4 bb = ((const float4*)bias)[lane];
    acc.x = dn * (acc.x + dn * hs.x) + bb.x;
    acc.y = dn * (acc.y + dn * hs.y) + bb.y;
    acc.z = dn * (acc.z + dn * hs.z) + bb.z;
    acc.w = dn * (acc.w + dn * hs.w) + bb.w;
    if (relu) {
        acc.x = fmaxf(acc.x, 0.f); acc.y = fmaxf(acc.y, 0.f);
        acc.z = fmaxf(acc.z, 0.f); acc.w = fmaxf(acc.w, 0.f);
    }
    ((float4*)Out)[w * 32 + lane] = acc;
}

// ---------------- per-node-column softmax over K (4 k-slices per column) -----------
__global__ void k_softmax_cols(float* __restrict__ Sc, float* __restrict__ rcpl) {
    __shared__ float red[4][64];
    int nl = threadIdx.x & 63;
    int sl = threadIdx.x >> 6;
    int n = blockIdx.x * 64 + nl;
    bool ok = n < NN;
    float m = -1e30f;
    if (ok) {
#pragma unroll 4
        for (int k = sl; k < KK; k += 4) m = fmaxf(m, Sc[(size_t)k * NN + n]);
    }
    red[sl][nl] = m;
    __syncthreads();
    m = fmaxf(fmaxf(red[0][nl], red[1][nl]), fmaxf(red[2][nl], red[3][nl]));
    __syncthreads();
    float l = 0.f;
    if (ok) {
#pragma unroll 4
        for (int k = sl; k < KK; k += 4) {
            size_t idx = (size_t)k * NN + n;
            float e = __expf(Sc[idx] - m);
            l += e;
            Sc[idx] = e;
        }
    }
    red[sl][nl] = l;
    __syncthreads();
    if (sl == 0 && ok)
        rcpl[n] = 1.f / (red[0][nl] + red[1][nl] + red[2][nl] + red[3][nl]);
}

// ---------------- elementwise helpers ----------------
__global__ void k_scale_rows(float* __restrict__ X, const float* __restrict__ r, int n) {
    int i = blockIdx.x * blockDim.x + threadIdx.x;
    if (i < n) X[i] *= r[i >> 7];
}
__global__ void k_copy(const float* __restrict__ a, float* __restrict__ b, int n) {
    int i = blockIdx.x * blockDim.x + threadIdx.x;
    if (i < n) b[i] = a[i];
}
__global__ void k_add(float* __restrict__ a, const float* __restrict__ b, int n) {
    int i = blockIdx.x * blockDim.x + threadIdx.x;
    if (i < n) a[i] += b[i];
}

// ---------------- LayerNorm rows of X[M,128] ----------------
__global__ void k_layernorm(float* __restrict__ X, const float* __restrict__ g,
                            const float* __restrict__ b, int M) {
    int w = (blockIdx.x * blockDim.x + threadIdx.x) >> 5;
    int lane = threadIdx.x & 31;
    if (w >= M) return;
    float4 v = ((const float4*)X)[w * 32 + lane];
    float s = v.x + v.y + v.z + v.w;
    float sq = v.x * v.x + v.y * v.y + v.z * v.z + v.w * v.w;
#pragma unroll
    for (int o = 16; o; o >>= 1) {
        s += __shfl_xor_sync(0xffffffffu, s, o);
        sq += __shfl_xor_sync(0xffffffffu, sq, o);
    }
    float mean = s * (1.f / 128.f);
    float var = sq * (1.f / 128.f) - mean * mean;
    float rstd = rsqrtf(var + 1e-5f);
    float4 gg = ((const float4*)g)[lane];
    float4 bb = ((const float4*)b)[lane];
    v.x = (v.x - mean) * rstd * gg.x + bb.x;
    v.y = (v.y - mean) * rstd * gg.y + bb.y;
    v.z = (v.z - mean) * rstd * gg.z + bb.z;
    v.w = (v.w - mean) * rstd * gg.w + bb.w;
    ((float4*)X)[w * 32 + lane] = v;
}

// ---------------- host orchestration ----------------
static float* faddr(const void* sym) {
    void* p = nullptr;
    cudaGetSymbolAddress(&p, sym);
    return (float*)p;
}
static int* iaddr(const void* sym) {
    void* p = nullptr;
    cudaGetSymbolAddress(&p, sym);
    return (int*)p;
}

extern "C" void kernel_launch(void* const* d_in, const int* in_sizes, int n_in,
                              void* d_out, int out_size) {
    const float* x  = (const float*)d_in[0];
    const int*   ei = (const int*)d_in[1];
    const float* W1 = (const float*)d_in[3];  const float* b1 = (const float*)d_in[4];
    const float* W2 = (const float*)d_in[5];  const float* b2 = (const float*)d_in[6];
    const float* S  = (const float*)d_in[7];
    const float* Wq = (const float*)d_in[8];  const float* bq = (const float*)d_in[9];
    const float* Wk = (const float*)d_in[10]; const float* bk = (const float*)d_in[11];
    const float* Wv = (const float*)d_in[12]; const float* bv = (const float*)d_in[13];
    const float* Wo = (const float*)d_in[14]; const float* bo = (const float*)d_in[15];
    const float* g0 = (const float*)d_in[16]; const float* be0 = (const float*)d_in[17];
    const float* g1 = (const float*)d_in[18]; const float* be1 = (const float*)d_in[19];
    const float* Wl = (const float*)d_in[20]; const float* bl = (const float*)d_in[21];
    const float* W3 = (const float*)d_in[22]; const float* b3 = (const float*)d_in[23];
    const float* W4 = (const float*)d_in[24]; const float* b4 = (const float*)d_in[25];
    const float* W5 = (const float*)d_in[26]; const float* b5 = (const float*)d_in[27];

    const int* src = ei;
    const int* dst = ei + NE;

    float* score = faddr(g_score);
    float* t     = faddr(g_t);
    float* h1    = faddr(g_h1);
    float* h2    = faddr(g_h2);
    float* Kd    = faddr(g_Kd);
    float* Vd    = faddr(g_Vd);
    float* Q     = faddr(g_Q);
    float* outb  = faddr(g_out);
    float* t2    = faddr(g_t2);
    float* xl    = faddr(g_xl);
    float* dinv  = faddr(g_dinv);
    float* rcpl  = faddr(g_rcpl);
    int* cnt   = iaddr(g_cnt);
    int* rptr  = iaddr(g_rptr);
    int* colv  = iaddr(g_col);
    int* bsums = iaddr(g_bsums);

    // opt-in dynamic smem for the tf32 gemm instantiations (idempotent, capture-safe)
    cudaFuncSetAttribute((const void*)k_gemm<0,0,0,3>, cudaFuncAttributeMaxDynamicSharedMemorySize, GSMEM);
    cudaFuncSetAttribute((const void*)k_gemm<0,1,0,1>, cudaFuncAttributeMaxDynamicSharedMemorySize, GSMEM);
    cudaFuncSetAttribute((const void*)k_gemm<0,0,1,1>, cudaFuncAttributeMaxDynamicSharedMemorySize, GSMEM);
    cudaFuncSetAttribute((const void*)k_gemm<1,0,2,3>, cudaFuncAttributeMaxDynamicSharedMemorySize, GSMEM);

    const int mbN = (NN + 127) / 128;   // 157
    const int mbK = (KK + 127) / 128;   // 16
    float* dOut = (float*)d_out;
    const float rs128 = 0.0883883476483184f;  // 1/sqrt(128)

    // --- zero the k-padding rows (score rows KK..KK32, xl rows KK..KK32) ---
    k_zero_float<<<((KK32 - KK) * NN + 255) / 256, 256>>>(score + (size_t)KK * NN, (KK32 - KK) * NN);
    k_zero_float<<<((KK32 - KK) * DD + 255) / 256, 256>>>(xl + (size_t)KK * DD, (KK32 - KK) * DD);

    // --- CSR + degree ---
    k_zero_int<<<(NN + 255) / 256, 256>>>(cnt, NN);
    k_count_dst<<<(NE + 255) / 256, 256>>>(dst, cnt);
    k_scan1<<<20, 1024>>>(cnt, rptr, bsums);
    k_scan2<<<1, 32>>>(bsums, 20);
    k_scan3<<<20, 1024>>>(rptr, bsums);
    k_dinv_reset<<<(NN + 255) / 256, 256>>>(cnt, dinv);
    k_fill_csr<<<(NE + 255) / 256, 256>>>(src, dst, rptr, cnt, colv);

    // --- GCN1, GCN2 ---
    k_gemm<0,0,0,3><<<dim3(mbN,1,1), 256, GSMEM>>>(x,  W1, t, NN, 128, 128, 128, 128, 128, 128, 1.f, nullptr, nullptr, 0);
    k_aggregate<<<(NN * 32 + 255) / 256, 256>>>(t, rptr, colv, dinv, b1, h1, 1);
    k_gemm<0,0,0,3><<<dim3(mbN,1,1), 256, GSMEM>>>(h1, W2, t, NN, 128, 128, 128, 128, 128, 128, 1.f, nullptr, nullptr, 0);
    k_aggregate<<<(NN * 32 + 255) / 256, 256>>>(t, rptr, colv, dinv, b2, h2, 1);

    // --- Q, Kd, Vd ---
    k_gemm<0,0,0,3><<<dim3(mbK,1,1), 256, GSMEM>>>(S,  Wq, Q, KK, 128, 128, 128, 128, 128, 128, 1.f, bq, nullptr, 0);
    k_gemm<0,0,0,3><<<dim3(mbN,1,1), 256, GSMEM>>>(h2, Wk, t, NN, 128, 128, 128, 128, 128, 128, 1.f, nullptr, nullptr, 0);
    k_aggregate<<<(NN * 32 + 255) / 256, 256>>>(t, rptr, colv, dinv, bk, Kd, 0);
    k_gemm<0,0,0,3><<<dim3(mbN,1,1), 256, GSMEM>>>(h2, Wv, t, NN, 128, 128, 128, 128, 128, 128, 1.f, nullptr, nullptr, 0);
    k_aggregate<<<(NN * 32 + 255) / 256, 256>>>(t, rptr, colv, dinv, bv, Vd, 0);

    // --- attention: score = Q @ Kd^T / sqrt(D)  (1xTF32: softmax washes scale bias) ---
    k_gemm<0,1,0,1><<<dim3(mbK, mbN, 1), 256, GSMEM>>>(Q, Kd, score, KK, NN, 128, 128, 128, 128, NN, rs128, nullptr, nullptr, 0);
    k_softmax_cols<<<(NN + 63) / 64, 256>>>(score, rcpl);
    k_scale_rows<<<(NN * DD + 255) / 256, 256>>>(Vd, rcpl, NN * DD);   // fold 1/l into V
    k_copy<<<(KK * DD + 255) / 256, 256>>>(Q, outb, KK * DD);          // Out = Q
    // Out += Aexp @ Vd_scaled (1xTF32: LayerNorm right after washes scale bias)
    k_gemm<0,0,1,1><<<dim3(mbK, 1, 16), 256, GSMEM>>>(score, Vd, outb, KK, 128, NN, 1280, NN, 128, 128, 1.f, nullptr, nullptr, 0);

    // --- epilogue on [K,128] ---
    k_layernorm<<<(KK * 32 + 255) / 256, 256>>>(outb, g0, be0, KK);
    k_gemm<0,0,0,3><<<dim3(mbK,1,1), 256, GSMEM>>>(outb, Wo, t2, KK, 128, 128, 128, 128, 128, 128, 1.f, bo, nullptr, 1);
    k_add<<<(KK * DD + 255) / 256, 256>>>(outb, t2, KK * DD);
    k_layernorm<<<(KK * 32 + 255) / 256, 256>>>(outb, g1, be1, KK);
    k_gemm<0,0,0,3><<<dim3(mbK,1,1), 256, GSMEM>>>(outb, Wl, xl, KK, 128, 128, 128, 128, 128, 128, 1.f, bl, nullptr, 0);

    // --- x_out = rcpl[n] * (Aexp^T @ xl), k padded to KK32 (pad rows are zero); 3x: no
    //     downstream normalization to absorb bias ---
    k_gemm<1,0,2,3><<<dim3(mbN,1,1), 256, GSMEM>>>(score, xl, h1, NN, 128, KK32, KK32, NN, 128, 128, 1.f, nullptr, rcpl, 0);

    // --- GCN3, GCN4, GCN5 ---
    k_gemm<0,0,0,3><<<dim3(mbN,1,1), 256, GSMEM>>>(h1, W3, t, NN, 128, 128, 128, 128, 128, 128, 1.f, nullptr, nullptr, 0);
    k_aggregate<<<(NN * 32 + 255) / 256, 256>>>(t, rptr, colv, dinv, b3, h2, 1);
    k_gemm<0,0,0,3><<<dim3(mbN,1,1), 256, GSMEM>>>(h2, W4, t, NN, 128, 128, 128, 128, 128, 128, 1.f, nullptr, nullptr, 0);
    k_aggregate<<<(NN * 32 + 255) / 256, 256>>>(t, rptr, colv, dinv, b4, h1, 1);
    k_gemm<0,0,0,3><<<dim3(mbN,1,1), 256, GSMEM>>>(h1, W5, t, NN, 128, 128, 128, 128, 128, 128, 1.f, nullptr, nullptr, 0);
    k_aggregate<<<(NN * 32 + 255) / 256, 256>>>(t, rptr, colv, dinv, b5, dOut, 0);
}

// round 11
// speedup vs baseline: 2.6508x; 1.2409x over previous
#include <cuda_runtime.h>
#include <math.h>

#define NN 20000
#define NE 320000
#define DD 128
#define KK 2000
#define KK32 2016   // KK padded to multiple of 32 for the ATX gemm

// ---------------- scratch (static device globals; no allocation) ----------------
__device__ float g_score[(size_t)KK32 * NN]; // exp(score - m); rows >= KK are zero
__device__ float g_t[NN * DD];
__device__ float g_h1[NN * DD];
__device__ float g_h2[NN * DD];
__device__ float g_Kd[NN * DD];
__device__ float g_Vd[NN * DD];
__device__ float g_Q[KK * DD];
__device__ float g_out[KK * DD];
__device__ float g_t2[KK * DD];
__device__ float g_xl[KK32 * DD];            // rows >= KK are zero
__device__ float g_dinv[NN];
__device__ float g_rcpl[NN];
__device__ float g_l[NN + 1];                // column sums; [NN] = qmax
__device__ float g_mbound[NN];               // per-column softmax shift (upper bound)
__device__ int   g_cnt[NN];
__device__ int   g_rptr[NN + 1];
__device__ int   g_col[NE];
__device__ int   g_bsums[64];

// ---------------- small utility kernels ----------------
__global__ void k_zero_int(int* p, int n) {
    int i = blockIdx.x * blockDim.x + threadIdx.x;
    if (i < n) p[i] = 0;
}
__global__ void k_zero_float(float* p, int n) {
    int i = blockIdx.x * blockDim.x + threadIdx.x;
    if (i < n) p[i] = 0.f;
}

__global__ void k_count_dst(const int* __restrict__ dst, int* __restrict__ cnt) {
    int e = blockIdx.x * blockDim.x + threadIdx.x;
    if (e < NE) atomicAdd(&cnt[dst[e]], 1);
}

__global__ void k_scan1(const int* __restrict__ cnt, int* __restrict__ rptr,
                        int* __restrict__ bsums) {
    __shared__ int sh[1024];
    int i = blockIdx.x * 1024 + threadIdx.x;
    int v = (i < NN) ? cnt[i] : 0;
    sh[threadIdx.x] = v;
    __syncthreads();
    for (int off = 1; off < 1024; off <<= 1) {
        int t = 0;
        if ((int)threadIdx.x >= off) t = sh[threadIdx.x - off];
        __syncthreads();
        sh[threadIdx.x] += t;
        __syncthreads();
    }
    if (i < NN) rptr[i] = sh[threadIdx.x] - v;   // exclusive
    if (threadIdx.x == 1023) bsums[blockIdx.x] = sh[1023];
}

__global__ void k_scan2(int* bsums, int nb) {
    if (threadIdx.x == 0 && blockIdx.x == 0) {
        int acc = 0;
        for (int b = 0; b < nb; b++) { int t = bsums[b]; bsums[b] = acc; acc += t; }
    }
}

__global__ void k_scan3(int* __restrict__ rptr, const int* __restrict__ bsums) {
    int i = blockIdx.x * 1024 + threadIdx.x;
    if (i < NN) rptr[i] += bsums[blockIdx.x];
    if (i == 0) rptr[NN] = NE;
}

__global__ void k_dinv_reset(int* __restrict__ cnt, float* __restrict__ dinv) {
    int n = blockIdx.x * blockDim.x + threadIdx.x;
    if (n < NN) {
        dinv[n] = rsqrtf((float)(cnt[n] + 1));  // +1 self loop
        cnt[n] = 0;                             // becomes cursor
    }
}

__global__ void k_fill_csr(const int* __restrict__ src, const int* __restrict__ dst,
                           const int* __restrict__ rptr, int* __restrict__ cnt,
                           int* __restrict__ colv) {
    int e = blockIdx.x * blockDim.x + threadIdx.x;
    if (e < NE) {
        int d = dst[e];
        int p = rptr[d] + atomicAdd(&cnt[d], 1);
        colv[p] = src[e];
    }
}

// qmax = max_k ||Q[k,:]||  (stored as g_l[NN]; positive-float int atomicMax)
__global__ void k_qmax(const float* __restrict__ Q, float* __restrict__ qmax) {
    int w = (blockIdx.x * blockDim.x + threadIdx.x) >> 5;
    int lane = threadIdx.x & 31;
    if (w >= KK) return;
    float4 v = ((const float4*)Q)[w * 32 + lane];
    float s = v.x * v.x + v.y * v.y + v.z * v.z + v.w * v.w;
#pragma unroll
    for (int o = 16; o; o >>= 1) s += __shfl_xor_sync(0xffffffffu, s, o);
    if (lane == 0) atomicMax((int*)qmax, __float_as_int(sqrtf(s)));
}

// m[n] = qmax * ||Kd[n,:]|| / sqrt(128)
__global__ void k_mbound(const float* __restrict__ Kd, const float* __restrict__ qmax,
                         float* __restrict__ mb) {
    int w = (blockIdx.x * blockDim.x + threadIdx.x) >> 5;
    int lane = threadIdx.x & 31;
    if (w >= NN) return;
    float4 v = ((const float4*)Kd)[w * 32 + lane];
    float s = v.x * v.x + v.y * v.y + v.z * v.z + v.w * v.w;
#pragma unroll
    for (int o = 16; o; o >>= 1) s += __shfl_xor_sync(0xffffffffu, s, o);
    if (lane == 0) mb[w] = qmax[0] * sqrtf(s) * 0.0883883476483184f;
}

__global__ void k_recip(const float* __restrict__ l, float* __restrict__ r) {
    int n = blockIdx.x * blockDim.x + threadIdx.x;
    if (n < NN) r[n] = 1.f / l[n];
}

// ================= tf32 tensor-core GEMM =================
// PREC=3: 3xTF32 fp32-accurate; PREC=2: split-A only (use with alpha bias correction);
// PREC=1: raw tf32 (only where softmax/LN cancels scale bias).
// EPI 0: C=acc*alpha+bias (opt relu); 1: atomicAdd; 2: C=rowscale[m]*acc*alpha;
// EPI 3: C=exp(acc*alpha - bias[n]) and atomicAdd per-column sums into rowscale[] (=l).
// (kE - kB) must be a multiple of 32 for every launch.
#define GBM 128
#define GBN 128
#define GBK 32
#define LDMK 36
#define LDKM 132
#define ASZ 4608
#define STG 9216
#define GSMEM (2 * STG * 4)

__device__ __forceinline__ void cp16(unsigned dst, const float* src, bool v) {
    int sz = v ? 16 : 0;
    asm volatile("cp.async.cg.shared.global [%0], [%1], 16, %2;\n"
                 :: "r"(dst), "l"(src), "r"(sz));
}
#define CP_COMMIT asm volatile("cp.async.commit_group;\n")
#define CP_WAIT0  asm volatile("cp.async.wait_group 0;\n" ::: "memory")

__device__ __forceinline__ void mma8(float* d, unsigned a0, unsigned a1, unsigned a2,
                                     unsigned a3, unsigned b0, unsigned b1) {
    asm volatile("mma.sync.aligned.m16n8k8.row.col.f32.tf32.tf32.f32 "
        "{%0,%1,%2,%3}, {%4,%5,%6,%7}, {%8,%9}, {%0,%1,%2,%3};\n"
        : "+f"(d[0]), "+f"(d[1]), "+f"(d[2]), "+f"(d[3])
        : "r"(a0), "r"(a1), "r"(a2), "r"(a3), "r"(b0), "r"(b1));
}
__device__ __forceinline__ unsigned lo_part(unsigned x) {
    return __float_as_uint(__uint_as_float(x) - __uint_as_float(x & 0xFFFFE000u));
}

template<int TRANSA, int TRANSB, int EPI, int PREC>
__global__ __launch_bounds__(256, 1)
void k_gemm(const float* __restrict__ A, const float* __restrict__ B,
            float* __restrict__ C, int M, int N, int Ktot, int kChunk,
            int ldA, int ldB, int ldC, float alpha,
            const float* __restrict__ bias, float* __restrict__ rowscale,
            int relu)
{
    extern __shared__ float smf[];
    const int tid = threadIdx.x;
    const int lane = tid & 31;
    const int warp = tid >> 5;
    const int wm = (warp >> 2) * 64;
    const int wn = (warp & 3) * 32;
    const int g = lane >> 2, tig = lane & 3;
    const int m0 = blockIdx.x * GBM;
    const int n0 = blockIdx.y * GBN;
    const int kB = blockIdx.z * kChunk;
    const int kE = (Ktot < kB + kChunk) ? Ktot : (kB + kChunk);
    const int T = (kE - kB) >> 5;

    const unsigned sbase = (unsigned)__cvta_generic_to_shared(smf);

    int arow, acol, brow, bcol;
    if (!TRANSA) { arow = tid >> 3; acol = (tid & 7) * 4; }
    else         { arow = tid >> 5; acol = (tid & 31) * 4; }
    if (!TRANSB) { brow = tid >> 5; bcol = (tid & 31) * 4; }
    else         { brow = tid >> 3; bcol = (tid & 7) * 4; }

    const int a_lr = ((lane >> 3) & 1) * 8 + (lane & 7);
    const int a_lk = (lane >> 4) * 4;
    const int b_lr = (lane >> 4) * 8 + (lane & 7);
    const int b_lk = ((lane >> 3) & 1) * 4;

    float acc[4][4][4];
#pragma unroll
    for (int i = 0; i < 4; i++)
#pragma unroll
        for (int j = 0; j < 4; j++)
#pragma unroll
            for (int q = 0; q < 4; q++) acc[i][j][q] = 0.f;

    auto prefetch = [&](int kt, int s) {
        unsigned abase = sbase + (unsigned)(s * STG) * 4u;
        unsigned bbase = abase + ASZ * 4u;
        int kof = kB + kt * 32;
#pragma unroll
        for (int p = 0; p < 4; p++) {
            if (!TRANSA) {
                int m = m0 + arow + 32 * p;
                bool v = m < M;
                const float* src = A + (size_t)(v ? m : 0) * ldA + kof + acol;
                cp16(abase + (unsigned)((arow + 32 * p) * LDMK + acol) * 4u, src, v);
            } else {
                int m = m0 + acol;
                bool v = m < M;
                const float* src = A + (size_t)(kof + arow + 8 * p) * ldA + (v ? m : 0);
                cp16(abase + (unsigned)((arow + 8 * p) * LDKM + acol) * 4u, src, v);
            }
        }
#pragma unroll
        for (int p = 0; p < 4; p++) {
            if (!TRANSB) {
                int n = n0 + bcol;
                bool v = n < N;
                const float* src = B + (size_t)(kof + brow + 8 * p) * ldB + (v ? n : 0);
                cp16(bbase + (unsigned)((brow + 8 * p) * LDKM + bcol) * 4u, src, v);
            } else {
                int n = n0 + brow + 32 * p;
                bool v = n < N;
                const float* src = B + (size_t)(v ? n : 0) * ldB + kof + bcol;
                cp16(bbase + (unsigned)((brow + 32 * p) * LDMK + bcol) * 4u, src, v);
            }
        }
    };

    prefetch(0, 0);
    CP_COMMIT;
    int s = 0;
    for (int kt = 0; kt < T; kt++) {
        CP_WAIT0;
        __syncthreads();
        if (kt + 1 < T) { prefetch(kt + 1, s ^ 1); CP_COMMIT; }
        const float* AsF = smf + s * STG;
        const float* BsF = AsF + ASZ;
        unsigned abase = sbase + (unsigned)(s * STG) * 4u;
        unsigned bbase = abase + ASZ * 4u;
#pragma unroll
        for (int ks = 0; ks < 4; ks++) {
            const int k0 = ks * 8;
            unsigned ah[4][4], al[4][4];
            if (!TRANSA) {
#pragma unroll
                for (int mf = 0; mf < 4; mf++) {
                    unsigned addr = abase + (unsigned)((wm + mf * 16 + a_lr) * LDMK + k0 + a_lk) * 4u;
                    asm volatile("ldmatrix.sync.aligned.m8n8.x4.shared.b16 {%0,%1,%2,%3}, [%4];\n"
                        : "=r"(ah[mf][0]), "=r"(ah[mf][1]), "=r"(ah[mf][2]), "=r"(ah[mf][3]) : "r"(addr));
                }
            } else {
#pragma unroll
                for (int mf = 0; mf < 4; mf++) {
                    int mb = wm + mf * 16 + g;
                    ah[mf][0] = __float_as_uint(AsF[(k0 + tig) * LDKM + mb]);
                    ah[mf][1] = __float_as_uint(AsF[(k0 + tig) * LDKM + mb + 8]);
                    ah[mf][2] = __float_as_uint(AsF[(k0 + tig + 4) * LDKM + mb]);
                    ah[mf][3] = __float_as_uint(AsF[(k0 + tig + 4) * LDKM + mb + 8]);
                }
            }
            if (PREC >= 2) {
#pragma unroll
                for (int mf = 0; mf < 4; mf++)
#pragma unroll
                    for (int q = 0; q < 4; q++) {
                        al[mf][q] = lo_part(ah[mf][q]);
                        ah[mf][q] &= 0xFFFFE000u;
                    }
            }
            unsigned braw[4][2];
            if (TRANSB) {
#pragma unroll
                for (int h = 0; h < 2; h++) {
                    unsigned addr = bbase + (unsigned)((wn + h * 16 + b_lr) * LDMK + k0 + b_lk) * 4u;
                    asm volatile("ldmatrix.sync.aligned.m8n8.x4.shared.b16 {%0,%1,%2,%3}, [%4];\n"
                        : "=r"(braw[2 * h][0]), "=r"(braw[2 * h][1]),
                          "=r"(braw[2 * h + 1][0]), "=r"(braw[2 * h + 1][1])
                        : "r"(addr));
                }
            } else {
#pragma unroll
                for (int nf = 0; nf < 4; nf++) {
                    int nb = wn + nf * 8 + g;
                    braw[nf][0] = __float_as_uint(BsF[(k0 + tig) * LDKM + nb]);
                    braw[nf][1] = __float_as_uint(BsF[(k0 + tig + 4) * LDKM + nb]);
                }
            }
#pragma unroll
            for (int nf = 0; nf < 4; nf++) {
                if (PREC == 3) {
                    unsigned bh0 = braw[nf][0] & 0xFFFFE000u;
                    unsigned bh1 = braw[nf][1] & 0xFFFFE000u;
                    unsigned bl0 = lo_part(braw[nf][0]);
                    unsigned bl1 = lo_part(braw[nf][1]);
#pragma unroll
                    for (int mf = 0; mf < 4; mf++) {
                        mma8(acc[mf][nf], ah[mf][0], ah[mf][1], ah[mf][2], ah[mf][3], bh0, bh1);
                        mma8(acc[mf][nf], ah[mf][0], ah[mf][1], ah[mf][2], ah[mf][3], bl0, bl1);
                        mma8(acc[mf][nf], al[mf][0], al[mf][1], al[mf][2], al[mf][3], bh0, bh1);
                    }
                } else if (PREC == 2) {
#pragma unroll
                    for (int mf = 0; mf < 4; mf++) {
                        mma8(acc[mf][nf], ah[mf][0], ah[mf][1], ah[mf][2], ah[mf][3],
                             braw[nf][0], braw[nf][1]);
                        mma8(acc[mf][nf], al[mf][0], al[mf][1], al[mf][2], al[mf][3],
                             braw[nf][0], braw[nf][1]);
                    }
                } else {
#pragma unroll
                    for (int mf = 0; mf < 4; mf++)
                        mma8(acc[mf][nf], ah[mf][0], ah[mf][1], ah[mf][2], ah[mf][3],
                             braw[nf][0], braw[nf][1]);
                }
            }
        }
        s ^= 1;
    }

    // epilogue
    float cs[4][2];
    if (EPI == 3) {
#pragma unroll
        for (int nf = 0; nf < 4; nf++) { cs[nf][0] = 0.f; cs[nf][1] = 0.f; }
    }
#pragma unroll
    for (int mf = 0; mf < 4; mf++) {
        int r0 = m0 + wm + mf * 16 + g;
        int r1 = r0 + 8;
#pragma unroll
        for (int nf = 0; nf < 4; nf++) {
            int c = n0 + wn + nf * 8 + tig * 2;
            float v0 = acc[mf][nf][0] * alpha;
            float v1 = acc[mf][nf][1] * alpha;
            float v2 = acc[mf][nf][2] * alpha;
            float v3 = acc[mf][nf][3] * alpha;
            if (EPI == 0) {
                float bb0 = bias ? bias[c] : 0.f;
                float bb1 = bias ? bias[c + 1] : 0.f;
                v0 += bb0; v1 += bb1; v2 += bb0; v3 += bb1;
                if (relu) {
                    v0 = fmaxf(v0, 0.f); v1 = fmaxf(v1, 0.f);
                    v2 = fmaxf(v2, 0.f); v3 = fmaxf(v3, 0.f);
                }
                if (c < N) {
                    if (r0 < M) { C[(size_t)r0 * ldC + c] = v0; C[(size_t)r0 * ldC + c + 1] = v1; }
                    if (r1 < M) { C[(size_t)r1 * ldC + c] = v2; C[(size_t)r1 * ldC + c + 1] = v3; }
                }
            } else if (EPI == 1) {
                if (c < N) {
                    if (r0 < M) { atomicAdd(&C[(size_t)r0 * ldC + c], v0); atomicAdd(&C[(size_t)r0 * ldC + c + 1], v1); }
                    if (r1 < M) { atomicAdd(&C[(size_t)r1 * ldC + c], v2); atomicAdd(&C[(size_t)r1 * ldC + c + 1], v3); }
                }
            } else if (EPI == 2) {
                if (c < N) {
                    if (r0 < M) { float sc = rowscale[r0]; C[(size_t)r0 * ldC + c] = sc * v0; C[(size_t)r0 * ldC + c + 1] = sc * v1; }
                    if (r1 < M) { float sc = rowscale[r1]; C[(size_t)r1 * ldC + c] = sc * v2; C[(size_t)r1 * ldC + c + 1] = sc * v3; }
                }
            } else {
                // EPI 3: exp(score - mbound[n]) + column partial sums
                bool c0ok = (c < N), c1ok = (c + 1 < N);
                float mc0 = c0ok ? bias[c] : 0.f;
                float mc1 = c1ok ? bias[c + 1] : 0.f;
                if (r0 < M) {
                    if (c0ok) { float e = __expf(v0 - mc0); C[(size_t)r0 * ldC + c] = e; cs[nf][0] += e; }
                    if (c1ok) { float e = __expf(v1 - mc1); C[(size_t)r0 * ldC + c + 1] = e; cs[nf][1] += e; }
                }
                if (r1 < M) {
                    if (c0ok) { float e = __expf(v2 - mc0); C[(size_t)r1 * ldC + c] = e; cs[nf][0] += e; }
                    if (c1ok) { float e = __expf(v3 - mc1); C[(size_t)r1 * ldC + c + 1] = e; cs[nf][1] += e; }
                }
            }
        }
    }
    if (EPI == 3) {
        // reduce over the 8 g-lanes (same tig -> same columns), then one atomic per column
#pragma unroll
        for (int nf = 0; nf < 4; nf++) {
#pragma unroll
            for (int j = 0; j < 2; j++) {
                float v = cs[nf][j];
                v += __shfl_xor_sync(0xffffffffu, v, 4);
                v += __shfl_xor_sync(0xffffffffu, v, 8);
                v += __shfl_xor_sync(0xffffffffu, v, 16);
                int c = n0 + wn + nf * 8 + tig * 2 + j;
                if (lane < 4 && c < N) atomicAdd(&rowscale[c], v);
            }
        }
    }
}

// ---------------- GCN aggregation ----------------
__global__ void k_aggregate(const float* __restrict__ H, const int* __restrict__ rptr,
                            const int* __restrict__ colv, const float* __restrict__ dinv,
                            const float* __restrict__ bias, float* __restrict__ Out,
                            int relu) {
    int w = (blockIdx.x * blockDim.x + threadIdx.x) >> 5;
    int lane = threadIdx.x & 31;
    if (w >= NN) return;
    const float4* H4 = (const float4*)H;
    float4 acc = make_float4(0.f, 0.f, 0.f, 0.f);
    int s = rptr[w], e = rptr[w + 1];
    for (int j = s; j < e; j++) {
        int src = colv[j];
        float wt = dinv[src];
        float4 h = H4[src * 32 + lane];
        acc.x += wt * h.x; acc.y += wt * h.y; acc.z += wt * h.z; acc.w += wt * h.w;
    }
    float dn = dinv[w];
    float4 hs = H4[w * 32 + lane];
    float4 bb = ((const float4*)bias)[lane];
    acc.x = dn * (acc.x + dn * hs.x) + bb.x;
    acc.y = dn * (acc.y + dn * hs.y) + bb.y;
    acc.z = dn * (acc.z + dn * hs.z) + bb.z;
    acc.w = dn * (acc.w + dn * hs.w) + bb.w;
    if (relu) {
        acc.x = fmaxf(acc.x, 0.f); acc.y = fmaxf(acc.y, 0.f);
        acc.z = fmaxf(acc.z, 0.f); acc.w = fmaxf(acc.w, 0.f);
    }
    ((float4*)Out)[w * 32 + lane] = acc;
}

// ---------------- elementwise helpers ----------------
__global__ void k_scale_rows(float* __restrict__ X, const float* __restrict__ r, int n) {
    int i = blockIdx.x * blockDim.x + threadIdx.x;
    if (i < n) X[i] *= r[i >> 7];
}
__global__ void k_copy(const float* __restrict__ a, float* __restrict__ b, int n) {
    int i = blockIdx.x * blockDim.x + threadIdx.x;
    if (i < n) b[i] = a[i];
}
__global__ void k_add(float* __restrict__ a, const float* __restrict__ b, int n) {
    int i = blockIdx.x * blockDim.x + threadIdx.x;
    if (i < n) a[i] += b[i];
}

// ---------------- LayerNorm rows of X[M,128] ----------------
__global__ void k_layernorm(float* __restrict__ X, const float* __restrict__ g,
                            const float* __restrict__ b, int M) {
    int w = (blockIdx.x * blockDim.x + threadIdx.x) >> 5;
    int lane = threadIdx.x & 31;
    if (w >= M) return;
    float4 v = ((const float4*)X)[w * 32 + lane];
    float s = v.x + v.y + v.z + v.w;
    float sq = v.x * v.x + v.y * v.y + v.z * v.z + v.w * v.w;
#pragma unroll
    for (int o = 16; o; o >>= 1) {
        s += __shfl_xor_sync(0xffffffffu, s, o);
        sq += __shfl_xor_sync(0xffffffffu, sq, o);
    }
    float mean = s * (1.f / 128.f);
    float var = sq * (1.f / 128.f) - mean * mean;
    float rstd = rsqrtf(var + 1e-5f);
    float4 gg = ((const float4*)g)[lane];
    float4 bb = ((const float4*)b)[lane];
    v.x = (v.x - mean) * rstd * gg.x + bb.x;
    v.y = (v.y - mean) * rstd * gg.y + bb.y;
    v.z = (v.z - mean) * rstd * gg.z + bb.z;
    v.w = (v.w - mean) * rstd * gg.w + bb.w;
    ((float4*)X)[w * 32 + lane] = v;
}

// ---------------- host orchestration ----------------
static float* faddr(const void* sym) {
    void* p = nullptr;
    cudaGetSymbolAddress(&p, sym);
    return (float*)p;
}
static int* iaddr(const void* sym) {
    void* p = nullptr;
    cudaGetSymbolAddress(&p, sym);
    return (int*)p;
}

extern "C" void kernel_launch(void* const* d_in, const int* in_sizes, int n_in,
                              void* d_out, int out_size) {
    const float* x  = (const float*)d_in[0];
    const int*   ei = (const int*)d_in[1];
    const float* W1 = (const float*)d_in[3];  const float* b1 = (const float*)d_in[4];
    const float* W2 = (const float*)d_in[5];  const float* b2 = (const float*)d_in[6];
    const float* S  = (const float*)d_in[7];
    const float* Wq = (const float*)d_in[8];  const float* bq = (const float*)d_in[9];
    const float* Wk = (const float*)d_in[10]; const float* bk = (const float*)d_in[11];
    const float* Wv = (const float*)d_in[12]; const float* bv = (const float*)d_in[13];
    const float* Wo = (const float*)d_in[14]; const float* bo = (const float*)d_in[15];
    const float* g0 = (const float*)d_in[16]; const float* be0 = (const float*)d_in[17];
    const float* g1 = (const float*)d_in[18]; const float* be1 = (const float*)d_in[19];
    const float* Wl = (const float*)d_in[20]; const float* bl = (const float*)d_in[21];
    const float* W3 = (const float*)d_in[22]; const float* b3 = (const float*)d_in[23];
    const float* W4 = (const float*)d_in[24]; const float* b4 = (const float*)d_in[25];
    const float* W5 = (const float*)d_in[26]; const float* b5 = (const float*)d_in[27];

    const int* src = ei;
    const int* dst = ei + NE;

    float* score = faddr(g_score);
    float* t     = faddr(g_t);
    float* h1    = faddr(g_h1);
    float* h2    = faddr(g_h2);
    float* Kd    = faddr(g_Kd);
    float* Vd    = faddr(g_Vd);
    float* Q     = faddr(g_Q);
    float* outb  = faddr(g_out);
    float* t2    = faddr(g_t2);
    float* xl    = faddr(g_xl);
    float* dinv  = faddr(g_dinv);
    float* rcpl  = faddr(g_rcpl);
    float* lsum  = faddr(g_l);
    float* mb    = faddr(g_mbound);
    int* cnt   = iaddr(g_cnt);
    int* rptr  = iaddr(g_rptr);
    int* colv  = iaddr(g_col);
    int* bsums = iaddr(g_bsums);

    cudaFuncSetAttribute((const void*)k_gemm<0,0,0,3>, cudaFuncAttributeMaxDynamicSharedMemorySize, GSMEM);
    cudaFuncSetAttribute((const void*)k_gemm<0,1,3,1>, cudaFuncAttributeMaxDynamicSharedMemorySize, GSMEM);
    cudaFuncSetAttribute((const void*)k_gemm<0,0,1,1>, cudaFuncAttributeMaxDynamicSharedMemorySize, GSMEM);
    cudaFuncSetAttribute((const void*)k_gemm<1,0,2,2>, cudaFuncAttributeMaxDynamicSharedMemorySize, GSMEM);

    const int mbN = (NN + 127) / 128;   // 157
    const int mbK = (KK + 127) / 128;   // 16
    float* dOut = (float*)d_out;
    const float rs128 = 0.0883883476483184f;  // 1/sqrt(128)

    // --- zero pads + column-sum accumulators (l, qmax) ---
    k_zero_float<<<((KK32 - KK) * NN + 255) / 256, 256>>>(score + (size_t)KK * NN, (KK32 - KK) * NN);
    k_zero_float<<<((KK32 - KK) * DD + 255) / 256, 256>>>(xl + (size_t)KK * DD, (KK32 - KK) * DD);
    k_zero_float<<<(NN + 1 + 255) / 256, 256>>>(lsum, NN + 1);

    // --- CSR + degree ---
    k_zero_int<<<(NN + 255) / 256, 256>>>(cnt, NN);
    k_count_dst<<<(NE + 255) / 256, 256>>>(dst, cnt);
    k_scan1<<<20, 1024>>>(cnt, rptr, bsums);
    k_scan2<<<1, 32>>>(bsums, 20);
    k_scan3<<<20, 1024>>>(rptr, bsums);
    k_dinv_reset<<<(NN + 255) / 256, 256>>>(cnt, dinv);
    k_fill_csr<<<(NE + 255) / 256, 256>>>(src, dst, rptr, cnt, colv);

    // --- GCN1, GCN2 ---
    k_gemm<0,0,0,3><<<dim3(mbN,1,1), 256, GSMEM>>>(x,  W1, t, NN, 128, 128, 128, 128, 128, 128, 1.f, nullptr, nullptr, 0);
    k_aggregate<<<(NN * 32 + 255) / 256, 256>>>(t, rptr, colv, dinv, b1, h1, 1);
    k_gemm<0,0,0,3><<<dim3(mbN,1,1), 256, GSMEM>>>(h1, W2, t, NN, 128, 128, 128, 128, 128, 128, 1.f, nullptr, nullptr, 0);
    k_aggregate<<<(NN * 32 + 255) / 256, 256>>>(t, rptr, colv, dinv, b2, h2, 1);

    // --- Q, Kd, Vd ---
    k_gemm<0,0,0,3><<<dim3(mbK,1,1), 256, GSMEM>>>(S,  Wq, Q, KK, 128, 128, 128, 128, 128, 128, 1.f, bq, nullptr, 0);
    k_gemm<0,0,0,3><<<dim3(mbN,1,1), 256, GSMEM>>>(h2, Wk, t, NN, 128, 128, 128, 128, 128, 128, 1.f, nullptr, nullptr, 0);
    k_aggregate<<<(NN * 32 + 255) / 256, 256>>>(t, rptr, colv, dinv, bk, Kd, 0);
    k_gemm<0,0,0,3><<<dim3(mbN,1,1), 256, GSMEM>>>(h2, Wv, t, NN, 128, 128, 128, 128, 128, 128, 1.f, nullptr, nullptr, 0);
    k_aggregate<<<(NN * 32 + 255) / 256, 256>>>(t, rptr, colv, dinv, bv, Vd, 0);

    // --- softmax bound: qmax (into lsum[NN]) then m[n] ---
    k_qmax<<<(KK * 32 + 255) / 256, 256>>>(Q, lsum + NN);
    k_mbound<<<(NN * 32 + 255) / 256, 256>>>(Kd, lsum + NN, mb);

    // --- fused score+exp+colsum: score = exp(Q@Kd^T/sqrt(D) - m[n]); l[n] += colsum ---
    k_gemm<0,1,3,1><<<dim3(mbK, mbN, 1), 256, GSMEM>>>(Q, Kd, score, KK, NN, 128, 128, 128, 128, NN, rs128, mb, lsum, 0);
    k_recip<<<(NN + 255) / 256, 256>>>(lsum, rcpl);
    k_scale_rows<<<(NN * DD + 255) / 256, 256>>>(Vd, rcpl, NN * DD);   // fold 1/l into V
    k_copy<<<(KK * DD + 255) / 256, 256>>>(Q, outb, KK * DD);          // Out = Q
    // Out += Aexp @ Vd_scaled (1xTF32: LayerNorm right after washes scale bias)
    k_gemm<0,0,1,1><<<dim3(mbK, 1, 16), 256, GSMEM>>>(score, Vd, outb, KK, 128, NN, 1280, NN, 128, 128, 1.f, nullptr, nullptr, 0);

    // --- epilogue on [K,128] ---
    k_layernorm<<<(KK * 32 + 255) / 256, 256>>>(outb, g0, be0, KK);
    k_gemm<0,0,0,3><<<dim3(mbK,1,1), 256, GSMEM>>>(outb, Wo, t2, KK, 128, 128, 128, 128, 128, 128, 1.f, bo, nullptr, 1);
    k_add<<<(KK * DD + 255) / 256, 256>>>(outb, t2, KK * DD);
    k_layernorm<<<(KK * 32 + 255) / 256, 256>>>(outb, g1, be1, KK);
    k_gemm<0,0,0,3><<<dim3(mbK,1,1), 256, GSMEM>>>(outb, Wl, xl, KK, 128, 128, 128, 128, 128, 128, 1.f, bl, nullptr, 0);

    // --- x_out = rcpl[n] * (Aexp^T @ xl): PREC=2 (split A exactly), alpha corrects
    //     the mean tf32-truncation shrink of B (xl): +2^-11/ln2*0.5 ~ 3.52e-4 ---
    k_gemm<1,0,2,2><<<dim3(mbN,1,1), 256, GSMEM>>>(score, xl, h1, NN, 128, KK32, KK32, NN, 128, 128, 1.000352f, nullptr, rcpl, 0);

    // --- GCN3, GCN4, GCN5 ---
    k_gemm<0,0,0,3><<<dim3(mbN,1,1), 256, GSMEM>>>(h1, W3, t, NN, 128, 128, 128, 128, 128, 128, 1.f, nullptr, nullptr, 0);
    k_aggregate<<<(NN * 32 + 255) / 256, 256>>>(t, rptr, colv, dinv, b3, h2, 1);
    k_gemm<0,0,0,3><<<dim3(mbN,1,1), 256, GSMEM>>>(h2, W4, t, NN, 128, 128, 128, 128, 128, 128, 1.f, nullptr, nullptr, 0);
    k_aggregate<<<(NN * 32 + 255) / 256, 256>>>(t, rptr, colv, dinv, b4, h1, 1);
    k_gemm<0,0,0,3><<<dim3(mbN,1,1), 256, GSMEM>>>(h1, W5, t, NN, 128, 128, 128, 128, 128, 128, 1.f, nullptr, nullptr, 0);
    k_aggregate<<<(NN * 32 + 255) / 256, 256>>>(t, rptr, colv, dinv, b5, dOut, 0);
}

// round 15
// speedup vs baseline: 3.0455x; 1.1489x over previous
#include <cuda_runtime.h>
#include <math.h>

#define NN 20000
#define NE 320000
#define DD 128
#define KK 2000
#define KK32 2016   // KK padded to multiple of 32 for the ATX gemm

// ---------------- scratch (static device globals; no allocation) ----------------
__device__ float g_score[(size_t)KK32 * NN]; // exp(score - m); rows >= KK are zero
__device__ float g_t[NN * DD];
__device__ float g_h1[NN * DD];
__device__ float g_h2[NN * DD];
__device__ float g_Kd[NN * DD];
__device__ float g_Vd[NN * DD];
__device__ float g_Q[KK * DD];
__device__ float g_out[KK * DD];
__device__ float g_t2[KK * DD];
__device__ float g_xl[KK32 * DD];            // rows >= KK are zero
__device__ float g_dinv[NN];
__device__ float g_rcpl[NN];
__device__ float g_l[NN + 1];                // column sums; [NN] = qmax
__device__ float g_mbound[NN];               // per-column softmax shift (upper bound)
__device__ int   g_cnt[NN];
__device__ int   g_rptr[NN + 1];
__device__ int   g_col[NE];
__device__ int   g_bsums[64];

// tf32 mean-truncation-shrink corrections (validated R10: alpha=1.000352 for one
// raw-tf32 operand; two raw operands compound to ~1.000704)
#define ALPHA1 1.000352f
#define ALPHA2 1.000704f

// ---------------- small utility kernels ----------------
__global__ void k_zero_int(int* p, int n) {
    int i = blockIdx.x * blockDim.x + threadIdx.x;
    if (i < n) p[i] = 0;
}
__global__ void k_zero_float(float* p, int n) {
    int i = blockIdx.x * blockDim.x + threadIdx.x;
    if (i < n) p[i] = 0.f;
}

__global__ void k_count_dst(const int* __restrict__ dst, int* __restrict__ cnt) {
    int e = blockIdx.x * blockDim.x + threadIdx.x;
    if (e < NE) atomicAdd(&cnt[dst[e]], 1);
}

__global__ void k_scan1(const int* __restrict__ cnt, int* __restrict__ rptr,
                        int* __restrict__ bsums) {
    __shared__ int sh[1024];
    int i = blockIdx.x * 1024 + threadIdx.x;
    int v = (i < NN) ? cnt[i] : 0;
    sh[threadIdx.x] = v;
    __syncthreads();
    for (int off = 1; off < 1024; off <<= 1) {
        int t = 0;
        if ((int)threadIdx.x >= off) t = sh[threadIdx.x - off];
        __syncthreads();
        sh[threadIdx.x] += t;
        __syncthreads();
    }
    if (i < NN) rptr[i] = sh[threadIdx.x] - v;   // exclusive
    if (threadIdx.x == 1023) bsums[blockIdx.x] = sh[1023];
}

__global__ void k_scan2(int* bsums, int nb) {
    if (threadIdx.x == 0 && blockIdx.x == 0) {
        int acc = 0;
        for (int b = 0; b < nb; b++) { int t = bsums[b]; bsums[b] = acc; acc += t; }
    }
}

__global__ void k_scan3(int* __restrict__ rptr, const int* __restrict__ bsums) {
    int i = blockIdx.x * 1024 + threadIdx.x;
    if (i < NN) rptr[i] += bsums[blockIdx.x];
    if (i == 0) rptr[NN] = NE;
}

__global__ void k_dinv_reset(int* __restrict__ cnt, float* __restrict__ dinv) {
    int n = blockIdx.x * blockDim.x + threadIdx.x;
    if (n < NN) {
        dinv[n] = rsqrtf((float)(cnt[n] + 1));  // +1 self loop
        cnt[n] = 0;                             // becomes cursor
    }
}

__global__ void k_fill_csr(const int* __restrict__ src, const int* __restrict__ dst,
                           const int* __restrict__ rptr, int* __restrict__ cnt,
                           int* __restrict__ colv) {
    int e = blockIdx.x * blockDim.x + threadIdx.x;
    if (e < NE) {
        int d = dst[e];
        int p = rptr[d] + atomicAdd(&cnt[d], 1);
        colv[p] = src[e];
    }
}

// qmax = max_k ||Q[k,:]||  (stored as g_l[NN]; positive-float int atomicMax)
__global__ void k_qmax(const float* __restrict__ Q, float* __restrict__ qmax) {
    int w = (blockIdx.x * blockDim.x + threadIdx.x) >> 5;
    int lane = threadIdx.x & 31;
    if (w >= KK) return;
    float4 v = ((const float4*)Q)[w * 32 + lane];
    float s = v.x * v.x + v.y * v.y + v.z * v.z + v.w * v.w;
#pragma unroll
    for (int o = 16; o; o >>= 1) s += __shfl_xor_sync(0xffffffffu, s, o);
    if (lane == 0) atomicMax((int*)qmax, __float_as_int(sqrtf(s)));
}

// m[n] = qmax * ||Kd[n,:]|| / sqrt(128)
__global__ void k_mbound(const float* __restrict__ Kd, const float* __restrict__ qmax,
                         float* __restrict__ mb) {
    int w = (blockIdx.x * blockDim.x + threadIdx.x) >> 5;
    int lane = threadIdx.x & 31;
    if (w >= NN) return;
    float4 v = ((const float4*)Kd)[w * 32 + lane];
    float s = v.x * v.x + v.y * v.y + v.z * v.z + v.w * v.w;
#pragma unroll
    for (int o = 16; o; o >>= 1) s += __shfl_xor_sync(0xffffffffu, s, o);
    if (lane == 0) mb[w] = qmax[0] * sqrtf(s) * 0.0883883476483184f;
}

__global__ void k_recip(const float* __restrict__ l, float* __restrict__ r) {
    int n = blockIdx.x * blockDim.x + threadIdx.x;
    if (n < NN) r[n] = 1.f / l[n];
}

// ================= tf32 tensor-core GEMM =================
// PREC=3: 3xTF32 fp32-accurate; PREC=2: split-A only (pair with ALPHA1);
// PREC=1: raw tf32 (pair with ALPHA2; only where softmax/LN absorbs residuals).
// EPI 0: C=acc*alpha+bias (opt relu); 1: atomicAdd; 2: C=rowscale[m]*acc*alpha;
// EPI 3: C=exp(acc*alpha - bias[n]) and atomicAdd per-column sums into rowscale[] (=l).
// NBLK: min blocks/SM for launch_bounds (2 only safe for PREC=1 register budget).
// (kE - kB) must be a multiple of 32 for every launch.
#define GBM 128
#define GBN 128
#define GBK 32
#define LDMK 36
#define LDKM 132
#define ASZ 4608
#define STG 9216
#define GSMEM (2 * STG * 4)

__device__ __forceinline__ void cp16(unsigned dst, const float* src, bool v) {
    int sz = v ? 16 : 0;
    asm volatile("cp.async.cg.shared.global [%0], [%1], 16, %2;\n"
                 :: "r"(dst), "l"(src), "r"(sz));
}
#define CP_COMMIT asm volatile("cp.async.commit_group;\n")
#define CP_WAIT0  asm volatile("cp.async.wait_group 0;\n" ::: "memory")

__device__ __forceinline__ void mma8(float* d, unsigned a0, unsigned a1, unsigned a2,
                                     unsigned a3, unsigned b0, unsigned b1) {
    asm volatile("mma.sync.aligned.m16n8k8.row.col.f32.tf32.tf32.f32 "
        "{%0,%1,%2,%3}, {%4,%5,%6,%7}, {%8,%9}, {%0,%1,%2,%3};\n"
        : "+f"(d[0]), "+f"(d[1]), "+f"(d[2]), "+f"(d[3])
        : "r"(a0), "r"(a1), "r"(a2), "r"(a3), "r"(b0), "r"(b1));
}
__device__ __forceinline__ unsigned lo_part(unsigned x) {
    return __float_as_uint(__uint_as_float(x) - __uint_as_float(x & 0xFFFFE000u));
}

template<int TRANSA, int TRANSB, int EPI, int PREC, int NBLK>
__global__ __launch_bounds__(256, NBLK)
void k_gemm(const float* __restrict__ A, const float* __restrict__ B,
            float* __restrict__ C, int M, int N, int Ktot, int kChunk,
            int ldA, int ldB, int ldC, float alpha,
            const float* __restrict__ bias, float* __restrict__ rowscale,
            int relu)
{
    extern __shared__ float smf[];
    const int tid = threadIdx.x;
    const int lane = tid & 31;
    const int warp = tid >> 5;
    const int wm = (warp >> 2) * 64;
    const int wn = (warp & 3) * 32;
    const int g = lane >> 2, tig = lane & 3;
    const int m0 = blockIdx.x * GBM;
    const int n0 = blockIdx.y * GBN;
    const int kB = blockIdx.z * kChunk;
    const int kE = (Ktot < kB + kChunk) ? Ktot : (kB + kChunk);
    const int T = (kE - kB) >> 5;

    const unsigned sbase = (unsigned)__cvta_generic_to_shared(smf);

    int arow, acol, brow, bcol;
    if (!TRANSA) { arow = tid >> 3; acol = (tid & 7) * 4; }
    else         { arow = tid >> 5; acol = (tid & 31) * 4; }
    if (!TRANSB) { brow = tid >> 5; bcol = (tid & 31) * 4; }
    else         { brow = tid >> 3; bcol = (tid & 7) * 4; }

    const int a_lr = ((lane >> 3) & 1) * 8 + (lane & 7);
    const int a_lk = (lane >> 4) * 4;
    const int b_lr = (lane >> 4) * 8 + (lane & 7);
    const int b_lk = ((lane >> 3) & 1) * 4;

    float acc[4][4][4];
#pragma unroll
    for (int i = 0; i < 4; i++)
#pragma unroll
        for (int j = 0; j < 4; j++)
#pragma unroll
            for (int q = 0; q < 4; q++) acc[i][j][q] = 0.f;

    auto prefetch = [&](int kt, int s) {
        unsigned abase = sbase + (unsigned)(s * STG) * 4u;
        unsigned bbase = abase + ASZ * 4u;
        int kof = kB + kt * 32;
#pragma unroll
        for (int p = 0; p < 4; p++) {
            if (!TRANSA) {
                int m = m0 + arow + 32 * p;
                bool v = m < M;
                const float* src = A + (size_t)(v ? m : 0) * ldA + kof + acol;
                cp16(abase + (unsigned)((arow + 32 * p) * LDMK + acol) * 4u, src, v);
            } else {
                int m = m0 + acol;
                bool v = m < M;
                const float* src = A + (size_t)(kof + arow + 8 * p) * ldA + (v ? m : 0);
                cp16(abase + (unsigned)((arow + 8 * p) * LDKM + acol) * 4u, src, v);
            }
        }
#pragma unroll
        for (int p = 0; p < 4; p++) {
            if (!TRANSB) {
                int n = n0 + bcol;
                bool v = n < N;
                const float* src = B + (size_t)(kof + brow + 8 * p) * ldB + (v ? n : 0);
                cp16(bbase + (unsigned)((brow + 8 * p) * LDKM + bcol) * 4u, src, v);
            } else {
                int n = n0 + brow + 32 * p;
                bool v = n < N;
                const float* src = B + (size_t)(v ? n : 0) * ldB + kof + bcol;
                cp16(bbase + (unsigned)((brow + 32 * p) * LDMK + bcol) * 4u, src, v);
            }
        }
    };

    prefetch(0, 0);
    CP_COMMIT;
    int s = 0;
    for (int kt = 0; kt < T; kt++) {
        CP_WAIT0;
        __syncthreads();
        if (kt + 1 < T) { prefetch(kt + 1, s ^ 1); CP_COMMIT; }
        const float* AsF = smf + s * STG;
        const float* BsF = AsF + ASZ;
        unsigned abase = sbase + (unsigned)(s * STG) * 4u;
        unsigned bbase = abase + ASZ * 4u;
#pragma unroll
        for (int ks = 0; ks < 4; ks++) {
            const int k0 = ks * 8;
            unsigned ah[4][4], al[4][4];
            if (!TRANSA) {
#pragma unroll
                for (int mf = 0; mf < 4; mf++) {
                    unsigned addr = abase + (unsigned)((wm + mf * 16 + a_lr) * LDMK + k0 + a_lk) * 4u;
                    asm volatile("ldmatrix.sync.aligned.m8n8.x4.shared.b16 {%0,%1,%2,%3}, [%4];\n"
                        : "=r"(ah[mf][0]), "=r"(ah[mf][1]), "=r"(ah[mf][2]), "=r"(ah[mf][3]) : "r"(addr));
                }
            } else {
#pragma unroll
                for (int mf = 0; mf < 4; mf++) {
                    int mb = wm + mf * 16 + g;
                    ah[mf][0] = __float_as_uint(AsF[(k0 + tig) * LDKM + mb]);
                    ah[mf][1] = __float_as_uint(AsF[(k0 + tig) * LDKM + mb + 8]);
                    ah[mf][2] = __float_as_uint(AsF[(k0 + tig + 4) * LDKM + mb]);
                    ah[mf][3] = __float_as_uint(AsF[(k0 + tig + 4) * LDKM + mb + 8]);
                }
            }
            if (PREC >= 2) {
#pragma unroll
                for (int mf = 0; mf < 4; mf++)
#pragma unroll
                    for (int q = 0; q < 4; q++) {
                        al[mf][q] = lo_part(ah[mf][q]);
                        ah[mf][q] &= 0xFFFFE000u;
                    }
            }
            unsigned braw[4][2];
            if (TRANSB) {
#pragma unroll
                for (int h = 0; h < 2; h++) {
                    unsigned addr = bbase + (unsigned)((wn + h * 16 + b_lr) * LDMK + k0 + b_lk) * 4u;
                    asm volatile("ldmatrix.sync.aligned.m8n8.x4.shared.b16 {%0,%1,%2,%3}, [%4];\n"
                        : "=r"(braw[2 * h][0]), "=r"(braw[2 * h][1]),
                          "=r"(braw[2 * h + 1][0]), "=r"(braw[2 * h + 1][1])
                        : "r"(addr));
                }
            } else {
#pragma unroll
                for (int nf = 0; nf < 4; nf++) {
                    int nb = wn + nf * 8 + g;
                    braw[nf][0] = __float_as_uint(BsF[(k0 + tig) * LDKM + nb]);
                    braw[nf][1] = __float_as_uint(BsF[(k0 + tig + 4) * LDKM + nb]);
                }
            }
#pragma unroll
            for (int nf = 0; nf < 4; nf++) {
                if (PREC == 3) {
                    unsigned bh0 = braw[nf][0] & 0xFFFFE000u;
                    unsigned bh1 = braw[nf][1] & 0xFFFFE000u;
                    unsigned bl0 = lo_part(braw[nf][0]);
                    unsigned bl1 = lo_part(braw[nf][1]);
#pragma unroll
                    for (int mf = 0; mf < 4; mf++) {
                        mma8(acc[mf][nf], ah[mf][0], ah[mf][1], ah[mf][2], ah[mf][3], bh0, bh1);
                        mma8(acc[mf][nf], ah[mf][0], ah[mf][1], ah[mf][2], ah[mf][3], bl0, bl1);
                        mma8(acc[mf][nf], al[mf][0], al[mf][1], al[mf][2], al[mf][3], bh0, bh1);
                    }
                } else if (PREC == 2) {
#pragma unroll
                    for (int mf = 0; mf < 4; mf++) {
                        mma8(acc[mf][nf], ah[mf][0], ah[mf][1], ah[mf][2], ah[mf][3],
                             braw[nf][0], braw[nf][1]);
                        mma8(acc[mf][nf], al[mf][0], al[mf][1], al[mf][2], al[mf][3],
                             braw[nf][0], braw[nf][1]);
                    }
                } else {
#pragma unroll
                    for (int mf = 0; mf < 4; mf++)
                        mma8(acc[mf][nf], ah[mf][0], ah[mf][1], ah[mf][2], ah[mf][3],
                             braw[nf][0], braw[nf][1]);
                }
            }
        }
        s ^= 1;
    }

    // epilogue
    float cs[4][2];
    if (EPI == 3) {
#pragma unroll
        for (int nf = 0; nf < 4; nf++) { cs[nf][0] = 0.f; cs[nf][1] = 0.f; }
    }
#pragma unroll
    for (int mf = 0; mf < 4; mf++) {
        int r0 = m0 + wm + mf * 16 + g;
        int r1 = r0 + 8;
#pragma unroll
        for (int nf = 0; nf < 4; nf++) {
            int c = n0 + wn + nf * 8 + tig * 2;
            float v0 = acc[mf][nf][0] * alpha;
            float v1 = acc[mf][nf][1] * alpha;
            float v2 = acc[mf][nf][2] * alpha;
            float v3 = acc[mf][nf][3] * alpha;
            if (EPI == 0) {
                float bb0 = bias ? bias[c] : 0.f;
                float bb1 = bias ? bias[c + 1] : 0.f;
                v0 += bb0; v1 += bb1; v2 += bb0; v3 += bb1;
                if (relu) {
                    v0 = fmaxf(v0, 0.f); v1 = fmaxf(v1, 0.f);
                    v2 = fmaxf(v2, 0.f); v3 = fmaxf(v3, 0.f);
                }
                if (c < N) {
                    if (r0 < M) { C[(size_t)r0 * ldC + c] = v0; C[(size_t)r0 * ldC + c + 1] = v1; }
                    if (r1 < M) { C[(size_t)r1 * ldC + c] = v2; C[(size_t)r1 * ldC + c + 1] = v3; }
                }
            } else if (EPI == 1) {
                if (c < N) {
                    if (r0 < M) { atomicAdd(&C[(size_t)r0 * ldC + c], v0); atomicAdd(&C[(size_t)r0 * ldC + c + 1], v1); }
                    if (r1 < M) { atomicAdd(&C[(size_t)r1 * ldC + c], v2); atomicAdd(&C[(size_t)r1 * ldC + c + 1], v3); }
                }
            } else if (EPI == 2) {
                if (c < N) {
                    if (r0 < M) { float sc = rowscale[r0]; C[(size_t)r0 * ldC + c] = sc * v0; C[(size_t)r0 * ldC + c + 1] = sc * v1; }
                    if (r1 < M) { float sc = rowscale[r1]; C[(size_t)r1 * ldC + c] = sc * v2; C[(size_t)r1 * ldC + c + 1] = sc * v3; }
                }
            } else {
                // EPI 3: exp(score - mbound[n]) + column partial sums
                bool c0ok = (c < N), c1ok = (c + 1 < N);
                float mc0 = c0ok ? bias[c] : 0.f;
                float mc1 = c1ok ? bias[c + 1] : 0.f;
                if (r0 < M) {
                    if (c0ok) { float e = __expf(v0 - mc0); C[(size_t)r0 * ldC + c] = e; cs[nf][0] += e; }
                    if (c1ok) { float e = __expf(v1 - mc1); C[(size_t)r0 * ldC + c + 1] = e; cs[nf][1] += e; }
                }
                if (r1 < M) {
                    if (c0ok) { float e = __expf(v2 - mc0); C[(size_t)r1 * ldC + c] = e; cs[nf][0] += e; }
                    if (c1ok) { float e = __expf(v3 - mc1); C[(size_t)r1 * ldC + c + 1] = e; cs[nf][1] += e; }
                }
            }
        }
    }
    if (EPI == 3) {
#pragma unroll
        for (int nf = 0; nf < 4; nf++) {
#pragma unroll
            for (int j = 0; j < 2; j++) {
                float v = cs[nf][j];
                v += __shfl_xor_sync(0xffffffffu, v, 4);
                v += __shfl_xor_sync(0xffffffffu, v, 8);
                v += __shfl_xor_sync(0xffffffffu, v, 16);
                int c = n0 + wn + nf * 8 + tig * 2 + j;
                if (lane < 4 && c < N) atomicAdd(&rowscale[c], v);
            }
        }
    }
}

// ---------------- GCN aggregation ----------------
__global__ void k_aggregate(const float* __restrict__ H, const int* __restrict__ rptr,
                            const int* __restrict__ colv, const float* __restrict__ dinv,
                            const float* __restrict__ bias, float* __restrict__ Out,
                            int relu) {
    int w = (blockIdx.x * blockDim.x + threadIdx.x) >> 5;
    int lane = threadIdx.x & 31;
    if (w >= NN) return;
    const float4* H4 = (const float4*)H;
    float4 acc = make_float4(0.f, 0.f, 0.f, 0.f);
    int s = rptr[w], e = rptr[w + 1];
    for (int j = s; j < e; j++) {
        int src = colv[j];
        float wt = dinv[src];
        float4 h = H4[src * 32 + lane];
        acc.x += wt * h.x; acc.y += wt * h.y; acc.z += wt * h.z; acc.w += wt * h.w;
    }
    float dn = dinv[w];
    float4 hs = H4[w * 32 + lane];
    float4 bb = ((const float4*)bias)[lane];
    acc.x = dn * (acc.x + dn * hs.x) + bb.x;
    acc.y = dn * (acc.y + dn * hs.y) + bb.y;
    acc.z = dn * (acc.z + dn * hs.z) + bb.z;
    acc.w = dn * (acc.w + dn * hs.w) + bb.w;
    if (relu) {
        acc.x = fmaxf(acc.x, 0.f); acc.y = fmaxf(acc.y, 0.f);
        acc.z = fmaxf(acc.z, 0.f); acc.w = fmaxf(acc.w, 0.f);
    }
    ((float4*)Out)[w * 32 + lane] = acc;
}

// ---------------- elementwise helpers ----------------
__global__ void k_scale_rows(float* __restrict__ X, const float* __restrict__ r, int n) {
    int i = blockIdx.x * blockDim.x + threadIdx.x;
    if (i < n) X[i] *= r[i >> 7];
}
__global__ void k_copy(const float* __restrict__ a, float* __restrict__ b, int n) {
    int i = blockIdx.x * blockDim.x + threadIdx.x;
    if (i < n) b[i] = a[i];
}
__global__ void k_add(float* __restrict__ a, const float* __restrict__ b, int n) {
    int i = blockIdx.x * blockDim.x + threadIdx.x;
    if (i < n) a[i] += b[i];
}

// ---------------- LayerNorm rows of X[M,128] ----------------
__global__ void k_layernorm(float* __restrict__ X, const float* __restrict__ g,
                            const float* __restrict__ b, int M) {
    int w = (blockIdx.x * blockDim.x + threadIdx.x) >> 5;
    int lane = threadIdx.x & 31;
    if (w >= M) return;
    float4 v = ((const float4*)X)[w * 32 + lane];
    float s = v.x + v.y + v.z + v.w;
    float sq = v.x * v.x + v.y * v.y + v.z * v.z + v.w * v.w;
#pragma unroll
    for (int o = 16; o; o >>= 1) {
        s += __shfl_xor_sync(0xffffffffu, s, o);
        sq += __shfl_xor_sync(0xffffffffu, sq, o);
    }
    float mean = s * (1.f / 128.f);
    float var = sq * (1.f / 128.f) - mean * mean;
    float rstd = rsqrtf(var + 1e-5f);
    float4 gg = ((const float4*)g)[lane];
    float4 bb = ((const float4*)b)[lane];
    v.x = (v.x - mean) * rstd * gg.x + bb.x;
    v.y = (v.y - mean) * rstd * gg.y + bb.y;
    v.z = (v.z - mean) * rstd * gg.z + bb.z;
    v.w = (v.w - mean) * rstd * gg.w + bb.w;
    ((float4*)X)[w * 32 + lane] = v;
}

// ---------------- host orchestration ----------------
static float* faddr(const void* sym) {
    void* p = nullptr;
    cudaGetSymbolAddress(&p, sym);
    return (float*)p;
}
static int* iaddr(const void* sym) {
    void* p = nullptr;
    cudaGetSymbolAddress(&p, sym);
    return (int*)p;
}

extern "C" void kernel_launch(void* const* d_in, const int* in_sizes, int n_in,
                              void* d_out, int out_size) {
    const float* x  = (const float*)d_in[0];
    const int*   ei = (const int*)d_in[1];
    const float* W1 = (const float*)d_in[3];  const float* b1 = (const float*)d_in[4];
    const float* W2 = (const float*)d_in[5];  const float* b2 = (const float*)d_in[6];
    const float* S  = (const float*)d_in[7];
    const float* Wq = (const float*)d_in[8];  const float* bq = (const float*)d_in[9];
    const float* Wk = (const float*)d_in[10]; const float* bk = (const float*)d_in[11];
    const float* Wv = (const float*)d_in[12]; const float* bv = (const float*)d_in[13];
    const float* Wo = (const float*)d_in[14]; const float* bo = (const float*)d_in[15];
    const float* g0 = (const float*)d_in[16]; const float* be0 = (const float*)d_in[17];
    const float* g1 = (const float*)d_in[18]; const float* be1 = (const float*)d_in[19];
    const float* Wl = (const float*)d_in[20]; const float* bl = (const float*)d_in[21];
    const float* W3 = (const float*)d_in[22]; const float* b3 = (const float*)d_in[23];
    const float* W4 = (const float*)d_in[24]; const float* b4 = (const float*)d_in[25];
    const float* W5 = (const float*)d_in[26]; const float* b5 = (const float*)d_in[27];

    const int* src = ei;
    const int* dst = ei + NE;

    float* score = faddr(g_score);
    float* t     = faddr(g_t);
    float* h1    = faddr(g_h1);
    float* h2    = faddr(g_h2);
    float* Kd    = faddr(g_Kd);
    float* Vd    = faddr(g_Vd);
    float* Q     = faddr(g_Q);
    float* outb  = faddr(g_out);
    float* t2    = faddr(g_t2);
    float* xl    = faddr(g_xl);
    float* dinv  = faddr(g_dinv);
    float* rcpl  = faddr(g_rcpl);
    float* lsum  = faddr(g_l);
    float* mb    = faddr(g_mbound);
    int* cnt   = iaddr(g_cnt);
    int* rptr  = iaddr(g_rptr);
    int* colv  = iaddr(g_col);
    int* bsums = iaddr(g_bsums);

    cudaFuncSetAttribute((const void*)k_gemm<0,0,0,2,1>, cudaFuncAttributeMaxDynamicSharedMemorySize, GSMEM);
    cudaFuncSetAttribute((const void*)k_gemm<0,1,3,1,2>, cudaFuncAttributeMaxDynamicSharedMemorySize, GSMEM);
    cudaFuncSetAttribute((const void*)k_gemm<0,0,1,1,2>, cudaFuncAttributeMaxDynamicSharedMemorySize, GSMEM);
    cudaFuncSetAttribute((const void*)k_gemm<1,0,2,2,1>, cudaFuncAttributeMaxDynamicSharedMemorySize, GSMEM);

    const int mbN = (NN + 127) / 128;   // 157
    const int mbK = (KK + 127) / 128;   // 16
    float* dOut = (float*)d_out;
    const float rs128c = 0.0883883476483184f * ALPHA2;  // 1/sqrt(128) * 1x-shrink fix

    // --- zero pads + column-sum accumulators (l, qmax) ---
    k_zero_float<<<((KK32 - KK) * NN + 255) / 256, 256>>>(score + (size_t)KK * NN, (KK32 - KK) * NN);
    k_zero_float<<<((KK32 - KK) * DD + 255) / 256, 256>>>(xl + (size_t)KK * DD, (KK32 - KK) * DD);
    k_zero_float<<<(NN + 1 + 255) / 256, 256>>>(lsum, NN + 1);

    // --- CSR + degree ---
    k_zero_int<<<(NN + 255) / 256, 256>>>(cnt, NN);
    k_count_dst<<<(NE + 255) / 256, 256>>>(dst, cnt);
    k_scan1<<<20, 1024>>>(cnt, rptr, bsums);
    k_scan2<<<1, 32>>>(bsums, 20);
    k_scan3<<<20, 1024>>>(rptr, bsums);
    k_dinv_reset<<<(NN + 255) / 256, 256>>>(cnt, dinv);
    k_fill_csr<<<(NE + 255) / 256, 256>>>(src, dst, rptr, cnt, colv);

    // --- GCN1, GCN2 (PREC=2 + ALPHA1) ---
    k_gemm<0,0,0,2,1><<<dim3(mbN,1,1), 256, GSMEM>>>(x,  W1, t, NN, 128, 128, 128, 128, 128, 128, ALPHA1, nullptr, nullptr, 0);
    k_aggregate<<<(NN * 32 + 255) / 256, 256>>>(t, rptr, colv, dinv, b1, h1, 1);
    k_gemm<0,0,0,2,1><<<dim3(mbN,1,1), 256, GSMEM>>>(h1, W2, t, NN, 128, 128, 128, 128, 128, 128, ALPHA1, nullptr, nullptr, 0);
    k_aggregate<<<(NN * 32 + 255) / 256, 256>>>(t, rptr, colv, dinv, b2, h2, 1);

    // --- Q, Kd, Vd ---
    k_gemm<0,0,0,2,1><<<dim3(mbK,1,1), 256, GSMEM>>>(S,  Wq, Q, KK, 128, 128, 128, 128, 128, 128, ALPHA1, bq, nullptr, 0);
    k_gemm<0,0,0,2,1><<<dim3(mbN,1,1), 256, GSMEM>>>(h2, Wk, t, NN, 128, 128, 128, 128, 128, 128, ALPHA1, nullptr, nullptr, 0);
    k_aggregate<<<(NN * 32 + 255) / 256, 256>>>(t, rptr, colv, dinv, bk, Kd, 0);
    k_gemm<0,0,0,2,1><<<dim3(mbN,1,1), 256, GSMEM>>>(h2, Wv, t, NN, 128, 128, 128, 128, 128, 128, ALPHA1, nullptr, nullptr, 0);
    k_aggregate<<<(NN * 32 + 255) / 256, 256>>>(t, rptr, colv, dinv, bv, Vd, 0);

    // --- softmax bound: qmax (into lsum[NN]) then m[n] ---
    k_qmax<<<(KK * 32 + 255) / 256, 256>>>(Q, lsum + NN);
    k_mbound<<<(NN * 32 + 255) / 256, 256>>>(Kd, lsum + NN, mb);

    // --- fused score+exp+colsum (PREC=1, ALPHA2 folded into scale) ---
    k_gemm<0,1,3,1,2><<<dim3(mbK, mbN, 1), 256, GSMEM>>>(Q, Kd, score, KK, NN, 128, 128, 128, 128, NN, rs128c, mb, lsum, 0);
    k_recip<<<(NN + 255) / 256, 256>>>(lsum, rcpl);
    k_scale_rows<<<(NN * DD + 255) / 256, 256>>>(Vd, rcpl, NN * DD);   // fold 1/l into V
    k_copy<<<(KK * DD + 255) / 256, 256>>>(Q, outb, KK * DD);          // Out = Q
    // Out += Aexp @ Vd_scaled (PREC=1 + ALPHA2; residual washed by following LN)
    k_gemm<0,0,1,1,2><<<dim3(mbK, 1, 16), 256, GSMEM>>>(score, Vd, outb, KK, 128, NN, 1280, NN, 128, 128, ALPHA2, nullptr, nullptr, 0);

    // --- epilogue on [K,128] ---
    k_layernorm<<<(KK * 32 + 255) / 256, 256>>>(outb, g0, be0, KK);
    k_gemm<0,0,0,2,1><<<dim3(mbK,1,1), 256, GSMEM>>>(outb, Wo, t2, KK, 128, 128, 128, 128, 128, 128, ALPHA1, bo, nullptr, 1);
    k_add<<<(KK * DD + 255) / 256, 256>>>(outb, t2, KK * DD);
    k_layernorm<<<(KK * 32 + 255) / 256, 256>>>(outb, g1, be1, KK);
    k_gemm<0,0,0,2,1><<<dim3(mbK,1,1), 256, GSMEM>>>(outb, Wl, xl, KK, 128, 128, 128, 128, 128, 128, ALPHA1, bl, nullptr, 0);

    // --- x_out = rcpl[n] * (Aexp^T @ xl): PREC=2 + ALPHA1 ---
    k_gemm<1,0,2,2,1><<<dim3(mbN,1,1), 256, GSMEM>>>(score, xl, h1, NN, 128, KK32, KK32, NN, 128, 128, ALPHA1, nullptr, rcpl, 0);

    // --- GCN3, GCN4, GCN5 (PREC=2 + ALPHA1) ---
    k_gemm<0,0,0,2,1><<<dim3(mbN,1,1), 256, GSMEM>>>(h1, W3, t, NN, 128, 128, 128, 128, 128, 128, ALPHA1, nullptr, nullptr, 0);
    k_aggregate<<<(NN * 32 + 255) / 256, 256>>>(t, rptr, colv, dinv, b3, h2, 1);
    k_gemm<0,0,0,2,1><<<dim3(mbN,1,1), 256, GSMEM>>>(h2, W4, t, NN, 128, 128, 128, 128, 128, 128, ALPHA1, nullptr, nullptr, 0);
    k_aggregate<<<(NN * 32 + 255) / 256, 256>>>(t, rptr, colv, dinv, b4, h1, 1);
    k_gemm<0,0,0,2,1><<<dim3(mbN,1,1), 256, GSMEM>>>(h1, W5, t, NN, 128, 128, 128, 128, 128, 128, ALPHA1, nullptr, nullptr, 0);
    k_aggregate<<<(NN * 32 + 255) / 256, 256>>>(t, rptr, colv, dinv, b5, dOut, 0);
}

// round 16
// speedup vs baseline: 3.4066x; 1.1186x over previous
#include <cuda_runtime.h>
#include <cuda_bf16.h>
#include <math.h>

#define NN 20000
#define NE 320000
#define DD 128
#define KK 2000
#define KK32 2016   // KK padded to multiple of 32 for the ATX gemm

// ---------------- scratch (static device globals; no allocation) ----------------
__device__ __nv_bfloat16 g_score[(size_t)KK32 * NN]; // exp(score-m) bf16; rows >= KK zero
__device__ float g_t[NN * DD];
__device__ float g_h1[NN * DD];
__device__ float g_h2[NN * DD];
__device__ float g_Kd[NN * DD];
__device__ float g_Vd[NN * DD];
__device__ float g_Q[KK * DD];
__device__ float g_out[KK * DD];
__device__ float g_xl[KK32 * DD];            // rows >= KK are zero
__device__ float g_dinv[NN];
__device__ float g_l[NN + 1];                // column sums; [NN] = qmax
__device__ float g_mbound[NN];               // per-column softmax shift (upper bound)
__device__ int   g_cnt[NN];
__device__ int   g_rptr[NN + 1];
__device__ int   g_col[NE];

// tf32 mean-truncation-shrink corrections (validated R10/R11)
#define ALPHA1 1.000352f
#define ALPHA2 1.000704f

// ---------------- fused zero kernel: score pads (bf16), xl pads, lsum ----------------
__global__ void k_zero_all(unsigned* scorepad_u32, float* xlpad, float* lsum) {
    int i = blockIdx.x * blockDim.x + threadIdx.x;
    const int NPAD_U32 = (KK32 - KK) * NN / 2;   // bf16 pads as u32
    if (i < NPAD_U32) scorepad_u32[i] = 0u;
    if (i < (KK32 - KK) * DD) xlpad[i] = 0.f;
    if (i < NN + 1) lsum[i] = 0.f;
}

__global__ void k_zero_int(int* p, int n) {
    int i = blockIdx.x * blockDim.x + threadIdx.x;
    if (i < n) p[i] = 0;
}

__global__ void k_count_dst(const int* __restrict__ dst, int* __restrict__ cnt) {
    int e = blockIdx.x * blockDim.x + threadIdx.x;
    if (e < NE) atomicAdd(&cnt[dst[e]], 1);
}

// single-block scan: rptr (exclusive), dinv, cnt reset, rptr[NN]=NE. 512 threads.
__global__ void k_scan_one(int* __restrict__ cnt, int* __restrict__ rptr,
                           float* __restrict__ dinv) {
    __shared__ int sh[512];
    const int CH = (NN + 511) / 512;   // 40
    int t = threadIdx.x;
    int s = 0;
    for (int j = 0; j < CH; j++) {
        int i = t * CH + j;
        if (i < NN) s += cnt[i];
    }
    sh[t] = s;
    __syncthreads();
    for (int off = 1; off < 512; off <<= 1) {
        int v = 0;
        if (t >= off) v = sh[t - off];
        __syncthreads();
        sh[t] += v;
        __syncthreads();
    }
    int run = sh[t] - s;   // exclusive prefix for this thread's chunk
    for (int j = 0; j < CH; j++) {
        int i = t * CH + j;
        if (i < NN) {
            int v = cnt[i];
            rptr[i] = run;
            run += v;
            dinv[i] = rsqrtf((float)(v + 1));
            cnt[i] = 0;
        }
    }
    if (t == 511) rptr[NN] = NE;
}

__global__ void k_fill_csr(const int* __restrict__ src, const int* __restrict__ dst,
                           const int* __restrict__ rptr, int* __restrict__ cnt,
                           int* __restrict__ colv) {
    int e = blockIdx.x * blockDim.x + threadIdx.x;
    if (e < NE) {
        int d = dst[e];
        int p = rptr[d] + atomicAdd(&cnt[d], 1);
        colv[p] = src[e];
    }
}

// qmax = max_k ||Q[k,:]||  (into g_l[NN]; positive-float int atomicMax)
__global__ void k_qmax(const float* __restrict__ Q, float* __restrict__ qmax) {
    int w = (blockIdx.x * blockDim.x + threadIdx.x) >> 5;
    int lane = threadIdx.x & 31;
    if (w >= KK) return;
    float4 v = ((const float4*)Q)[w * 32 + lane];
    float s = v.x * v.x + v.y * v.y + v.z * v.z + v.w * v.w;
#pragma unroll
    for (int o = 16; o; o >>= 1) s += __shfl_xor_sync(0xffffffffu, s, o);
    if (lane == 0) atomicMax((int*)qmax, __float_as_int(sqrtf(s)));
}

// m[n] = qmax * ||Kd[n,:]|| / sqrt(128)
__global__ void k_mbound(const float* __restrict__ Kd, const float* __restrict__ qmax,
                         float* __restrict__ mb) {
    int w = (blockIdx.x * blockDim.x + threadIdx.x) >> 5;
    int lane = threadIdx.x & 31;
    if (w >= NN) return;
    float4 v = ((const float4*)Kd)[w * 32 + lane];
    float s = v.x * v.x + v.y * v.y + v.z * v.z + v.w * v.w;
#pragma unroll
    for (int o = 16; o; o >>= 1) s += __shfl_xor_sync(0xffffffffu, s, o);
    if (lane == 0) mb[w] = qmax[0] * sqrtf(s) * 0.0883883476483184f;
}

// ================= tf32 tensor-core GEMM =================
// PREC=3: 3xTF32 fp32-accurate; PREC=2: split-A (pair ALPHA1); PREC=1: raw (pair ALPHA2,
// or ALPHA1 when ABF16 since A is then exact-in-tf32).
// ABF16=1: A operand is bf16 in gmem/smem, expanded <<16 to fp32 (EXACT as tf32).
// EPI 0: C=acc*alpha+bias (opt relu; opt dup-store to C2); 1: atomicAdd;
// EPI 2: C = acc*alpha / rowscale[m]; 3: C(bf16)=exp(acc*alpha-bias[n]) + col sums
//        (accumulated from the ROUNDED bf16 values) atomicAdd'ed into rowscale;
// EPI 5: C += relu(acc*alpha + bias)  (in-place; block's C rows == its A rows).
// (kE - kB) must be a multiple of 32 for every launch.
#define GBM 128
#define GBN 128
#define LDMK 36
#define LDKM 132
#define LDMKH 40     // bf16 A [row][k] stride
#define LDKMH 136    // bf16 A [k][row] stride
#define ASZ 4608
#define STG 9216
#define GSMEM (2 * STG * 4)

__device__ __forceinline__ void cp16(unsigned dst, const void* src, bool v) {
    int sz = v ? 16 : 0;
    asm volatile("cp.async.cg.shared.global [%0], [%1], 16, %2;\n"
                 :: "r"(dst), "l"(src), "r"(sz));
}
#define CP_COMMIT asm volatile("cp.async.commit_group;\n")
#define CP_WAIT0  asm volatile("cp.async.wait_group 0;\n" ::: "memory")

__device__ __forceinline__ void mma8(float* d, unsigned a0, unsigned a1, unsigned a2,
                                     unsigned a3, unsigned b0, unsigned b1) {
    asm volatile("mma.sync.aligned.m16n8k8.row.col.f32.tf32.tf32.f32 "
        "{%0,%1,%2,%3}, {%4,%5,%6,%7}, {%8,%9}, {%0,%1,%2,%3};\n"
        : "+f"(d[0]), "+f"(d[1]), "+f"(d[2]), "+f"(d[3])
        : "r"(a0), "r"(a1), "r"(a2), "r"(a3), "r"(b0), "r"(b1));
}
__device__ __forceinline__ unsigned lo_part(unsigned x) {
    return __float_as_uint(__uint_as_float(x) - __uint_as_float(x & 0xFFFFE000u));
}

template<int TRANSA, int TRANSB, int EPI, int PREC, int NBLK, int ABF16>
__global__ __launch_bounds__(256, NBLK)
void k_gemm(const void* __restrict__ Ap, const float* __restrict__ B,
            void* __restrict__ Cp, int M, int N, int Ktot, int kChunk,
            int ldA, int ldB, int ldC, float alpha,
            const float* __restrict__ bias, float* __restrict__ rowscale,
            int relu, float* __restrict__ C2)
{
    extern __shared__ float smf[];
    const int tid = threadIdx.x;
    const int lane = tid & 31;
    const int warp = tid >> 5;
    const int wm = (warp >> 2) * 64;
    const int wn = (warp & 3) * 32;
    const int g = lane >> 2, tig = lane & 3;
    const int m0 = blockIdx.x * GBM;
    const int n0 = blockIdx.y * GBN;
    const int kB = blockIdx.z * kChunk;
    const int kE = (Ktot < kB + kChunk) ? Ktot : (kB + kChunk);
    const int T = (kE - kB) >> 5;

    const unsigned sbase = (unsigned)__cvta_generic_to_shared(smf);
    const float* Af = (const float*)Ap;
    const __nv_bfloat16* Ah = (const __nv_bfloat16*)Ap;
    float* C = (float*)Cp;
    __nv_bfloat16* Cbh = (__nv_bfloat16*)Cp;

    int arow, acol, brow, bcol;
    if (!ABF16) {
        if (!TRANSA) { arow = tid >> 3; acol = (tid & 7) * 4; }
        else         { arow = tid >> 5; acol = (tid & 31) * 4; }
    } else {
        if (!TRANSA) { arow = tid >> 2; acol = (tid & 3) * 8; }   // 64 rows/pass, 8 bf16
        else         { arow = tid >> 4; acol = (tid & 15) * 8; }  // 16 k-rows/pass
    }
    if (!TRANSB) { brow = tid >> 5; bcol = (tid & 31) * 4; }
    else         { brow = tid >> 3; bcol = (tid & 7) * 4; }

    const int a_lr = ((lane >> 3) & 1) * 8 + (lane & 7);
    const int a_lk = (lane >> 4) * 4;
    const int b_lr = (lane >> 4) * 8 + (lane & 7);
    const int b_lk = ((lane >> 3) & 1) * 4;

    float acc[4][4][4];
#pragma unroll
    for (int i = 0; i < 4; i++)
#pragma unroll
        for (int j = 0; j < 4; j++)
#pragma unroll
            for (int q = 0; q < 4; q++) acc[i][j][q] = 0.f;

    auto prefetch = [&](int kt, int s) {
        unsigned abase = sbase + (unsigned)(s * STG) * 4u;
        unsigned bbase = abase + ASZ * 4u;
        int kof = kB + kt * 32;
        if (!ABF16) {
#pragma unroll
            for (int p = 0; p < 4; p++) {
                if (!TRANSA) {
                    int m = m0 + arow + 32 * p;
                    bool v = m < M;
                    const float* src = Af + (size_t)(v ? m : 0) * ldA + kof + acol;
                    cp16(abase + (unsigned)((arow + 32 * p) * LDMK + acol) * 4u, src, v);
                } else {
                    int m = m0 + acol;
                    bool v = m < M;
                    const float* src = Af + (size_t)(kof + arow + 8 * p) * ldA + (v ? m : 0);
                    cp16(abase + (unsigned)((arow + 8 * p) * LDKM + acol) * 4u, src, v);
                }
            }
        } else {
#pragma unroll
            for (int p = 0; p < 2; p++) {
                if (!TRANSA) {
                    int r = arow + 64 * p;            // 0..127 tile row (m)
                    int m = m0 + r;
                    bool v = m < M;
                    const __nv_bfloat16* src = Ah + (size_t)(v ? m : 0) * ldA + kof + acol;
                    cp16(abase + (unsigned)((r * LDMKH + acol) * 2), src, v);
                } else {
                    int kr = arow + 16 * p;           // 0..31 tile k-row
                    int m = m0 + acol;
                    bool v = m < M;
                    const __nv_bfloat16* src = Ah + (size_t)(kof + kr) * ldA + (v ? m : 0);
                    cp16(abase + (unsigned)((kr * LDKMH + acol) * 2), src, v);
                }
            }
        }
#pragma unroll
        for (int p = 0; p < 4; p++) {
            if (!TRANSB) {
                int n = n0 + bcol;
                bool v = n < N;
                const float* src = B + (size_t)(kof + brow + 8 * p) * ldB + (v ? n : 0);
                cp16(bbase + (unsigned)((brow + 8 * p) * LDKM + bcol) * 4u, src, v);
            } else {
                int n = n0 + brow + 32 * p;
                bool v = n < N;
                const float* src = B + (size_t)(v ? n : 0) * ldB + kof + bcol;
                cp16(bbase + (unsigned)((brow + 32 * p) * LDMK + bcol) * 4u, src, v);
            }
        }
    };

    prefetch(0, 0);
    CP_COMMIT;
    int s = 0;
    for (int kt = 0; kt < T; kt++) {
        CP_WAIT0;
        __syncthreads();
        if (kt + 1 < T) { prefetch(kt + 1, s ^ 1); CP_COMMIT; }
        const float* AsF = smf + s * STG;
        const unsigned short* AsH = (const unsigned short*)AsF;
        const float* BsF = AsF + ASZ;
        unsigned abase = sbase + (unsigned)(s * STG) * 4u;
        unsigned bbase = abase + ASZ * 4u;
#pragma unroll
        for (int ks = 0; ks < 4; ks++) {
            const int k0 = ks * 8;
            unsigned ah[4][4], al[4][4];
            if (ABF16) {
#pragma unroll
                for (int mf = 0; mf < 4; mf++) {
                    int rb = wm + mf * 16 + g;
                    if (!TRANSA) {
                        ah[mf][0] = (unsigned)AsH[rb * LDMKH + k0 + tig] << 16;
                        ah[mf][1] = (unsigned)AsH[(rb + 8) * LDMKH + k0 + tig] << 16;
                        ah[mf][2] = (unsigned)AsH[rb * LDMKH + k0 + tig + 4] << 16;
                        ah[mf][3] = (unsigned)AsH[(rb + 8) * LDMKH + k0 + tig + 4] << 16;
                    } else {
                        ah[mf][0] = (unsigned)AsH[(k0 + tig) * LDKMH + rb] << 16;
                        ah[mf][1] = (unsigned)AsH[(k0 + tig) * LDKMH + rb + 8] << 16;
                        ah[mf][2] = (unsigned)AsH[(k0 + tig + 4) * LDKMH + rb] << 16;
                        ah[mf][3] = (unsigned)AsH[(k0 + tig + 4) * LDKMH + rb + 8] << 16;
                    }
                }
            } else if (!TRANSA) {
#pragma unroll
                for (int mf = 0; mf < 4; mf++) {
                    unsigned addr = abase + (unsigned)((wm + mf * 16 + a_lr) * LDMK + k0 + a_lk) * 4u;
                    asm volatile("ldmatrix.sync.aligned.m8n8.x4.shared.b16 {%0,%1,%2,%3}, [%4];\n"
                        : "=r"(ah[mf][0]), "=r"(ah[mf][1]), "=r"(ah[mf][2]), "=r"(ah[mf][3]) : "r"(addr));
                }
            } else {
#pragma unroll
                for (int mf = 0; mf < 4; mf++) {
                    int mb = wm + mf * 16 + g;
                    ah[mf][0] = __float_as_uint(AsF[(k0 + tig) * LDKM + mb]);
                    ah[mf][1] = __float_as_uint(AsF[(k0 + tig) * LDKM + mb + 8]);
                    ah[mf][2] = __float_as_uint(AsF[(k0 + tig + 4) * LDKM + mb]);
                    ah[mf][3] = __float_as_uint(AsF[(k0 + tig + 4) * LDKM + mb + 8]);
                }
            }
            if (!ABF16 && PREC >= 2) {
#pragma unroll
                for (int mf = 0; mf < 4; mf++)
#pragma unroll
                    for (int q = 0; q < 4; q++) {
                        al[mf][q] = lo_part(ah[mf][q]);
                        ah[mf][q] &= 0xFFFFE000u;
                    }
            }
            unsigned braw[4][2];
            if (TRANSB) {
#pragma unroll
                for (int h = 0; h < 2; h++) {
                    unsigned addr = bbase + (unsigned)((wn + h * 16 + b_lr) * LDMK + k0 + b_lk) * 4u;
                    asm volatile("ldmatrix.sync.aligned.m8n8.x4.shared.b16 {%0,%1,%2,%3}, [%4];\n"
                        : "=r"(braw[2 * h][0]), "=r"(braw[2 * h][1]),
                          "=r"(braw[2 * h + 1][0]), "=r"(braw[2 * h + 1][1])
                        : "r"(addr));
                }
            } else {
#pragma unroll
                for (int nf = 0; nf < 4; nf++) {
                    int nb = wn + nf * 8 + g;
                    braw[nf][0] = __float_as_uint(BsF[(k0 + tig) * LDKM + nb]);
                    braw[nf][1] = __float_as_uint(BsF[(k0 + tig + 4) * LDKM + nb]);
                }
            }
#pragma unroll
            for (int nf = 0; nf < 4; nf++) {
                if (!ABF16 && PREC == 3) {
                    unsigned bh0 = braw[nf][0] & 0xFFFFE000u;
                    unsigned bh1 = braw[nf][1] & 0xFFFFE000u;
                    unsigned bl0 = lo_part(braw[nf][0]);
                    unsigned bl1 = lo_part(braw[nf][1]);
#pragma unroll
                    for (int mf = 0; mf < 4; mf++) {
                        mma8(acc[mf][nf], ah[mf][0], ah[mf][1], ah[mf][2], ah[mf][3], bh0, bh1);
                        mma8(acc[mf][nf], ah[mf][0], ah[mf][1], ah[mf][2], ah[mf][3], bl0, bl1);
                        mma8(acc[mf][nf], al[mf][0], al[mf][1], al[mf][2], al[mf][3], bh0, bh1);
                    }
                } else if (!ABF16 && PREC == 2) {
#pragma unroll
                    for (int mf = 0; mf < 4; mf++) {
                        mma8(acc[mf][nf], ah[mf][0], ah[mf][1], ah[mf][2], ah[mf][3],
                             braw[nf][0], braw[nf][1]);
                        mma8(acc[mf][nf], al[mf][0], al[mf][1], al[mf][2], al[mf][3],
                             braw[nf][0], braw[nf][1]);
                    }
                } else {
#pragma unroll
                    for (int mf = 0; mf < 4; mf++)
                        mma8(acc[mf][nf], ah[mf][0], ah[mf][1], ah[mf][2], ah[mf][3],
                             braw[nf][0], braw[nf][1]);
                }
            }
        }
        s ^= 1;
    }

    // epilogue
    float cs[4][2];
    if (EPI == 3) {
#pragma unroll
        for (int nf = 0; nf < 4; nf++) { cs[nf][0] = 0.f; cs[nf][1] = 0.f; }
    }
#pragma unroll
    for (int mf = 0; mf < 4; mf++) {
        int r0 = m0 + wm + mf * 16 + g;
        int r1 = r0 + 8;
#pragma unroll
        for (int nf = 0; nf < 4; nf++) {
            int c = n0 + wn + nf * 8 + tig * 2;
            float v0 = acc[mf][nf][0] * alpha;
            float v1 = acc[mf][nf][1] * alpha;
            float v2 = acc[mf][nf][2] * alpha;
            float v3 = acc[mf][nf][3] * alpha;
            if (EPI == 0) {
                float bb0 = bias ? bias[c] : 0.f;
                float bb1 = bias ? bias[c + 1] : 0.f;
                v0 += bb0; v1 += bb1; v2 += bb0; v3 += bb1;
                if (relu) {
                    v0 = fmaxf(v0, 0.f); v1 = fmaxf(v1, 0.f);
                    v2 = fmaxf(v2, 0.f); v3 = fmaxf(v3, 0.f);
                }
                if (c < N) {
                    if (r0 < M) {
                        C[(size_t)r0 * ldC + c] = v0; C[(size_t)r0 * ldC + c + 1] = v1;
                        if (C2) { C2[(size_t)r0 * ldC + c] = v0; C2[(size_t)r0 * ldC + c + 1] = v1; }
                    }
                    if (r1 < M) {
                        C[(size_t)r1 * ldC + c] = v2; C[(size_t)r1 * ldC + c + 1] = v3;
                        if (C2) { C2[(size_t)r1 * ldC + c] = v2; C2[(size_t)r1 * ldC + c + 1] = v3; }
                    }
                }
            } else if (EPI == 1) {
                if (c < N) {
                    if (r0 < M) { atomicAdd(&C[(size_t)r0 * ldC + c], v0); atomicAdd(&C[(size_t)r0 * ldC + c + 1], v1); }
                    if (r1 < M) { atomicAdd(&C[(size_t)r1 * ldC + c], v2); atomicAdd(&C[(size_t)r1 * ldC + c + 1], v3); }
                }
            } else if (EPI == 2) {
                if (c < N) {
                    if (r0 < M) { float sc = 1.f / rowscale[r0]; C[(size_t)r0 * ldC + c] = sc * v0; C[(size_t)r0 * ldC + c + 1] = sc * v1; }
                    if (r1 < M) { float sc = 1.f / rowscale[r1]; C[(size_t)r1 * ldC + c] = sc * v2; C[(size_t)r1 * ldC + c + 1] = sc * v3; }
                }
            } else if (EPI == 5) {
                float bb0 = bias ? bias[c] : 0.f;
                float bb1 = bias ? bias[c + 1] : 0.f;
                v0 = fmaxf(v0 + bb0, 0.f); v1 = fmaxf(v1 + bb1, 0.f);
                v2 = fmaxf(v2 + bb0, 0.f); v3 = fmaxf(v3 + bb1, 0.f);
                if (c < N) {
                    if (r0 < M) { C[(size_t)r0 * ldC + c] += v0; C[(size_t)r0 * ldC + c + 1] += v1; }
                    if (r1 < M) { C[(size_t)r1 * ldC + c] += v2; C[(size_t)r1 * ldC + c + 1] += v3; }
                }
            } else {
                // EPI 3: bf16 store of exp(score - mbound[n]) + col sums from ROUNDED values
                bool c0ok = (c < N), c1ok = (c + 1 < N);
                float mc0 = c0ok ? bias[c] : 0.f;
                float mc1 = c1ok ? bias[c + 1] : 0.f;
                if (r0 < M && c0ok) {
                    __nv_bfloat16 h0 = __float2bfloat16_rn(__expf(v0 - mc0));
                    __nv_bfloat16 h1 = __float2bfloat16_rn(__expf(v1 - mc1));
                    __nv_bfloat162 pk; pk.x = h0; pk.y = h1;
                    *(__nv_bfloat162*)&Cbh[(size_t)r0 * ldC + c] = pk;
                    cs[nf][0] += __bfloat162float(h0);
                    cs[nf][1] += __bfloat162float(h1);
                }
                if (r1 < M && c0ok) {
                    __nv_bfloat16 h2 = __float2bfloat16_rn(__expf(v2 - mc0));
                    __nv_bfloat16 h3 = __float2bfloat16_rn(__expf(v3 - mc1));
                    __nv_bfloat162 pk; pk.x = h2; pk.y = h3;
                    *(__nv_bfloat162*)&Cbh[(size_t)r1 * ldC + c] = pk;
                    cs[nf][0] += __bfloat162float(h2);
                    cs[nf][1] += __bfloat162float(h3);
                }
            }
        }
    }
    if (EPI == 3) {
#pragma unroll
        for (int nf = 0; nf < 4; nf++) {
#pragma unroll
            for (int j = 0; j < 2; j++) {
                float v = cs[nf][j];
                v += __shfl_xor_sync(0xffffffffu, v, 4);
                v += __shfl_xor_sync(0xffffffffu, v, 8);
                v += __shfl_xor_sync(0xffffffffu, v, 16);
                int c = n0 + wn + nf * 8 + tig * 2 + j;
                if (lane < 4 && c < N) atomicAdd(&rowscale[c], v);
            }
        }
    }
}

// ---------------- GCN aggregation (opt: multiply result by 1/invscale[node]) --------
__global__ void k_aggregate(const float* __restrict__ H, const int* __restrict__ rptr,
                            const int* __restrict__ colv, const float* __restrict__ dinv,
                            const float* __restrict__ bias, float* __restrict__ Out,
                            int relu, const float* __restrict__ invscale) {
    int w = (blockIdx.x * blockDim.x + threadIdx.x) >> 5;
    int lane = threadIdx.x & 31;
    if (w >= NN) return;
    const float4* H4 = (const float4*)H;
    float4 acc = make_float4(0.f, 0.f, 0.f, 0.f);
    int s = rptr[w], e = rptr[w + 1];
    for (int j = s; j < e; j++) {
        int src = colv[j];
        float wt = dinv[src];
        float4 h = H4[src * 32 + lane];
        acc.x += wt * h.x; acc.y += wt * h.y; acc.z += wt * h.z; acc.w += wt * h.w;
    }
    float dn = dinv[w];
    float4 hs = H4[w * 32 + lane];
    float4 bb = ((const float4*)bias)[lane];
    acc.x = dn * (acc.x + dn * hs.x) + bb.x;
    acc.y = dn * (acc.y + dn * hs.y) + bb.y;
    acc.z = dn * (acc.z + dn * hs.z) + bb.z;
    acc.w = dn * (acc.w + dn * hs.w) + bb.w;
    if (relu) {
        acc.x = fmaxf(acc.x, 0.f); acc.y = fmaxf(acc.y, 0.f);
        acc.z = fmaxf(acc.z, 0.f); acc.w = fmaxf(acc.w, 0.f);
    }
    if (invscale) {
        float rs = 1.f / invscale[w];
        acc.x *= rs; acc.y *= rs; acc.z *= rs; acc.w *= rs;
    }
    ((float4*)Out)[w * 32 + lane] = acc;
}

// ---------------- LayerNorm rows of X[M,128] ----------------
__global__ void k_layernorm(float* __restrict__ X, const float* __restrict__ g,
                            const float* __restrict__ b, int M) {
    int w = (blockIdx.x * blockDim.x + threadIdx.x) >> 5;
    int lane = threadIdx.x & 31;
    if (w >= M) return;
    float4 v = ((const float4*)X)[w * 32 + lane];
    float s = v.x + v.y + v.z + v.w;
    float sq = v.x * v.x + v.y * v.y + v.z * v.z + v.w * v.w;
#pragma unroll
    for (int o = 16; o; o >>= 1) {
        s += __shfl_xor_sync(0xffffffffu, s, o);
        sq += __shfl_xor_sync(0xffffffffu, sq, o);
    }
    float mean = s * (1.f / 128.f);
    float var = sq * (1.f / 128.f) - mean * mean;
    float rstd = rsqrtf(var + 1e-5f);
    float4 gg = ((const float4*)g)[lane];
    float4 bb = ((const float4*)b)[lane];
    v.x = (v.x - mean) * rstd * gg.x + bb.x;
    v.y = (v.y - mean) * rstd * gg.y + bb.y;
    v.z = (v.z - mean) * rstd * gg.z + bb.z;
    v.w = (v.w - mean) * rstd * gg.w + bb.w;
    ((float4*)X)[w * 32 + lane] = v;
}

// ---------------- host orchestration ----------------
static float* faddr(const void* sym) {
    void* p = nullptr;
    cudaGetSymbolAddress(&p, sym);
    return (float*)p;
}
static int* iaddr(const void* sym) {
    void* p = nullptr;
    cudaGetSymbolAddress(&p, sym);
    return (int*)p;
}

extern "C" void kernel_launch(void* const* d_in, const int* in_sizes, int n_in,
                              void* d_out, int out_size) {
    const float* x  = (const float*)d_in[0];
    const int*   ei = (const int*)d_in[1];
    const float* W1 = (const float*)d_in[3];  const float* b1 = (const float*)d_in[4];
    const float* W2 = (const float*)d_in[5];  const float* b2 = (const float*)d_in[6];
    const float* S  = (const float*)d_in[7];
    const float* Wq = (const float*)d_in[8];  const float* bq = (const float*)d_in[9];
    const float* Wk = (const float*)d_in[10]; const float* bk = (const float*)d_in[11];
    const float* Wv = (const float*)d_in[12]; const float* bv = (const float*)d_in[13];
    const float* Wo = (const float*)d_in[14]; const float* bo = (const float*)d_in[15];
    const float* g0 = (const float*)d_in[16]; const float* be0 = (const float*)d_in[17];
    const float* g1 = (const float*)d_in[18]; const float* be1 = (const float*)d_in[19];
    const float* Wl = (const float*)d_in[20]; const float* bl = (const float*)d_in[21];
    const float* W3 = (const float*)d_in[22]; const float* b3 = (const float*)d_in[23];
    const float* W4 = (const float*)d_in[24]; const float* b4 = (const float*)d_in[25];
    const float* W5 = (const float*)d_in[26]; const float* b5 = (const float*)d_in[27];

    const int* src = ei;
    const int* dst = ei + NE;

    __nv_bfloat16* score;
    { void* p = nullptr; cudaGetSymbolAddress(&p, g_score); score = (__nv_bfloat16*)p; }
    float* t     = faddr(g_t);
    float* h1    = faddr(g_h1);
    float* h2    = faddr(g_h2);
    float* Kd    = faddr(g_Kd);
    float* Vd    = faddr(g_Vd);
    float* Q     = faddr(g_Q);
    float* outb  = faddr(g_out);
    float* xl    = faddr(g_xl);
    float* dinv  = faddr(g_dinv);
    float* lsum  = faddr(g_l);
    float* mb    = faddr(g_mbound);
    int* cnt   = iaddr(g_cnt);
    int* rptr  = iaddr(g_rptr);
    int* colv  = iaddr(g_col);

    cudaFuncSetAttribute((const void*)k_gemm<0,0,0,2,1,0>, cudaFuncAttributeMaxDynamicSharedMemorySize, GSMEM);
    cudaFuncSetAttribute((const void*)k_gemm<0,0,0,3,1,0>, cudaFuncAttributeMaxDynamicSharedMemorySize, GSMEM);
    cudaFuncSetAttribute((const void*)k_gemm<0,0,5,2,1,0>, cudaFuncAttributeMaxDynamicSharedMemorySize, GSMEM);
    cudaFuncSetAttribute((const void*)k_gemm<0,1,3,1,2,0>, cudaFuncAttributeMaxDynamicSharedMemorySize, GSMEM);
    cudaFuncSetAttribute((const void*)k_gemm<0,0,1,1,2,1>, cudaFuncAttributeMaxDynamicSharedMemorySize, GSMEM);
    cudaFuncSetAttribute((const void*)k_gemm<1,0,2,1,2,1>, cudaFuncAttributeMaxDynamicSharedMemorySize, GSMEM);

    const int mbN = (NN + 127) / 128;   // 157
    const int mbK = (KK + 127) / 128;   // 16
    float* dOut = (float*)d_out;
    const float rs128c = 0.0883883476483184f * ALPHA2;  // both operands raw tf32

    // --- fused zeroing (score bf16 pads, xl pads, lsum+qmax) ---
    k_zero_all<<<(((KK32 - KK) * NN / 2) + 255) / 256, 256>>>(
        (unsigned*)(score + (size_t)KK * NN), xl + (size_t)KK * DD, lsum);

    // --- CSR + degree ---
    k_zero_int<<<(NN + 255) / 256, 256>>>(cnt, NN);
    k_count_dst<<<(NE + 255) / 256, 256>>>(dst, cnt);
    k_scan_one<<<1, 512>>>(cnt, rptr, dinv);
    k_fill_csr<<<(NE + 255) / 256, 256>>>(src, dst, rptr, cnt, colv);

    // --- GCN1, GCN2 (PREC=2 + ALPHA1) ---
    k_gemm<0,0,0,2,1,0><<<dim3(mbN,1,1), 256, GSMEM>>>(x,  W1, t, NN, 128, 128, 128, 128, 128, 128, ALPHA1, nullptr, nullptr, 0, nullptr);
    k_aggregate<<<(NN * 32 + 255) / 256, 256>>>(t, rptr, colv, dinv, b1, h1, 1, nullptr);
    k_gemm<0,0,0,2,1,0><<<dim3(mbN,1,1), 256, GSMEM>>>(h1, W2, t, NN, 128, 128, 128, 128, 128, 128, ALPHA1, nullptr, nullptr, 0, nullptr);
    k_aggregate<<<(NN * 32 + 255) / 256, 256>>>(t, rptr, colv, dinv, b2, h2, 1, nullptr);

    // --- Q (dual-write into outb), Kd ---
    k_gemm<0,0,0,2,1,0><<<dim3(mbK,1,1), 256, GSMEM>>>(S,  Wq, Q, KK, 128, 128, 128, 128, 128, 128, ALPHA1, bq, nullptr, 0, outb);
    k_gemm<0,0,0,2,1,0><<<dim3(mbN,1,1), 256, GSMEM>>>(h2, Wk, t, NN, 128, 128, 128, 128, 128, 128, ALPHA1, nullptr, nullptr, 0, nullptr);
    k_aggregate<<<(NN * 32 + 255) / 256, 256>>>(t, rptr, colv, dinv, bk, Kd, 0, nullptr);

    // --- softmax bound: qmax (into lsum[NN]) then m[n] ---
    k_qmax<<<(KK * 32 + 255) / 256, 256>>>(Q, lsum + NN);
    k_mbound<<<(NN * 32 + 255) / 256, 256>>>(Kd, lsum + NN, mb);

    // --- fused score+exp(bf16)+colsum ---
    k_gemm<0,1,3,1,2,0><<<dim3(mbK, mbN, 1), 256, GSMEM>>>(Q, Kd, score, KK, NN, 128, 128, 128, 128, NN, rs128c, mb, lsum, 0, nullptr);

    // --- Vd (aggregate scales by 1/lsum[n]; ready only after score gemm) ---
    k_gemm<0,0,0,2,1,0><<<dim3(mbN,1,1), 256, GSMEM>>>(h2, Wv, t, NN, 128, 128, 128, 128, 128, 128, ALPHA1, nullptr, nullptr, 0, nullptr);
    k_aggregate<<<(NN * 32 + 255) / 256, 256>>>(t, rptr, colv, dinv, bv, Vd, 0, lsum);

    // --- Out += Aexp(bf16, exact in tf32) @ Vd_scaled: 1 MMA + ALPHA1 ---
    k_gemm<0,0,1,1,2,1><<<dim3(mbK, 1, 16), 256, GSMEM>>>(score, Vd, outb, KK, 128, NN, 1280, NN, 128, 128, ALPHA1, nullptr, nullptr, 0, nullptr);

    // --- epilogue on [K,128] ---
    k_layernorm<<<(KK * 32 + 255) / 256, 256>>>(outb, g0, be0, KK);
    k_gemm<0,0,5,2,1,0><<<dim3(mbK,1,1), 256, GSMEM>>>(outb, Wo, outb, KK, 128, 128, 128, 128, 128, 128, ALPHA1, bo, nullptr, 1, nullptr);
    k_layernorm<<<(KK * 32 + 255) / 256, 256>>>(outb, g1, be1, KK);
    k_gemm<0,0,0,2,1,0><<<dim3(mbK,1,1), 256, GSMEM>>>(outb, Wl, xl, KK, 128, 128, 128, 128, 128, 128, ALPHA1, bl, nullptr, 0, nullptr);

    // --- x_out = (Aexp^T @ xl) / lsum[n]: A exact bf16-in-tf32, B raw + ALPHA1 ---
    k_gemm<1,0,2,1,2,1><<<dim3(mbN,1,1), 256, GSMEM>>>(score, xl, h1, NN, 128, KK32, KK32, NN, 128, 128, ALPHA1, nullptr, lsum, 0, nullptr);

    // --- GCN3, GCN4 (PREC=2), GCN5 (PREC=3, final output insurance) ---
    k_gemm<0,0,0,2,1,0><<<dim3(mbN,1,1), 256, GSMEM>>>(h1, W3, t, NN, 128, 128, 128, 128, 128, 128, ALPHA1, nullptr, nullptr, 0, nullptr);
    k_aggregate<<<(NN * 32 + 255) / 256, 256>>>(t, rptr, colv, dinv, b3, h2, 1, nullptr);
    k_gemm<0,0,0,2,1,0><<<dim3(mbN,1,1), 256, GSMEM>>>(h2, W4, t, NN, 128, 128, 128, 128, 128, 128, ALPHA1, nullptr, nullptr, 0, nullptr);
    k_aggregate<<<(NN * 32 + 255) / 256, 256>>>(t, rptr, colv, dinv, b4, h1, 1, nullptr);
    k_gemm<0,0,0,3,1,0><<<dim3(mbN,1,1), 256, GSMEM>>>(h1, W5, t, NN, 128, 128, 128, 128, 128, 128, 1.f, nullptr, nullptr, 0, nullptr);
    k_aggregate<<<(NN * 32 + 255) / 256, 256>>>(t, rptr, colv, dinv, b5, dOut, 0, nullptr);
}

// round 17
// speedup vs baseline: 3.6423x; 1.0692x over previous
#include <cuda_runtime.h>
#include <cuda_bf16.h>
#include <math.h>

#define NN 20000
#define NE 320000
#define DD 128
#define KK 2000
#define KK32 2016   // KK padded to multiple of 32 for the ATX gemm

// ---------------- scratch (static device globals; no allocation) ----------------
__device__ __nv_bfloat16 g_score[(size_t)KK32 * NN]; // exp(score-m) bf16; rows >= KK zero
__device__ float g_t[NN * DD];
__device__ float g_h1[NN * DD];
__device__ float g_h2[NN * DD];
__device__ float g_Kd[NN * DD];
__device__ float g_Vd[NN * DD];
__device__ float g_Q[KK * DD];
__device__ float g_out[KK * DD];
__device__ float g_xl[KK32 * DD];            // rows >= KK are zero
__device__ float g_dinv[NN];
__device__ float g_l[NN + 1];                // column sums; [NN] = qmax
__device__ float g_mbound[NN];               // per-column softmax shift (upper bound)
__device__ int   g_cnt[NN];
__device__ int   g_rptr[NN + 1];
__device__ int   g_col[NE];
__device__ int   g_bsums[64];

// tf32 mean-truncation-shrink corrections (validated R10/R11)
#define ALPHA1 1.000352f
#define ALPHA2 1.000704f

// ---------------- fused zero kernel: score pads (bf16), xl pads, lsum, cnt ----------
__global__ void k_zero_all(unsigned* scorepad_u32, float* xlpad, float* lsum, int* cnt) {
    int i = blockIdx.x * blockDim.x + threadIdx.x;
    const int NPAD_U32 = (KK32 - KK) * NN / 2;   // bf16 pads as u32
    if (i < NPAD_U32) scorepad_u32[i] = 0u;
    if (i < (KK32 - KK) * DD) xlpad[i] = 0.f;
    if (i < NN + 1) lsum[i] = 0.f;
    if (i < NN) cnt[i] = 0;
}

__global__ void k_count_dst(const int* __restrict__ dst, int* __restrict__ cnt) {
    int e = blockIdx.x * blockDim.x + threadIdx.x;
    if (e < NE) atomicAdd(&cnt[dst[e]], 1);
}

// ---------------- parallel 3-phase scan (R6-validated; k_scan_one was 42us serial) ----
__global__ void k_scan1(const int* __restrict__ cnt, int* __restrict__ rptr,
                        int* __restrict__ bsums) {
    __shared__ int sh[1024];
    int i = blockIdx.x * 1024 + threadIdx.x;
    int v = (i < NN) ? cnt[i] : 0;
    sh[threadIdx.x] = v;
    __syncthreads();
    for (int off = 1; off < 1024; off <<= 1) {
        int t = 0;
        if ((int)threadIdx.x >= off) t = sh[threadIdx.x - off];
        __syncthreads();
        sh[threadIdx.x] += t;
        __syncthreads();
    }
    if (i < NN) rptr[i] = sh[threadIdx.x] - v;   // exclusive
    if (threadIdx.x == 1023) bsums[blockIdx.x] = sh[1023];
}

__global__ void k_scan2(int* bsums, int nb) {
    if (threadIdx.x == 0 && blockIdx.x == 0) {
        int acc = 0;
        for (int b = 0; b < nb; b++) { int t = bsums[b]; bsums[b] = acc; acc += t; }
    }
}

// add-back + dinv + cnt reset fused
__global__ void k_scan3(int* __restrict__ rptr, const int* __restrict__ bsums,
                        int* __restrict__ cnt, float* __restrict__ dinv) {
    int i = blockIdx.x * 1024 + threadIdx.x;
    if (i < NN) {
        rptr[i] += bsums[blockIdx.x];
        dinv[i] = rsqrtf((float)(cnt[i] + 1));  // +1 self loop
        cnt[i] = 0;                             // becomes cursor
    }
    if (i == 0) rptr[NN] = NE;
}

__global__ void k_fill_csr(const int* __restrict__ src, const int* __restrict__ dst,
                           const int* __restrict__ rptr, int* __restrict__ cnt,
                           int* __restrict__ colv) {
    int e = blockIdx.x * blockDim.x + threadIdx.x;
    if (e < NE) {
        int d = dst[e];
        int p = rptr[d] + atomicAdd(&cnt[d], 1);
        colv[p] = src[e];
    }
}

// qmax = max_k ||Q[k,:]||  (into g_l[NN]; positive-float int atomicMax)
__global__ void k_qmax(const float* __restrict__ Q, float* __restrict__ qmax) {
    int w = (blockIdx.x * blockDim.x + threadIdx.x) >> 5;
    int lane = threadIdx.x & 31;
    if (w >= KK) return;
    float4 v = ((const float4*)Q)[w * 32 + lane];
    float s = v.x * v.x + v.y * v.y + v.z * v.z + v.w * v.w;
#pragma unroll
    for (int o = 16; o; o >>= 1) s += __shfl_xor_sync(0xffffffffu, s, o);
    if (lane == 0) atomicMax((int*)qmax, __float_as_int(sqrtf(s)));
}

// ================= tf32 tensor-core GEMM =================
// PREC=3: 3xTF32 fp32-accurate; PREC=2: split-A (pair ALPHA1); PREC=1: raw (pair ALPHA2,
// or ALPHA1 when ABF16 since A is then exact-in-tf32).
// ABF16=1: A operand is bf16 in gmem/smem, expanded <<16 to fp32 (EXACT as tf32).
// EPI 0: C=acc*alpha+bias (opt relu; opt dup-store to C2); 1: atomicAdd;
// EPI 2: C = acc*alpha / rowscale[m]; 3: C(bf16)=exp(acc*alpha-bias[n]) + col sums
//        (accumulated from the ROUNDED bf16 values) atomicAdd'ed into rowscale;
// EPI 5: C += relu(acc*alpha + bias)  (in-place; block's C rows == its A rows).
// (kE - kB) must be a multiple of 32 for every launch.
#define GBM 128
#define GBN 128
#define LDMK 36
#define LDKM 132
#define LDMKH 40     // bf16 A [row][k] stride
#define LDKMH 136    // bf16 A [k][row] stride
#define ASZ 4608
#define STG 9216
#define GSMEM (2 * STG * 4)

__device__ __forceinline__ void cp16(unsigned dst, const void* src, bool v) {
    int sz = v ? 16 : 0;
    asm volatile("cp.async.cg.shared.global [%0], [%1], 16, %2;\n"
                 :: "r"(dst), "l"(src), "r"(sz));
}
#define CP_COMMIT asm volatile("cp.async.commit_group;\n")
#define CP_WAIT0  asm volatile("cp.async.wait_group 0;\n" ::: "memory")

__device__ __forceinline__ void mma8(float* d, unsigned a0, unsigned a1, unsigned a2,
                                     unsigned a3, unsigned b0, unsigned b1) {
    asm volatile("mma.sync.aligned.m16n8k8.row.col.f32.tf32.tf32.f32 "
        "{%0,%1,%2,%3}, {%4,%5,%6,%7}, {%8,%9}, {%0,%1,%2,%3};\n"
        : "+f"(d[0]), "+f"(d[1]), "+f"(d[2]), "+f"(d[3])
        : "r"(a0), "r"(a1), "r"(a2), "r"(a3), "r"(b0), "r"(b1));
}
__device__ __forceinline__ unsigned lo_part(unsigned x) {
    return __float_as_uint(__uint_as_float(x) - __uint_as_float(x & 0xFFFFE000u));
}

template<int TRANSA, int TRANSB, int EPI, int PREC, int NBLK, int ABF16>
__global__ __launch_bounds__(256, NBLK)
void k_gemm(const void* __restrict__ Ap, const float* __restrict__ B,
            void* __restrict__ Cp, int M, int N, int Ktot, int kChunk,
            int ldA, int ldB, int ldC, float alpha,
            const float* __restrict__ bias, float* __restrict__ rowscale,
            int relu, float* __restrict__ C2)
{
    extern __shared__ float smf[];
    const int tid = threadIdx.x;
    const int lane = tid & 31;
    const int warp = tid >> 5;
    const int wm = (warp >> 2) * 64;
    const int wn = (warp & 3) * 32;
    const int g = lane >> 2, tig = lane & 3;
    const int m0 = blockIdx.x * GBM;
    const int n0 = blockIdx.y * GBN;
    const int kB = blockIdx.z * kChunk;
    const int kE = (Ktot < kB + kChunk) ? Ktot : (kB + kChunk);
    const int T = (kE - kB) >> 5;

    const unsigned sbase = (unsigned)__cvta_generic_to_shared(smf);
    const float* Af = (const float*)Ap;
    const __nv_bfloat16* Ah = (const __nv_bfloat16*)Ap;
    float* C = (float*)Cp;
    __nv_bfloat16* Cbh = (__nv_bfloat16*)Cp;

    int arow, acol, brow, bcol;
    if (!ABF16) {
        if (!TRANSA) { arow = tid >> 3; acol = (tid & 7) * 4; }
        else         { arow = tid >> 5; acol = (tid & 31) * 4; }
    } else {
        if (!TRANSA) { arow = tid >> 2; acol = (tid & 3) * 8; }   // 64 rows/pass, 8 bf16
        else         { arow = tid >> 4; acol = (tid & 15) * 8; }  // 16 k-rows/pass
    }
    if (!TRANSB) { brow = tid >> 5; bcol = (tid & 31) * 4; }
    else         { brow = tid >> 3; bcol = (tid & 7) * 4; }

    const int a_lr = ((lane >> 3) & 1) * 8 + (lane & 7);
    const int a_lk = (lane >> 4) * 4;
    const int b_lr = (lane >> 4) * 8 + (lane & 7);
    const int b_lk = ((lane >> 3) & 1) * 4;

    float acc[4][4][4];
#pragma unroll
    for (int i = 0; i < 4; i++)
#pragma unroll
        for (int j = 0; j < 4; j++)
#pragma unroll
            for (int q = 0; q < 4; q++) acc[i][j][q] = 0.f;

    auto prefetch = [&](int kt, int s) {
        unsigned abase = sbase + (unsigned)(s * STG) * 4u;
        unsigned bbase = abase + ASZ * 4u;
        int kof = kB + kt * 32;
        if (!ABF16) {
#pragma unroll
            for (int p = 0; p < 4; p++) {
                if (!TRANSA) {
                    int m = m0 + arow + 32 * p;
                    bool v = m < M;
                    const float* src = Af + (size_t)(v ? m : 0) * ldA + kof + acol;
                    cp16(abase + (unsigned)((arow + 32 * p) * LDMK + acol) * 4u, src, v);
                } else {
                    int m = m0 + acol;
                    bool v = m < M;
                    const float* src = Af + (size_t)(kof + arow + 8 * p) * ldA + (v ? m : 0);
                    cp16(abase + (unsigned)((arow + 8 * p) * LDKM + acol) * 4u, src, v);
                }
            }
        } else {
#pragma unroll
            for (int p = 0; p < 2; p++) {
                if (!TRANSA) {
                    int r = arow + 64 * p;            // 0..127 tile row (m)
                    int m = m0 + r;
                    bool v = m < M;
                    const __nv_bfloat16* src = Ah + (size_t)(v ? m : 0) * ldA + kof + acol;
                    cp16(abase + (unsigned)((r * LDMKH + acol) * 2), src, v);
                } else {
                    int kr = arow + 16 * p;           // 0..31 tile k-row
                    int m = m0 + acol;
                    bool v = m < M;
                    const __nv_bfloat16* src = Ah + (size_t)(kof + kr) * ldA + (v ? m : 0);
                    cp16(abase + (unsigned)((kr * LDKMH + acol) * 2), src, v);
                }
            }
        }
#pragma unroll
        for (int p = 0; p < 4; p++) {
            if (!TRANSB) {
                int n = n0 + bcol;
                bool v = n < N;
                const float* src = B + (size_t)(kof + brow + 8 * p) * ldB + (v ? n : 0);
                cp16(bbase + (unsigned)((brow + 8 * p) * LDKM + bcol) * 4u, src, v);
            } else {
                int n = n0 + brow + 32 * p;
                bool v = n < N;
                const float* src = B + (size_t)(v ? n : 0) * ldB + kof + bcol;
                cp16(bbase + (unsigned)((brow + 32 * p) * LDMK + bcol) * 4u, src, v);
            }
        }
    };

    prefetch(0, 0);
    CP_COMMIT;
    int s = 0;
    for (int kt = 0; kt < T; kt++) {
        CP_WAIT0;
        __syncthreads();
        if (kt + 1 < T) { prefetch(kt + 1, s ^ 1); CP_COMMIT; }
        const float* AsF = smf + s * STG;
        const unsigned short* AsH = (const unsigned short*)AsF;
        const float* BsF = AsF + ASZ;
        unsigned abase = sbase + (unsigned)(s * STG) * 4u;
        unsigned bbase = abase + ASZ * 4u;
#pragma unroll
        for (int ks = 0; ks < 4; ks++) {
            const int k0 = ks * 8;
            unsigned ah[4][4], al[4][4];
            if (ABF16) {
#pragma unroll
                for (int mf = 0; mf < 4; mf++) {
                    int rb = wm + mf * 16 + g;
                    if (!TRANSA) {
                        ah[mf][0] = (unsigned)AsH[rb * LDMKH + k0 + tig] << 16;
                        ah[mf][1] = (unsigned)AsH[(rb + 8) * LDMKH + k0 + tig] << 16;
                        ah[mf][2] = (unsigned)AsH[rb * LDMKH + k0 + tig + 4] << 16;
                        ah[mf][3] = (unsigned)AsH[(rb + 8) * LDMKH + k0 + tig + 4] << 16;
                    } else {
                        ah[mf][0] = (unsigned)AsH[(k0 + tig) * LDKMH + rb] << 16;
                        ah[mf][1] = (unsigned)AsH[(k0 + tig) * LDKMH + rb + 8] << 16;
                        ah[mf][2] = (unsigned)AsH[(k0 + tig + 4) * LDKMH + rb] << 16;
                        ah[mf][3] = (unsigned)AsH[(k0 + tig + 4) * LDKMH + rb + 8] << 16;
                    }
                }
            } else if (!TRANSA) {
#pragma unroll
                for (int mf = 0; mf < 4; mf++) {
                    unsigned addr = abase + (unsigned)((wm + mf * 16 + a_lr) * LDMK + k0 + a_lk) * 4u;
                    asm volatile("ldmatrix.sync.aligned.m8n8.x4.shared.b16 {%0,%1,%2,%3}, [%4];\n"
                        : "=r"(ah[mf][0]), "=r"(ah[mf][1]), "=r"(ah[mf][2]), "=r"(ah[mf][3]) : "r"(addr));
                }
            } else {
#pragma unroll
                for (int mf = 0; mf < 4; mf++) {
                    int mb = wm + mf * 16 + g;
                    ah[mf][0] = __float_as_uint(AsF[(k0 + tig) * LDKM + mb]);
                    ah[mf][1] = __float_as_uint(AsF[(k0 + tig) * LDKM + mb + 8]);
                    ah[mf][2] = __float_as_uint(AsF[(k0 + tig + 4) * LDKM + mb]);
                    ah[mf][3] = __float_as_uint(AsF[(k0 + tig + 4) * LDKM + mb + 8]);
                }
            }
            if (!ABF16 && PREC >= 2) {
#pragma unroll
                for (int mf = 0; mf < 4; mf++)
#pragma unroll
                    for (int q = 0; q < 4; q++) {
                        al[mf][q] = lo_part(ah[mf][q]);
                        ah[mf][q] &= 0xFFFFE000u;
                    }
            }
            unsigned braw[4][2];
            if (TRANSB) {
#pragma unroll
                for (int h = 0; h < 2; h++) {
                    unsigned addr = bbase + (unsigned)((wn + h * 16 + b_lr) * LDMK + k0 + b_lk) * 4u;
                    asm volatile("ldmatrix.sync.aligned.m8n8.x4.shared.b16 {%0,%1,%2,%3}, [%4];\n"
                        : "=r"(braw[2 * h][0]), "=r"(braw[2 * h][1]),
                          "=r"(braw[2 * h + 1][0]), "=r"(braw[2 * h + 1][1])
                        : "r"(addr));
                }
            } else {
#pragma unroll
                for (int nf = 0; nf < 4; nf++) {
                    int nb = wn + nf * 8 + g;
                    braw[nf][0] = __float_as_uint(BsF[(k0 + tig) * LDKM + nb]);
                    braw[nf][1] = __float_as_uint(BsF[(k0 + tig + 4) * LDKM + nb]);
                }
            }
#pragma unroll
            for (int nf = 0; nf < 4; nf++) {
                if (!ABF16 && PREC == 3) {
                    unsigned bh0 = braw[nf][0] & 0xFFFFE000u;
                    unsigned bh1 = braw[nf][1] & 0xFFFFE000u;
                    unsigned bl0 = lo_part(braw[nf][0]);
                    unsigned bl1 = lo_part(braw[nf][1]);
#pragma unroll
                    for (int mf = 0; mf < 4; mf++) {
                        mma8(acc[mf][nf], ah[mf][0], ah[mf][1], ah[mf][2], ah[mf][3], bh0, bh1);
                        mma8(acc[mf][nf], ah[mf][0], ah[mf][1], ah[mf][2], ah[mf][3], bl0, bl1);
                        mma8(acc[mf][nf], al[mf][0], al[mf][1], al[mf][2], al[mf][3], bh0, bh1);
                    }
                } else if (!ABF16 && PREC == 2) {
#pragma unroll
                    for (int mf = 0; mf < 4; mf++) {
                        mma8(acc[mf][nf], ah[mf][0], ah[mf][1], ah[mf][2], ah[mf][3],
                             braw[nf][0], braw[nf][1]);
                        mma8(acc[mf][nf], al[mf][0], al[mf][1], al[mf][2], al[mf][3],
                             braw[nf][0], braw[nf][1]);
                    }
                } else {
#pragma unroll
                    for (int mf = 0; mf < 4; mf++)
                        mma8(acc[mf][nf], ah[mf][0], ah[mf][1], ah[mf][2], ah[mf][3],
                             braw[nf][0], braw[nf][1]);
                }
            }
        }
        s ^= 1;
    }

    // epilogue
    float cs[4][2];
    if (EPI == 3) {
#pragma unroll
        for (int nf = 0; nf < 4; nf++) { cs[nf][0] = 0.f; cs[nf][1] = 0.f; }
    }
#pragma unroll
    for (int mf = 0; mf < 4; mf++) {
        int r0 = m0 + wm + mf * 16 + g;
        int r1 = r0 + 8;
#pragma unroll
        for (int nf = 0; nf < 4; nf++) {
            int c = n0 + wn + nf * 8 + tig * 2;
            float v0 = acc[mf][nf][0] * alpha;
            float v1 = acc[mf][nf][1] * alpha;
            float v2 = acc[mf][nf][2] * alpha;
            float v3 = acc[mf][nf][3] * alpha;
            if (EPI == 0) {
                float bb0 = bias ? bias[c] : 0.f;
                float bb1 = bias ? bias[c + 1] : 0.f;
                v0 += bb0; v1 += bb1; v2 += bb0; v3 += bb1;
                if (relu) {
                    v0 = fmaxf(v0, 0.f); v1 = fmaxf(v1, 0.f);
                    v2 = fmaxf(v2, 0.f); v3 = fmaxf(v3, 0.f);
                }
                if (c < N) {
                    if (r0 < M) {
                        C[(size_t)r0 * ldC + c] = v0; C[(size_t)r0 * ldC + c + 1] = v1;
                        if (C2) { C2[(size_t)r0 * ldC + c] = v0; C2[(size_t)r0 * ldC + c + 1] = v1; }
                    }
                    if (r1 < M) {
                        C[(size_t)r1 * ldC + c] = v2; C[(size_t)r1 * ldC + c + 1] = v3;
                        if (C2) { C2[(size_t)r1 * ldC + c] = v2; C2[(size_t)r1 * ldC + c + 1] = v3; }
                    }
                }
            } else if (EPI == 1) {
                if (c < N) {
                    if (r0 < M) { atomicAdd(&C[(size_t)r0 * ldC + c], v0); atomicAdd(&C[(size_t)r0 * ldC + c + 1], v1); }
                    if (r1 < M) { atomicAdd(&C[(size_t)r1 * ldC + c], v2); atomicAdd(&C[(size_t)r1 * ldC + c + 1], v3); }
                }
            } else if (EPI == 2) {
                if (c < N) {
                    if (r0 < M) { float sc = 1.f / rowscale[r0]; C[(size_t)r0 * ldC + c] = sc * v0; C[(size_t)r0 * ldC + c + 1] = sc * v1; }
                    if (r1 < M) { float sc = 1.f / rowscale[r1]; C[(size_t)r1 * ldC + c] = sc * v2; C[(size_t)r1 * ldC + c + 1] = sc * v3; }
                }
            } else if (EPI == 5) {
                float bb0 = bias ? bias[c] : 0.f;
                float bb1 = bias ? bias[c + 1] : 0.f;
                v0 = fmaxf(v0 + bb0, 0.f); v1 = fmaxf(v1 + bb1, 0.f);
                v2 = fmaxf(v2 + bb0, 0.f); v3 = fmaxf(v3 + bb1, 0.f);
                if (c < N) {
                    if (r0 < M) { C[(size_t)r0 * ldC + c] += v0; C[(size_t)r0 * ldC + c + 1] += v1; }
                    if (r1 < M) { C[(size_t)r1 * ldC + c] += v2; C[(size_t)r1 * ldC + c + 1] += v3; }
                }
            } else {
                // EPI 3: bf16 store of exp(score - mbound[n]) + col sums from ROUNDED values
                bool c0ok = (c < N);
                float mc0 = c0ok ? bias[c] : 0.f;
                float mc1 = (c + 1 < N) ? bias[c + 1] : 0.f;
                if (r0 < M && c0ok) {
                    __nv_bfloat16 h0 = __float2bfloat16_rn(__expf(v0 - mc0));
                    __nv_bfloat16 h1 = __float2bfloat16_rn(__expf(v1 - mc1));
                    __nv_bfloat162 pk; pk.x = h0; pk.y = h1;
                    *(__nv_bfloat162*)&Cbh[(size_t)r0 * ldC + c] = pk;
                    cs[nf][0] += __bfloat162float(h0);
                    cs[nf][1] += __bfloat162float(h1);
                }
                if (r1 < M && c0ok) {
                    __nv_bfloat16 h2 = __float2bfloat16_rn(__expf(v2 - mc0));
                    __nv_bfloat16 h3 = __float2bfloat16_rn(__expf(v3 - mc1));
                    __nv_bfloat162 pk; pk.x = h2; pk.y = h3;
                    *(__nv_bfloat162*)&Cbh[(size_t)r1 * ldC + c] = pk;
                    cs[nf][0] += __bfloat162float(h2);
                    cs[nf][1] += __bfloat162float(h3);
                }
            }
        }
    }
    if (EPI == 3) {
#pragma unroll
        for (int nf = 0; nf < 4; nf++) {
#pragma unroll
            for (int j = 0; j < 2; j++) {
                float v = cs[nf][j];
                v += __shfl_xor_sync(0xffffffffu, v, 4);
                v += __shfl_xor_sync(0xffffffffu, v, 8);
                v += __shfl_xor_sync(0xffffffffu, v, 16);
                int c = n0 + wn + nf * 8 + tig * 2 + j;
                if (lane < 4 && c < N) atomicAdd(&rowscale[c], v);
            }
        }
    }
}

// ---------------- GCN aggregation ----------------
// invscale != null: multiply result by 1/invscale[node] (fold softmax 1/l into Vd)
// mbout != null: also emit mbout[n] = qmaxp[0] * ||row|| / sqrt(128)  (fused k_mbound)
__global__ void k_aggregate(const float* __restrict__ H, const int* __restrict__ rptr,
                            const int* __restrict__ colv, const float* __restrict__ dinv,
                            const float* __restrict__ bias, float* __restrict__ Out,
                            int relu, const float* __restrict__ invscale,
                            const float* __restrict__ qmaxp, float* __restrict__ mbout) {
    int w = (blockIdx.x * blockDim.x + threadIdx.x) >> 5;
    int lane = threadIdx.x & 31;
    if (w >= NN) return;
    const float4* H4 = (const float4*)H;
    float4 acc = make_float4(0.f, 0.f, 0.f, 0.f);
    int s = rptr[w], e = rptr[w + 1];
    for (int j = s; j < e; j++) {
        int src = colv[j];
        float wt = dinv[src];
        float4 h = H4[src * 32 + lane];
        acc.x += wt * h.x; acc.y += wt * h.y; acc.z += wt * h.z; acc.w += wt * h.w;
    }
    float dn = dinv[w];
    float4 hs = H4[w * 32 + lane];
    float4 bb = ((const float4*)bias)[lane];
    acc.x = dn * (acc.x + dn * hs.x) + bb.x;
    acc.y = dn * (acc.y + dn * hs.y) + bb.y;
    acc.z = dn * (acc.z + dn * hs.z) + bb.z;
    acc.w = dn * (acc.w + dn * hs.w) + bb.w;
    if (relu) {
        acc.x = fmaxf(acc.x, 0.f); acc.y = fmaxf(acc.y, 0.f);
        acc.z = fmaxf(acc.z, 0.f); acc.w = fmaxf(acc.w, 0.f);
    }
    if (invscale) {
        float rs = 1.f / invscale[w];
        acc.x *= rs; acc.y *= rs; acc.z *= rs; acc.w *= rs;
    }
    if (mbout) {
        float nq = acc.x * acc.x + acc.y * acc.y + acc.z * acc.z + acc.w * acc.w;
#pragma unroll
        for (int o = 16; o; o >>= 1) nq += __shfl_xor_sync(0xffffffffu, nq, o);
        if (lane == 0) mbout[w] = qmaxp[0] * sqrtf(nq) * 0.0883883476483184f;
    }
    ((float4*)Out)[w * 32 + lane] = acc;
}

// ---------------- LayerNorm rows of X[M,128] ----------------
__global__ void k_layernorm(float* __restrict__ X, const float* __restrict__ g,
                            const float* __restrict__ b, int M) {
    int w = (blockIdx.x * blockDim.x + threadIdx.x) >> 5;
    int lane = threadIdx.x & 31;
    if (w >= M) return;
    float4 v = ((const float4*)X)[w * 32 + lane];
    float s = v.x + v.y + v.z + v.w;
    float sq = v.x * v.x + v.y * v.y + v.z * v.z + v.w * v.w;
#pragma unroll
    for (int o = 16; o; o >>= 1) {
        s += __shfl_xor_sync(0xffffffffu, s, o);
        sq += __shfl_xor_sync(0xffffffffu, sq, o);
    }
    float mean = s * (1.f / 128.f);
    float var = sq * (1.f / 128.f) - mean * mean;
    float rstd = rsqrtf(var + 1e-5f);
    float4 gg = ((const float4*)g)[lane];
    float4 bb = ((const float4*)b)[lane];
    v.x = (v.x - mean) * rstd * gg.x + bb.x;
    v.y = (v.y - mean) * rstd * gg.y + bb.y;
    v.z = (v.z - mean) * rstd * gg.z + bb.z;
    v.w = (v.w - mean) * rstd * gg.w + bb.w;
    ((float4*)X)[w * 32 + lane] = v;
}

// ---------------- host orchestration ----------------
static float* faddr(const void* sym) {
    void* p = nullptr;
    cudaGetSymbolAddress(&p, sym);
    return (float*)p;
}
static int* iaddr(const void* sym) {
    void* p = nullptr;
    cudaGetSymbolAddress(&p, sym);
    return (int*)p;
}

extern "C" void kernel_launch(void* const* d_in, const int* in_sizes, int n_in,
                              void* d_out, int out_size) {
    const float* x  = (const float*)d_in[0];
    const int*   ei = (const int*)d_in[1];
    const float* W1 = (const float*)d_in[3];  const float* b1 = (const float*)d_in[4];
    const float* W2 = (const float*)d_in[5];  const float* b2 = (const float*)d_in[6];
    const float* S  = (const float*)d_in[7];
    const float* Wq = (const float*)d_in[8];  const float* bq = (const float*)d_in[9];
    const float* Wk = (const float*)d_in[10]; const float* bk = (const float*)d_in[11];
    const float* Wv = (const float*)d_in[12]; const float* bv = (const float*)d_in[13];
    const float* Wo = (const float*)d_in[14]; const float* bo = (const float*)d_in[15];
    const float* g0 = (const float*)d_in[16]; const float* be0 = (const float*)d_in[17];
    const float* g1 = (const float*)d_in[18]; const float* be1 = (const float*)d_in[19];
    const float* Wl = (const float*)d_in[20]; const float* bl = (const float*)d_in[21];
    const float* W3 = (const float*)d_in[22]; const float* b3 = (const float*)d_in[23];
    const float* W4 = (const float*)d_in[24]; const float* b4 = (const float*)d_in[25];
    const float* W5 = (const float*)d_in[26]; const float* b5 = (const float*)d_in[27];

    const int* src = ei;
    const int* dst = ei + NE;

    __nv_bfloat16* score;
    { void* p = nullptr; cudaGetSymbolAddress(&p, g_score); score = (__nv_bfloat16*)p; }
    float* t     = faddr(g_t);
    float* h1    = faddr(g_h1);
    float* h2    = faddr(g_h2);
    float* Kd    = faddr(g_Kd);
    float* Vd    = faddr(g_Vd);
    float* Q     = faddr(g_Q);
    float* outb  = faddr(g_out);
    float* xl    = faddr(g_xl);
    float* dinv  = faddr(g_dinv);
    float* lsum  = faddr(g_l);
    float* mb    = faddr(g_mbound);
    int* cnt   = iaddr(g_cnt);
    int* rptr  = iaddr(g_rptr);
    int* colv  = iaddr(g_col);
    int* bsums = iaddr(g_bsums);

    cudaFuncSetAttribute((const void*)k_gemm<0,0,0,2,1,0>, cudaFuncAttributeMaxDynamicSharedMemorySize, GSMEM);
    cudaFuncSetAttribute((const void*)k_gemm<0,0,0,3,1,0>, cudaFuncAttributeMaxDynamicSharedMemorySize, GSMEM);
    cudaFuncSetAttribute((const void*)k_gemm<0,0,5,2,1,0>, cudaFuncAttributeMaxDynamicSharedMemorySize, GSMEM);
    cudaFuncSetAttribute((const void*)k_gemm<0,1,3,1,2,0>, cudaFuncAttributeMaxDynamicSharedMemorySize, GSMEM);
    cudaFuncSetAttribute((const void*)k_gemm<0,0,1,1,2,1>, cudaFuncAttributeMaxDynamicSharedMemorySize, GSMEM);
    cudaFuncSetAttribute((const void*)k_gemm<1,0,2,1,2,1>, cudaFuncAttributeMaxDynamicSharedMemorySize, GSMEM);

    const int mbN = (NN + 127) / 128;   // 157
    const int mbK = (KK + 127) / 128;   // 16
    float* dOut = (float*)d_out;
    const float rs128c = 0.0883883476483184f * ALPHA2;  // both operands raw tf32

    // --- fused zeroing (score bf16 pads, xl pads, lsum+qmax, cnt) ---
    k_zero_all<<<(((KK32 - KK) * NN / 2) + 255) / 256, 256>>>(
        (unsigned*)(score + (size_t)KK * NN), xl + (size_t)KK * DD, lsum, cnt);

    // --- CSR + degree (parallel 3-phase scan) ---
    k_count_dst<<<(NE + 255) / 256, 256>>>(dst, cnt);
    k_scan1<<<20, 1024>>>(cnt, rptr, bsums);
    k_scan2<<<1, 32>>>(bsums, 20);
    k_scan3<<<20, 1024>>>(rptr, bsums, cnt, dinv);
    k_fill_csr<<<(NE + 255) / 256, 256>>>(src, dst, rptr, cnt, colv);

    // --- GCN1, GCN2 (PREC=2 + ALPHA1) ---
    k_gemm<0,0,0,2,1,0><<<dim3(mbN,1,1), 256, GSMEM>>>(x,  W1, t, NN, 128, 128, 128, 128, 128, 128, ALPHA1, nullptr, nullptr, 0, nullptr);
    k_aggregate<<<(NN * 32 + 255) / 256, 256>>>(t, rptr, colv, dinv, b1, h1, 1, nullptr, nullptr, nullptr);
    k_gemm<0,0,0,2,1,0><<<dim3(mbN,1,1), 256, GSMEM>>>(h1, W2, t, NN, 128, 128, 128, 128, 128, 128, ALPHA1, nullptr, nullptr, 0, nullptr);
    k_aggregate<<<(NN * 32 + 255) / 256, 256>>>(t, rptr, colv, dinv, b2, h2, 1, nullptr, nullptr, nullptr);

    // --- Q (dual-write into outb), qmax, Kd (fused mbound) ---
    k_gemm<0,0,0,2,1,0><<<dim3(mbK,1,1), 256, GSMEM>>>(S,  Wq, Q, KK, 128, 128, 128, 128, 128, 128, ALPHA1, bq, nullptr, 0, outb);
    k_qmax<<<(KK * 32 + 255) / 256, 256>>>(Q, lsum + NN);
    k_gemm<0,0,0,2,1,0><<<dim3(mbN,1,1), 256, GSMEM>>>(h2, Wk, t, NN, 128, 128, 128, 128, 128, 128, ALPHA1, nullptr, nullptr, 0, nullptr);
    k_aggregate<<<(NN * 32 + 255) / 256, 256>>>(t, rptr, colv, dinv, bk, Kd, 0, nullptr, lsum + NN, mb);

    // --- fused score+exp(bf16)+colsum ---
    k_gemm<0,1,3,1,2,0><<<dim3(mbK, mbN, 1), 256, GSMEM>>>(Q, Kd, score, KK, NN, 128, 128, 128, 128, NN, rs128c, mb, lsum, 0, nullptr);

    // --- Vd (aggregate scales by 1/lsum[n]) ---
    k_gemm<0,0,0,2,1,0><<<dim3(mbN,1,1), 256, GSMEM>>>(h2, Wv, t, NN, 128, 128, 128, 128, 128, 128, ALPHA1, nullptr, nullptr, 0, nullptr);
    k_aggregate<<<(NN * 32 + 255) / 256, 256>>>(t, rptr, colv, dinv, bv, Vd, 0, lsum, nullptr, nullptr);

    // --- Out += Aexp(bf16, exact in tf32) @ Vd_scaled: 18-way split-K fills the wave ---
    k_gemm<0,0,1,1,2,1><<<dim3(mbK, 1, 18), 256, GSMEM>>>(score, Vd, outb, KK, 128, NN, 1120, NN, 128, 128, ALPHA1, nullptr, nullptr, 0, nullptr);

    // --- epilogue on [K,128] ---
    k_layernorm<<<(KK * 32 + 255) / 256, 256>>>(outb, g0, be0, KK);
    k_gemm<0,0,5,2,1,0><<<dim3(mbK,1,1), 256, GSMEM>>>(outb, Wo, outb, KK, 128, 128, 128, 128, 128, 128, ALPHA1, bo, nullptr, 1, nullptr);
    k_layernorm<<<(KK * 32 + 255) / 256, 256>>>(outb, g1, be1, KK);
    k_gemm<0,0,0,2,1,0><<<dim3(mbK,1,1), 256, GSMEM>>>(outb, Wl, xl, KK, 128, 128, 128, 128, 128, 128, ALPHA1, bl, nullptr, 0, nullptr);

    // --- x_out = (Aexp^T @ xl) / lsum[n]: A exact bf16-in-tf32, B raw + ALPHA1 ---
    k_gemm<1,0,2,1,2,1><<<dim3(mbN,1,1), 256, GSMEM>>>(score, xl, h1, NN, 128, KK32, KK32, NN, 128, 128, ALPHA1, nullptr, lsum, 0, nullptr);

    // --- GCN3, GCN4 (PREC=2), GCN5 (PREC=3, final output insurance) ---
    k_gemm<0,0,0,2,1,0><<<dim3(mbN,1,1), 256, GSMEM>>>(h1, W3, t, NN, 128, 128, 128, 128, 128, 128, ALPHA1, nullptr, nullptr, 0, nullptr);
    k_aggregate<<<(NN * 32 + 255) / 256, 256>>>(t, rptr, colv, dinv, b3, h2, 1, nullptr, nullptr, nullptr);
    k_gemm<0,0,0,2,1,0><<<dim3(mbN,1,1), 256, GSMEM>>>(h2, W4, t, NN, 128, 128, 128, 128, 128, 128, ALPHA1, nullptr, nullptr, 0, nullptr);
    k_aggregate<<<(NN * 32 + 255) / 256, 256>>>(t, rptr, colv, dinv, b4, h1, 1, nullptr, nullptr, nullptr);
    k_gemm<0,0,0,3,1,0><<<dim3(mbN,1,1), 256, GSMEM>>>(h1, W5, t, NN, 128, 128, 128, 128, 128, 128, 1.f, nullptr, nullptr, 0, nullptr);
    k_aggregate<<<(NN * 32 + 255) / 256, 256>>>(t, rptr, colv, dinv, b5, dOut, 0, nullptr, nullptr, nullptr);
}